// round 1
// baseline (speedup 1.0000x reference)
#include <cuda_runtime.h>

#define NB 64
#define NC 8
#define NH 256
#define NW 256
#define HW (NH*NW)

// Scratch (allocation-free rule: __device__ globals)
__device__ float g_q[NB*HW];            // 16.7 MB
__device__ float g_k[NB*HW];            // 16.7 MB
__device__ float g_attn[NB*NH*NH];      // 16.7 MB

// ---------------------------------------------------------------------------
// Kernel A: q,k 1x1-conv projections.  q[b,p] = sum_c w1[c]*x[b,c,p] + b1
// ---------------------------------------------------------------------------
__global__ __launch_bounds__(256)
void qk_kernel(const float* __restrict__ x,
               const float* __restrict__ w1, const float* __restrict__ b1,
               const float* __restrict__ w2, const float* __restrict__ b2) {
    int t = blockIdx.x * 256 + threadIdx.x;     // over NB*HW
    int b = t >> 16;                            // /65536
    int p = t & 65535;
    const float* xb = x + (size_t)b * NC * HW + p;
    float q = b1[0], k = b2[0];
#pragma unroll
    for (int c = 0; c < NC; c++) {
        float xv = xb[(size_t)c * HW];
        q = fmaf(w1[c], xv, q);
        k = fmaf(w2[c], xv, k);
    }
    g_q[t] = q;
    g_k[t] = k;
}

// ---------------------------------------------------------------------------
// Kernel B: scores[b,i,j] = sum_w q[b,i,w]*k[b,j,w]
// 128x128 tile per block, KC=8, 8x8 accumulators per thread.
// grid (2 j-tiles, 2 i-tiles, 64 b), 256 threads
// ---------------------------------------------------------------------------
__global__ __launch_bounds__(256, 2)
void scores_kernel() {
    __shared__ float qs[8][128];
    __shared__ float ks[8][128];
    const int b  = blockIdx.z;
    const int i0 = blockIdx.y * 128;
    const int j0 = blockIdx.x * 128;
    const float* q = g_q + (size_t)b * HW;
    const float* k = g_k + (size_t)b * HW;
    const int tid = threadIdx.x;
    const int tx = tid & 15, ty = tid >> 4;
    const int lr = tid >> 1;           // 0..127 (tile row)
    const int lc = (tid & 1) * 4;      // 0 or 4 (k sub-col)

    float acc[8][8];
#pragma unroll
    for (int i = 0; i < 8; i++)
#pragma unroll
        for (int j = 0; j < 8; j++) acc[i][j] = 0.f;

    for (int kk = 0; kk < NW; kk += 8) {
        float4 qv = *(const float4*)(q + (size_t)(i0 + lr) * NW + kk + lc);
        float4 kv = *(const float4*)(k + (size_t)(j0 + lr) * NW + kk + lc);
        __syncthreads();
        qs[lc + 0][lr] = qv.x; qs[lc + 1][lr] = qv.y;
        qs[lc + 2][lr] = qv.z; qs[lc + 3][lr] = qv.w;
        ks[lc + 0][lr] = kv.x; ks[lc + 1][lr] = kv.y;
        ks[lc + 2][lr] = kv.z; ks[lc + 3][lr] = kv.w;
        __syncthreads();
#pragma unroll
        for (int u = 0; u < 8; u++) {
            float a[8], bb[8];
            *(float4*)&a[0]  = *(const float4*)&qs[u][ty * 8];
            *(float4*)&a[4]  = *(const float4*)&qs[u][ty * 8 + 4];
            *(float4*)&bb[0] = *(const float4*)&ks[u][tx * 8];
            *(float4*)&bb[4] = *(const float4*)&ks[u][tx * 8 + 4];
#pragma unroll
            for (int i = 0; i < 8; i++)
#pragma unroll
                for (int j = 0; j < 8; j++)
                    acc[i][j] = fmaf(a[i], bb[j], acc[i][j]);
        }
    }

    float* dst = g_attn + (size_t)b * NH * NH;
#pragma unroll
    for (int i = 0; i < 8; i++) {
        int row = i0 + ty * 8 + i;
        float4 o0 = make_float4(acc[i][0], acc[i][1], acc[i][2], acc[i][3]);
        float4 o1 = make_float4(acc[i][4], acc[i][5], acc[i][6], acc[i][7]);
        *(float4*)(dst + (size_t)row * NH + j0 + tx * 8)     = o0;
        *(float4*)(dst + (size_t)row * NH + j0 + tx * 8 + 4) = o1;
    }
}

// ---------------------------------------------------------------------------
// Kernel C: row softmax over j (256 values). One warp per row.
// ---------------------------------------------------------------------------
__global__ __launch_bounds__(256)
void softmax_kernel() {
    int row  = blockIdx.x * 8 + (threadIdx.x >> 5);
    int lane = threadIdx.x & 31;
    float* p = g_attn + (size_t)row * NH;
    float4 v0 = *(const float4*)(p + lane * 8);
    float4 v1 = *(const float4*)(p + lane * 8 + 4);
    float m = fmaxf(fmaxf(fmaxf(v0.x, v0.y), fmaxf(v0.z, v0.w)),
                    fmaxf(fmaxf(v1.x, v1.y), fmaxf(v1.z, v1.w)));
#pragma unroll
    for (int o = 16; o > 0; o >>= 1) m = fmaxf(m, __shfl_xor_sync(0xffffffffu, m, o));
    v0.x = expf(v0.x - m); v0.y = expf(v0.y - m);
    v0.z = expf(v0.z - m); v0.w = expf(v0.w - m);
    v1.x = expf(v1.x - m); v1.y = expf(v1.y - m);
    v1.z = expf(v1.z - m); v1.w = expf(v1.w - m);
    float s = v0.x + v0.y + v0.z + v0.w + v1.x + v1.y + v1.z + v1.w;
#pragma unroll
    for (int o = 16; o > 0; o >>= 1) s += __shfl_xor_sync(0xffffffffu, s, o);
    float inv = 1.0f / s;
    v0.x *= inv; v0.y *= inv; v0.z *= inv; v0.w *= inv;
    v1.x *= inv; v1.y *= inv; v1.z *= inv; v1.w *= inv;
    *(float4*)(p + lane * 8)     = v0;
    *(float4*)(p + lane * 8 + 4) = v1;
}

// ---------------------------------------------------------------------------
// Kernel D: y[c',i,w] = sum_j attn[i,j]*x[c',j,w];  out[c] = w3[c,:]·y + b3[c]
// Block tile: 64 i x 32 w x all 8 channels. grid (8 w-tiles, 4 i-tiles, 64 b)
// 256 threads (tx: 16 over w-pairs, ty: 16 over i-quads). 64 fp32 acc/thread.
// ---------------------------------------------------------------------------
__global__ __launch_bounds__(256, 2)
void out_kernel(const float* __restrict__ x,
                const float* __restrict__ w3, const float* __restrict__ b3,
                float* __restrict__ out) {
    __shared__ float as[64][20];        // attn tile, padded (80B rows: 16B aligned, conflict-free)
    __shared__ float xs[8][16][32];     // x tile [c][j][w]
    __shared__ float w3s[64];
    __shared__ float b3s[8];

    const int b  = blockIdx.z;
    const int i0 = blockIdx.y * 64;
    const int w0 = blockIdx.x * 32;
    const int tid = threadIdx.x;
    const int tx = tid & 15, ty = tid >> 4;

    if (tid < 64) w3s[tid] = w3[tid];
    if (tid < 8)  b3s[tid] = b3[tid];

    float acc[8][4][2];
#pragma unroll
    for (int c = 0; c < 8; c++)
#pragma unroll
        for (int i = 0; i < 4; i++) { acc[c][i][0] = 0.f; acc[c][i][1] = 0.f; }

    const float* attn = g_attn + (size_t)b * NH * NH;
    const int a_i  = tid >> 2;          // 0..63
    const int a_jq = (tid & 3) * 4;     // 0,4,8,12

    for (int j0 = 0; j0 < NH; j0 += 16) {
        // stage global->regs
        float4 av = *(const float4*)(attn + (size_t)(i0 + a_i) * NH + j0 + a_jq);
        float4 xv[4];
#pragma unroll
        for (int r = 0; r < 4; r++) {
            int m = tid + 256 * r;
            int quad = m & 7, j = (m >> 3) & 15, c = m >> 7;
            xv[r] = *(const float4*)(x + (((size_t)(b * 8 + c)) * NH + (j0 + j)) * NW
                                       + w0 + quad * 4);
        }
        __syncthreads();
        *(float4*)&as[a_i][a_jq] = av;
#pragma unroll
        for (int r = 0; r < 4; r++) {
            int m = tid + 256 * r;
            int quad = m & 7, j = (m >> 3) & 15, c = m >> 7;
            *(float4*)&xs[c][j][quad * 4] = xv[r];
        }
        __syncthreads();

#pragma unroll
        for (int j = 0; j < 16; j++) {
            float a0 = as[ty * 4 + 0][j];
            float a1 = as[ty * 4 + 1][j];
            float a2 = as[ty * 4 + 2][j];
            float a3 = as[ty * 4 + 3][j];
#pragma unroll
            for (int c = 0; c < 8; c++) {
                float2 xw = *(const float2*)&xs[c][j][tx * 2];
                acc[c][0][0] = fmaf(a0, xw.x, acc[c][0][0]);
                acc[c][0][1] = fmaf(a0, xw.y, acc[c][0][1]);
                acc[c][1][0] = fmaf(a1, xw.x, acc[c][1][0]);
                acc[c][1][1] = fmaf(a1, xw.y, acc[c][1][1]);
                acc[c][2][0] = fmaf(a2, xw.x, acc[c][2][0]);
                acc[c][2][1] = fmaf(a2, xw.y, acc[c][2][1]);
                acc[c][3][0] = fmaf(a3, xw.x, acc[c][3][0]);
                acc[c][3][1] = fmaf(a3, xw.y, acc[c][3][1]);
            }
        }
    }

    // Epilogue: per-pixel 8x8 channel mix (out = w3 @ y + b3), write out
#pragma unroll
    for (int ii = 0; ii < 4; ii++) {
        int i = i0 + ty * 4 + ii;
#pragma unroll
        for (int c = 0; c < 8; c++) {
            float ox = b3s[c], oy = b3s[c];
#pragma unroll
            for (int cp = 0; cp < 8; cp++) {
                float wv = w3s[c * 8 + cp];
                ox = fmaf(wv, acc[cp][ii][0], ox);
                oy = fmaf(wv, acc[cp][ii][1], oy);
            }
            float2 o = make_float2(ox, oy);
            *(float2*)(out + (((size_t)(b * 8 + c)) * NH + i) * NW + w0 + tx * 2) = o;
        }
    }
}

// ---------------------------------------------------------------------------
extern "C" void kernel_launch(void* const* d_in, const int* in_sizes, int n_in,
                              void* d_out, int out_size) {
    const float* x  = (const float*)d_in[0];
    const float* w1 = (const float*)d_in[1];
    const float* b1 = (const float*)d_in[2];
    const float* w2 = (const float*)d_in[3];
    const float* b2 = (const float*)d_in[4];
    const float* w3 = (const float*)d_in[5];
    const float* b3 = (const float*)d_in[6];
    float* out = (float*)d_out;

    // A: q,k projections
    qk_kernel<<<(NB * HW) / 256, 256>>>(x, w1, b1, w2, b2);
    // B: scores = q @ k^T (per batch)
    dim3 gb(2, 2, NB);
    scores_kernel<<<gb, 256>>>();
    // C: row softmax
    softmax_kernel<<<(NB * NH) / 8, 256>>>();
    // D: out = w3 @ (attn @ x) + b3
    dim3 gd(NW / 32, NH / 64, NB);
    out_kernel<<<gd, 256>>>(x, w3, b3, out);
}

// round 3
// speedup vs baseline: 1.8125x; 1.8125x over previous
#include <cuda_runtime.h>
#include <cstdint>

#define NB 64
#define NC 8
#define NH 256
#define NW 256
#define HW (NH*NW)

// Scratch (__device__ globals per allocation-free rule)
__device__ float g_q[NB*HW];                 // 16.7 MB
__device__ float g_k[NB*HW];                 // 16.7 MB
__device__ float g_attn[NB*NH*NH];           // 16.7 MB
__device__ float g_v[(size_t)NB*NC*HW];      // 134 MB, layout [b][c][j][w] (== x layout)

// ---------------------------------------------------------------------------
// helpers
// ---------------------------------------------------------------------------
__device__ __forceinline__ float f2tf(float x) {
    uint32_t u;
    asm("cvt.rna.tf32.f32 %0, %1;" : "=r"(u) : "f"(x));
    return __uint_as_float(u);
}
#define MMA_TF32(d, a0, a1, a2, a3, b0, b1)                                       \
    asm volatile("mma.sync.aligned.m16n8k8.row.col.f32.tf32.tf32.f32 "            \
                 "{%0,%1,%2,%3},{%4,%5,%6,%7},{%8,%9},{%0,%1,%2,%3};"             \
                 : "+f"(d[0]), "+f"(d[1]), "+f"(d[2]), "+f"(d[3])                  \
                 : "r"(a0), "r"(a1), "r"(a2), "r"(a3), "r"(b0), "r"(b1))

// ---------------------------------------------------------------------------
// Kernel A: fused projections. q,k = 1x1 conv; v = w3@x + b3 (b3 folded here,
// valid because softmax rows sum to 1). Each thread does 4 pixels (float4).
// ---------------------------------------------------------------------------
__global__ __launch_bounds__(256)
void proj_kernel(const float* __restrict__ x,
                 const float* __restrict__ w1, const float* __restrict__ b1,
                 const float* __restrict__ w2, const float* __restrict__ b2,
                 const float* __restrict__ w3, const float* __restrict__ b3) {
    __shared__ float w1s[8], w2s[8], w3s[64], b3s[8], bqk[2];
    const int tid = threadIdx.x;
    if (tid < 8)  { w1s[tid] = w1[tid]; w2s[tid] = w2[tid]; b3s[tid] = b3[tid]; }
    if (tid < 64) w3s[tid] = w3[tid];
    if (tid == 0) { bqk[0] = b1[0]; bqk[1] = b2[0]; }
    __syncthreads();

    const int t = blockIdx.x * 256 + tid;        // over NB*HW/4
    const int b = t >> 14;                       // HW/4 = 16384
    const int off = (t & 16383) << 2;
    const size_t base = (size_t)b * 8 * HW + off;

    float4 xv[8];
#pragma unroll
    for (int c = 0; c < 8; c++) xv[c] = *(const float4*)(x + base + (size_t)c * HW);

    float4 q = make_float4(bqk[0], bqk[0], bqk[0], bqk[0]);
    float4 k = make_float4(bqk[1], bqk[1], bqk[1], bqk[1]);
#pragma unroll
    for (int c = 0; c < 8; c++) {
        q.x = fmaf(w1s[c], xv[c].x, q.x); q.y = fmaf(w1s[c], xv[c].y, q.y);
        q.z = fmaf(w1s[c], xv[c].z, q.z); q.w = fmaf(w1s[c], xv[c].w, q.w);
        k.x = fmaf(w2s[c], xv[c].x, k.x); k.y = fmaf(w2s[c], xv[c].y, k.y);
        k.z = fmaf(w2s[c], xv[c].z, k.z); k.w = fmaf(w2s[c], xv[c].w, k.w);
    }
    *(float4*)(g_q + (size_t)b * HW + off) = q;
    *(float4*)(g_k + (size_t)b * HW + off) = k;

#pragma unroll
    for (int cp = 0; cp < 8; cp++) {
        float4 v = make_float4(b3s[cp], b3s[cp], b3s[cp], b3s[cp]);
#pragma unroll
        for (int c = 0; c < 8; c++) {
            float w = w3s[cp * 8 + c];
            v.x = fmaf(w, xv[c].x, v.x); v.y = fmaf(w, xv[c].y, v.y);
            v.z = fmaf(w, xv[c].z, v.z); v.w = fmaf(w, xv[c].w, v.w);
        }
        *(float4*)(g_v + base + (size_t)cp * HW) = v;
    }
}

// ---------------------------------------------------------------------------
// Kernel B: scores (fp32, validated round 1)
// ---------------------------------------------------------------------------
__global__ __launch_bounds__(256, 2)
void scores_kernel() {
    __shared__ float qs[8][128];
    __shared__ float ks[8][128];
    const int b  = blockIdx.z;
    const int i0 = blockIdx.y * 128;
    const int j0 = blockIdx.x * 128;
    const float* q = g_q + (size_t)b * HW;
    const float* k = g_k + (size_t)b * HW;
    const int tid = threadIdx.x;
    const int tx = tid & 15, ty = tid >> 4;
    const int lr = tid >> 1;
    const int lc = (tid & 1) * 4;

    float acc[8][8];
#pragma unroll
    for (int i = 0; i < 8; i++)
#pragma unroll
        for (int j = 0; j < 8; j++) acc[i][j] = 0.f;

    for (int kk = 0; kk < NW; kk += 8) {
        float4 qv = *(const float4*)(q + (size_t)(i0 + lr) * NW + kk + lc);
        float4 kv = *(const float4*)(k + (size_t)(j0 + lr) * NW + kk + lc);
        __syncthreads();
        qs[lc + 0][lr] = qv.x; qs[lc + 1][lr] = qv.y;
        qs[lc + 2][lr] = qv.z; qs[lc + 3][lr] = qv.w;
        ks[lc + 0][lr] = kv.x; ks[lc + 1][lr] = kv.y;
        ks[lc + 2][lr] = kv.z; ks[lc + 3][lr] = kv.w;
        __syncthreads();
#pragma unroll
        for (int u = 0; u < 8; u++) {
            float a[8], bb[8];
            *(float4*)&a[0]  = *(const float4*)&qs[u][ty * 8];
            *(float4*)&a[4]  = *(const float4*)&qs[u][ty * 8 + 4];
            *(float4*)&bb[0] = *(const float4*)&ks[u][tx * 8];
            *(float4*)&bb[4] = *(const float4*)&ks[u][tx * 8 + 4];
#pragma unroll
            for (int i = 0; i < 8; i++)
#pragma unroll
                for (int j = 0; j < 8; j++)
                    acc[i][j] = fmaf(a[i], bb[j], acc[i][j]);
        }
    }
    float* dst = g_attn + (size_t)b * NH * NH;
#pragma unroll
    for (int i = 0; i < 8; i++) {
        int row = i0 + ty * 8 + i;
        *(float4*)(dst + (size_t)row * NH + j0 + tx * 8) =
            make_float4(acc[i][0], acc[i][1], acc[i][2], acc[i][3]);
        *(float4*)(dst + (size_t)row * NH + j0 + tx * 8 + 4) =
            make_float4(acc[i][4], acc[i][5], acc[i][6], acc[i][7]);
    }
}

// ---------------------------------------------------------------------------
// Kernel C: row softmax (fp32, validated round 1)
// ---------------------------------------------------------------------------
__global__ __launch_bounds__(256)
void softmax_kernel() {
    int row  = blockIdx.x * 8 + (threadIdx.x >> 5);
    int lane = threadIdx.x & 31;
    float* p = g_attn + (size_t)row * NH;
    float4 v0 = *(const float4*)(p + lane * 8);
    float4 v1 = *(const float4*)(p + lane * 8 + 4);
    float m = fmaxf(fmaxf(fmaxf(v0.x, v0.y), fmaxf(v0.z, v0.w)),
                    fmaxf(fmaxf(v1.x, v1.y), fmaxf(v1.z, v1.w)));
#pragma unroll
    for (int o = 16; o > 0; o >>= 1) m = fmaxf(m, __shfl_xor_sync(0xffffffffu, m, o));
    v0.x = expf(v0.x - m); v0.y = expf(v0.y - m);
    v0.z = expf(v0.z - m); v0.w = expf(v0.w - m);
    v1.x = expf(v1.x - m); v1.y = expf(v1.y - m);
    v1.z = expf(v1.z - m); v1.w = expf(v1.w - m);
    float s = v0.x + v0.y + v0.z + v0.w + v1.x + v1.y + v1.z + v1.w;
#pragma unroll
    for (int o = 16; o > 0; o >>= 1) s += __shfl_xor_sync(0xffffffffu, s, o);
    float inv = 1.0f / s;
    v0.x *= inv; v0.y *= inv; v0.z *= inv; v0.w *= inv;
    v1.x *= inv; v1.y *= inv; v1.z *= inv; v1.w *= inv;
    *(float4*)(p + lane * 8)     = v0;
    *(float4*)(p + lane * 8 + 4) = v1;
}

// ---------------------------------------------------------------------------
// Kernel D: out[b,c] = attn_b @ v[b,c] via tf32 mma.sync (HMMA).
// CTA: M=128 (i) x N=256 (w), K=256 (j) in 16 chunks of 16.
// 512 threads = 16 warps (4m x 4n), warp tile 32x64 (2 m16 x 8 n8 frags).
// Smem: A [i][k'] stride 20 (k'=(k%4)*4+k/4), B [k][n] stride 264.
// ---------------------------------------------------------------------------
#define KC 16
#define A_STRIDE 20
#define B_STRIDE 264
#define A_FLOATS (128 * A_STRIDE)          // 2560
#define B_FLOATS (KC * B_STRIDE)           // 4224
#define STAGE_FLOATS (A_FLOATS + B_FLOATS) // 6784
#define SMEM_TOT (2 * STAGE_FLOATS * 4)    // 54272 B

__global__ __launch_bounds__(512, 1)
void mma_out_kernel(float* __restrict__ out) {
    extern __shared__ float sm[];
    const int tid = threadIdx.x;
    const int lane = tid & 31;
    const int warp = tid >> 5;
    const int warpM = warp & 3;             // 4 m-groups
    const int warpN = warp >> 2;            // 4 n-groups
    const int g = lane >> 2, t4 = lane & 3;

    const int i0 = blockIdx.x * 128;
    const int c  = blockIdx.y;
    const int b  = blockIdx.z;

    const float* Ab = g_attn + (size_t)b * NH * NH + (size_t)i0 * NH;
    const float* Bb = g_v + ((size_t)(b * 8 + c)) * HW;

    // staging indices (fixed per thread)
    const int a_row = tid >> 2, a_kq = tid & 3;

    float acc[2][8][4];
#pragma unroll
    for (int mi = 0; mi < 2; mi++)
#pragma unroll
        for (int ni = 0; ni < 8; ni++)
#pragma unroll
            for (int r = 0; r < 4; r++) acc[mi][ni][r] = 0.f;

    // ---- stage chunk 0 ----
    {
        float4 va = *(const float4*)(Ab + (size_t)a_row * NH + a_kq * 4);
        float* da = sm + a_row * A_STRIDE;
        da[0 * 4 + a_kq] = f2tf(va.x); da[1 * 4 + a_kq] = f2tf(va.y);
        da[2 * 4 + a_kq] = f2tf(va.z); da[3 * 4 + a_kq] = f2tf(va.w);
#pragma unroll
        for (int r = 0; r < 2; r++) {
            int m = tid + 512 * r;
            int krow = m >> 6, nq = m & 63;
            float4 vb = *(const float4*)(Bb + (size_t)krow * NW + nq * 4);
            float4 t = make_float4(f2tf(vb.x), f2tf(vb.y), f2tf(vb.z), f2tf(vb.w));
            *(float4*)(sm + A_FLOATS + krow * B_STRIDE + nq * 4) = t;
        }
    }
    __syncthreads();

    for (int kc = 0; kc < 16; kc++) {
        const int s = kc & 1;
        float4 pa, pb0, pb1;
        int pk0 = (kc + 1) * KC;
        if (kc < 15) {
            pa = *(const float4*)(Ab + (size_t)a_row * NH + pk0 + a_kq * 4);
            {
                int m = tid;
                int krow = m >> 6, nq = m & 63;
                pb0 = *(const float4*)(Bb + (size_t)(pk0 + krow) * NW + nq * 4);
            }
            {
                int m = tid + 512;
                int krow = m >> 6, nq = m & 63;
                pb1 = *(const float4*)(Bb + (size_t)(pk0 + krow) * NW + nq * 4);
            }
        }

        // ---- compute chunk kc from stage s ----
        const float* As = sm + s * STAGE_FLOATS;
        const float* Bs = As + A_FLOATS;
        float4 afr[2][2];
#pragma unroll
        for (int mi = 0; mi < 2; mi++) {
            int rb = warpM * 32 + mi * 16 + g;
            afr[mi][0] = *(const float4*)(As + rb * A_STRIDE + t4 * 4);
            afr[mi][1] = *(const float4*)(As + (rb + 8) * A_STRIDE + t4 * 4);
        }
#pragma unroll
        for (int ni = 0; ni < 8; ni++) {
            int n = warpN * 64 + ni * 8 + g;
            uint32_t b00 = __float_as_uint(Bs[(t4)      * B_STRIDE + n]);
            uint32_t b01 = __float_as_uint(Bs[(t4 + 4)  * B_STRIDE + n]);
            uint32_t b10 = __float_as_uint(Bs[(t4 + 8)  * B_STRIDE + n]);
            uint32_t b11 = __float_as_uint(Bs[(t4 + 12) * B_STRIDE + n]);
#pragma unroll
            for (int mi = 0; mi < 2; mi++) {
                MMA_TF32(acc[mi][ni],
                         __float_as_uint(afr[mi][0].x), __float_as_uint(afr[mi][1].x),
                         __float_as_uint(afr[mi][0].y), __float_as_uint(afr[mi][1].y),
                         b00, b01);
                MMA_TF32(acc[mi][ni],
                         __float_as_uint(afr[mi][0].z), __float_as_uint(afr[mi][1].z),
                         __float_as_uint(afr[mi][0].w), __float_as_uint(afr[mi][1].w),
                         b10, b11);
            }
        }

        if (kc < 15) {
            float* dstg = sm + (s ^ 1) * STAGE_FLOATS;
            float* da = dstg + a_row * A_STRIDE;
            da[0 * 4 + a_kq] = f2tf(pa.x); da[1 * 4 + a_kq] = f2tf(pa.y);
            da[2 * 4 + a_kq] = f2tf(pa.z); da[3 * 4 + a_kq] = f2tf(pa.w);
            {
                int m = tid;
                int krow = m >> 6, nq = m & 63;
                float4 t = make_float4(f2tf(pb0.x), f2tf(pb0.y), f2tf(pb0.z), f2tf(pb0.w));
                *(float4*)(dstg + A_FLOATS + krow * B_STRIDE + nq * 4) = t;
            }
            {
                int m = tid + 512;
                int krow = m >> 6, nq = m & 63;
                float4 t = make_float4(f2tf(pb1.x), f2tf(pb1.y), f2tf(pb1.z), f2tf(pb1.w));
                *(float4*)(dstg + A_FLOATS + krow * B_STRIDE + nq * 4) = t;
            }
        }
        __syncthreads();
    }

    // ---- epilogue ----
    float* ob = out + ((size_t)(b * 8 + c)) * HW;
#pragma unroll
    for (int mi = 0; mi < 2; mi++) {
        int row = i0 + warpM * 32 + mi * 16 + g;
#pragma unroll
        for (int ni = 0; ni < 8; ni++) {
            int col = warpN * 64 + ni * 8 + t4 * 2;
            *(float2*)(ob + (size_t)row * NW + col) =
                make_float2(acc[mi][ni][0], acc[mi][ni][1]);
            *(float2*)(ob + (size_t)(row + 8) * NW + col) =
                make_float2(acc[mi][ni][2], acc[mi][ni][3]);
        }
    }
}

// ---------------------------------------------------------------------------
extern "C" void kernel_launch(void* const* d_in, const int* in_sizes, int n_in,
                              void* d_out, int out_size) {
    const float* x  = (const float*)d_in[0];
    const float* w1 = (const float*)d_in[1];
    const float* b1 = (const float*)d_in[2];
    const float* w2 = (const float*)d_in[3];
    const float* b2 = (const float*)d_in[4];
    const float* w3 = (const float*)d_in[5];
    const float* b3 = (const float*)d_in[6];
    float* out = (float*)d_out;

    static bool configured = false;
    if (!configured) {
        cudaFuncSetAttribute(mma_out_kernel,
                             cudaFuncAttributeMaxDynamicSharedMemorySize, SMEM_TOT);
        configured = true;
    }

    proj_kernel<<<(NB * HW) / 1024, 256>>>(x, w1, b1, w2, b2, w3, b3);
    dim3 gb(2, 2, NB);
    scores_kernel<<<gb, 256>>>();
    softmax_kernel<<<(NB * NH) / 8, 256>>>();
    dim3 gd(2, 8, NB);
    mma_out_kernel<<<gd, 512, SMEM_TOT>>>(out);
}

// round 4
// speedup vs baseline: 2.0942x; 1.1554x over previous
#include <cuda_runtime.h>
#include <cstdint>

#define NB 64
#define NC 8
#define NH 256
#define NW 256
#define HW (NH*NW)

// Scratch (__device__ globals per allocation-free rule)
__device__ float g_q[NB*HW];                 // 16.7 MB
__device__ float g_k[NB*HW];                 // 16.7 MB
__device__ float g_attn[NB*NH*NH];           // 16.7 MB (tf32, k-permuted after softmax)
__device__ float g_vt[(size_t)NB*NC*HW];     // 134 MB, [b][c][w][j] tf32, j-permuted

// ---------------------------------------------------------------------------
// helpers
// ---------------------------------------------------------------------------
__device__ __forceinline__ float f2tf(float x) {
    uint32_t u;
    asm("cvt.rna.tf32.f32 %0, %1;" : "=r"(u) : "f"(x));
    return __uint_as_float(u);
}
__device__ __forceinline__ uint32_t smem_u32(const void* p) {
    uint32_t a;
    asm("{ .reg .u64 t; cvta.to.shared.u64 t, %1; cvt.u32.u64 %0, t; }" : "=r"(a) : "l"(p));
    return a;
}
__device__ __forceinline__ float4 lds128(uint32_t a) {
    float4 v;
    asm volatile("ld.shared.v4.f32 {%0,%1,%2,%3}, [%4];"
                 : "=f"(v.x), "=f"(v.y), "=f"(v.z), "=f"(v.w) : "r"(a));
    return v;
}
#define CP16(sa, ga) asm volatile("cp.async.cg.shared.global [%0], [%1], 16;" :: "r"(sa), "l"(ga))
#define CP_COMMIT()  asm volatile("cp.async.commit_group;")
#define CP_WAIT2()   asm volatile("cp.async.wait_group 2;")
#define MMA_TF32(d, a0, a1, a2, a3, b0, b1)                                       \
    asm volatile("mma.sync.aligned.m16n8k8.row.col.f32.tf32.tf32.f32 "            \
                 "{%0,%1,%2,%3},{%4,%5,%6,%7},{%8,%9},{%0,%1,%2,%3};"             \
                 : "+f"(d[0]), "+f"(d[1]), "+f"(d[2]), "+f"(d[3])                  \
                 : "r"(a0), "r"(a1), "r"(a2), "r"(a3), "r"(b0), "r"(b1))
#define U(f) __float_as_uint(f)

// ---------------------------------------------------------------------------
// Kernel A: fused projections. q,k 1x1 conv (fp32); v = w3@x + b3 (b3 folded,
// valid since softmax rows sum to 1) written TRANSPOSED [b][c][w][j],
// tf32-rounded, j permuted within 16-blocks (p = 4*(j%4) + (j%16)/4).
// block 256 thr, tile 32w x 32j. grid (8 w-tiles, 8 j-tiles, 64 b)
// ---------------------------------------------------------------------------
__global__ __launch_bounds__(256)
void proj_kernel(const float* __restrict__ x,
                 const float* __restrict__ w1, const float* __restrict__ b1,
                 const float* __restrict__ w2, const float* __restrict__ b2,
                 const float* __restrict__ w3, const float* __restrict__ b3) {
    __shared__ float xt_s[8][32][33];
    __shared__ float w1s[8], w2s[8], w3s[64], b3s[8], bqk[2];
    const int tid = threadIdx.x;
    if (tid < 8)  { w1s[tid] = w1[tid]; w2s[tid] = w2[tid]; b3s[tid] = b3[tid]; }
    if (tid < 64) w3s[tid] = w3[tid];
    if (tid == 0) { bqk[0] = b1[0]; bqk[1] = b2[0]; }
    __syncthreads();
    const int b = blockIdx.z, j0 = blockIdx.y * 32, w0 = blockIdx.x * 32;
    const int w = tid & 31, jl = tid >> 5;
    const float* xb = x + (size_t)b * NC * HW;

#pragma unroll
    for (int js = 0; js < 32; js += 8) {
        const int j = j0 + js + jl;
        float xv[8];
        float q = bqk[0], k = bqk[1];
#pragma unroll
        for (int c = 0; c < 8; c++) {
            xv[c] = xb[(size_t)c * HW + (size_t)j * NW + w0 + w];
            q = fmaf(w1s[c], xv[c], q);
            k = fmaf(w2s[c], xv[c], k);
        }
        g_q[(size_t)b * HW + (size_t)j * NW + w0 + w] = q;
        g_k[(size_t)b * HW + (size_t)j * NW + w0 + w] = k;
#pragma unroll
        for (int c = 0; c < 8; c++) {
            float s = b3s[c];
#pragma unroll
            for (int cp = 0; cp < 8; cp++) s = fmaf(w3s[c * 8 + cp], xv[cp], s);
            xt_s[c][js + jl][w] = s;
        }
    }
    __syncthreads();
    // transposed + permuted + tf32 write
    const int jj = tid & 31, wl = tid >> 5;
    const int jp = (jj & 16) | (((jj & 3) << 2) | ((jj & 15) >> 2));
#pragma unroll
    for (int c = 0; c < 8; c++)
#pragma unroll
        for (int ws = 0; ws < 32; ws += 8) {
            int wg = ws + wl;
            g_vt[(((size_t)(b * 8 + c)) * NW + w0 + wg) * NH + j0 + jp] =
                f2tf(xt_s[c][jj][wg]);
        }
}

// ---------------------------------------------------------------------------
// Kernel B: scores (fp32, validated)
// ---------------------------------------------------------------------------
__global__ __launch_bounds__(256, 2)
void scores_kernel() {
    __shared__ float qs[8][128];
    __shared__ float ks[8][128];
    const int b  = blockIdx.z;
    const int i0 = blockIdx.y * 128;
    const int j0 = blockIdx.x * 128;
    const float* q = g_q + (size_t)b * HW;
    const float* k = g_k + (size_t)b * HW;
    const int tid = threadIdx.x;
    const int tx = tid & 15, ty = tid >> 4;
    const int lr = tid >> 1;
    const int lc = (tid & 1) * 4;

    float acc[8][8];
#pragma unroll
    for (int i = 0; i < 8; i++)
#pragma unroll
        for (int j = 0; j < 8; j++) acc[i][j] = 0.f;

    for (int kk = 0; kk < NW; kk += 8) {
        float4 qv = *(const float4*)(q + (size_t)(i0 + lr) * NW + kk + lc);
        float4 kv = *(const float4*)(k + (size_t)(j0 + lr) * NW + kk + lc);
        __syncthreads();
        qs[lc + 0][lr] = qv.x; qs[lc + 1][lr] = qv.y;
        qs[lc + 2][lr] = qv.z; qs[lc + 3][lr] = qv.w;
        ks[lc + 0][lr] = kv.x; ks[lc + 1][lr] = kv.y;
        ks[lc + 2][lr] = kv.z; ks[lc + 3][lr] = kv.w;
        __syncthreads();
#pragma unroll
        for (int u = 0; u < 8; u++) {
            float a[8], bb[8];
            *(float4*)&a[0]  = *(const float4*)&qs[u][ty * 8];
            *(float4*)&a[4]  = *(const float4*)&qs[u][ty * 8 + 4];
            *(float4*)&bb[0] = *(const float4*)&ks[u][tx * 8];
            *(float4*)&bb[4] = *(const float4*)&ks[u][tx * 8 + 4];
#pragma unroll
            for (int i = 0; i < 8; i++)
#pragma unroll
                for (int j = 0; j < 8; j++)
                    acc[i][j] = fmaf(a[i], bb[j], acc[i][j]);
        }
    }
    float* dst = g_attn + (size_t)b * NH * NH;
#pragma unroll
    for (int i = 0; i < 8; i++) {
        int row = i0 + ty * 8 + i;
        *(float4*)(dst + (size_t)row * NH + j0 + tx * 8) =
            make_float4(acc[i][0], acc[i][1], acc[i][2], acc[i][3]);
        *(float4*)(dst + (size_t)row * NH + j0 + tx * 8 + 4) =
            make_float4(acc[i][4], acc[i][5], acc[i][6], acc[i][7]);
    }
}

// ---------------------------------------------------------------------------
// Kernel C: row softmax (fp32 math), stores tf32-rounded + k-permuted.
// ---------------------------------------------------------------------------
__global__ __launch_bounds__(256)
void softmax_kernel() {
    int row  = blockIdx.x * 8 + (threadIdx.x >> 5);
    int lane = threadIdx.x & 31;
    float* p = g_attn + (size_t)row * NH;
    float4 v0 = *(const float4*)(p + lane * 8);
    float4 v1 = *(const float4*)(p + lane * 8 + 4);
    float m = fmaxf(fmaxf(fmaxf(v0.x, v0.y), fmaxf(v0.z, v0.w)),
                    fmaxf(fmaxf(v1.x, v1.y), fmaxf(v1.z, v1.w)));
#pragma unroll
    for (int o = 16; o > 0; o >>= 1) m = fmaxf(m, __shfl_xor_sync(0xffffffffu, m, o));
    v0.x = expf(v0.x - m); v0.y = expf(v0.y - m);
    v0.z = expf(v0.z - m); v0.w = expf(v0.w - m);
    v1.x = expf(v1.x - m); v1.y = expf(v1.y - m);
    v1.z = expf(v1.z - m); v1.w = expf(v1.w - m);
    float s = v0.x + v0.y + v0.z + v0.w + v1.x + v1.y + v1.z + v1.w;
#pragma unroll
    for (int o = 16; o > 0; o >>= 1) s += __shfl_xor_sync(0xffffffffu, s, o);
    float inv = 1.0f / s;
    float vals[8] = { v0.x * inv, v0.y * inv, v0.z * inv, v0.w * inv,
                      v1.x * inv, v1.y * inv, v1.z * inv, v1.w * inv };
    __syncwarp();   // all reads of this row complete before permuted writes
#pragma unroll
    for (int r = 0; r < 8; r++) {
        int j = lane * 8 + r;
        int blk = j & ~15, w = j & 15;
        p[blk + ((w & 3) << 2) + (w >> 2)] = f2tf(vals[r]);
    }
}

// ---------------------------------------------------------------------------
// Kernel D: out[b,c] = attn_b @ v[b,c], tf32 mma.sync, 4-stage cp.async.
// CTA 128(M) x 256(N), K=256 in 16 chunks. 256 thr = 8 warps, warp 64x64.
// Smem per stage: A [row][16k, XOR-swz 16B quads] 8KB; B [n][16k, swz] 16KB.
// ---------------------------------------------------------------------------
#define KC 16
#define NSTG 4
#define A_ST 8192
#define B_ST 16384
#define STG_BYTES (A_ST + B_ST)          // 24576
#define SMEM_TOT (NSTG * STG_BYTES)      // 98304

__global__ __launch_bounds__(256, 1)
void mma_out_kernel(float* __restrict__ out) {
    extern __shared__ char smem[];
    const uint32_t sb = smem_u32(smem);
    const int tid = threadIdx.x;
    const int lane = tid & 31, warp = tid >> 5;
    const int warpM = warp & 1, warpN = warp >> 1;
    const int g = lane >> 2, t4 = lane & 3;

    const int i0 = blockIdx.x * 128;
    const int c  = blockIdx.y;
    const int b  = blockIdx.z;
    const float* Ab = g_attn + (size_t)b * NH * NH + (size_t)i0 * NH;
    const float* Bb = g_vt + ((size_t)(b * 8 + c)) * HW;

    // staging indices (A: 2 chunks/thread, B: 4 chunks/thread)
    const int ar0 = tid >> 2, aq = tid & 3;

    float acc[4][8][4];
#pragma unroll
    for (int mi = 0; mi < 4; mi++)
#pragma unroll
        for (int ni = 0; ni < 8; ni++)
#pragma unroll
            for (int r = 0; r < 4; r++) acc[mi][ni][r] = 0.f;

    // prologue: stage chunks 0..2
#pragma unroll
    for (int s = 0; s < NSTG - 1; s++) {
        const float* Ak = Ab + s * KC;
        const float* Bk = Bb + s * KC;
        uint32_t as = sb + s * STG_BYTES;
        uint32_t bs = as + A_ST;
#pragma unroll
        for (int u = 0; u < 2; u++) {
            int row = ar0 + 64 * u;
            CP16(as + row * 64 + ((aq ^ (row & 3)) << 4), Ak + (size_t)row * NH + aq * 4);
        }
#pragma unroll
        for (int u = 0; u < 4; u++) {
            int n = ar0 + 64 * u;
            CP16(bs + n * 64 + ((aq ^ (n & 3)) << 4), Bk + (size_t)n * NH + aq * 4);
        }
        CP_COMMIT();
    }

    for (int kc = 0; kc < 16; kc++) {
        if (kc > 0) __syncthreads();             // slot (kc+3)%4 free (compute kc-1 done)
        const int pf = kc + NSTG - 1;
        if (pf < 16) {
            const float* Ak = Ab + pf * KC;
            const float* Bk = Bb + pf * KC;
            uint32_t as = sb + (pf & 3) * STG_BYTES;
            uint32_t bs = as + A_ST;
#pragma unroll
            for (int u = 0; u < 2; u++) {
                int row = ar0 + 64 * u;
                CP16(as + row * 64 + ((aq ^ (row & 3)) << 4), Ak + (size_t)row * NH + aq * 4);
            }
#pragma unroll
            for (int u = 0; u < 4; u++) {
                int n = ar0 + 64 * u;
                CP16(bs + n * 64 + ((aq ^ (n & 3)) << 4), Bk + (size_t)n * NH + aq * 4);
            }
        }
        CP_COMMIT();
        CP_WAIT2();                              // chunk kc arrived
        __syncthreads();

        const uint32_t as = sb + (kc & 3) * STG_BYTES;
        const uint32_t bs = as + A_ST;
        const uint32_t swq = (uint32_t)(t4 ^ (g & 3)) << 4;

        float4 afr[4][2];
#pragma unroll
        for (int mi = 0; mi < 4; mi++) {
            int rb = warpM * 64 + mi * 16 + g;
            afr[mi][0] = lds128(as + rb * 64 + swq);
            afr[mi][1] = lds128(as + (rb + 8) * 64 + swq);
        }
#pragma unroll
        for (int ni = 0; ni < 8; ni++) {
            int n = warpN * 64 + ni * 8 + g;
            float4 bf = lds128(bs + n * 64 + swq);
#pragma unroll
            for (int mi = 0; mi < 4; mi++) {
                MMA_TF32(acc[mi][ni],
                         U(afr[mi][0].x), U(afr[mi][1].x),
                         U(afr[mi][0].y), U(afr[mi][1].y),
                         U(bf.x), U(bf.y));
                MMA_TF32(acc[mi][ni],
                         U(afr[mi][0].z), U(afr[mi][1].z),
                         U(afr[mi][0].w), U(afr[mi][1].w),
                         U(bf.z), U(bf.w));
            }
        }
    }

    // epilogue
    float* ob = out + ((size_t)(b * 8 + c)) * HW;
#pragma unroll
    for (int mi = 0; mi < 4; mi++) {
        int row = i0 + warpM * 64 + mi * 16 + g;
#pragma unroll
        for (int ni = 0; ni < 8; ni++) {
            int col = warpN * 64 + ni * 8 + t4 * 2;
            *(float2*)(ob + (size_t)row * NW + col) =
                make_float2(acc[mi][ni][0], acc[mi][ni][1]);
            *(float2*)(ob + (size_t)(row + 8) * NW + col) =
                make_float2(acc[mi][ni][2], acc[mi][ni][3]);
        }
    }
}

// ---------------------------------------------------------------------------
extern "C" void kernel_launch(void* const* d_in, const int* in_sizes, int n_in,
                              void* d_out, int out_size) {
    const float* x  = (const float*)d_in[0];
    const float* w1 = (const float*)d_in[1];
    const float* b1 = (const float*)d_in[2];
    const float* w2 = (const float*)d_in[3];
    const float* b2 = (const float*)d_in[4];
    const float* w3 = (const float*)d_in[5];
    const float* b3 = (const float*)d_in[6];
    float* out = (float*)d_out;

    static bool configured = false;
    if (!configured) {
        cudaFuncSetAttribute(mma_out_kernel,
                             cudaFuncAttributeMaxDynamicSharedMemorySize, SMEM_TOT);
        configured = true;
    }

    dim3 ga(8, 8, NB);
    proj_kernel<<<ga, 256>>>(x, w1, b1, w2, b2, w3, b3);
    dim3 gb(2, 2, NB);
    scores_kernel<<<gb, 256>>>();
    softmax_kernel<<<(NB * NH) / 8, 256>>>();
    dim3 gd(2, 8, NB);   // m-tile fastest: CTA pairs share v[b,c] in L2
    mma_out_kernel<<<gd, 256, SMEM_TOT>>>(out);
}

// round 5
// speedup vs baseline: 2.3571x; 1.1255x over previous
#include <cuda_runtime.h>
#include <cstdint>

#define NB 64
#define NC 8
#define NH 256
#define NW 256
#define HW (NH*NW)

// Scratch (__device__ globals per allocation-free rule)
__device__ float g_q[NB*HW];                 // 16.7 MB
__device__ float g_k[NB*HW];                 // 16.7 MB
__device__ float g_attn[NB*NH*NH];           // 16.7 MB (tf32, k-permuted after softmax)
__device__ float g_vt[(size_t)NB*NC*HW];     // 134 MB, [b][c][w][j] tf32, j-permuted

// ---------------------------------------------------------------------------
// helpers
// ---------------------------------------------------------------------------
__device__ __forceinline__ float f2tf(float x) {
    uint32_t u;
    asm("cvt.rna.tf32.f32 %0, %1;" : "=r"(u) : "f"(x));
    return __uint_as_float(u);
}
__device__ __forceinline__ uint32_t smem_u32(const void* p) {
    uint32_t a;
    asm("{ .reg .u64 t; cvta.to.shared.u64 t, %1; cvt.u32.u64 %0, t; }" : "=r"(a) : "l"(p));
    return a;
}
__device__ __forceinline__ float4 lds128(uint32_t a) {
    float4 v;
    asm volatile("ld.shared.v4.f32 {%0,%1,%2,%3}, [%4];"
                 : "=f"(v.x), "=f"(v.y), "=f"(v.z), "=f"(v.w) : "r"(a));
    return v;
}
#define CP16(sa, ga) asm volatile("cp.async.cg.shared.global [%0], [%1], 16;" :: "r"(sa), "l"(ga))
#define CP_COMMIT()  asm volatile("cp.async.commit_group;")
#define CP_WAIT1()   asm volatile("cp.async.wait_group 1;")
#define MMA_TF32(d, a0, a1, a2, a3, b0, b1)                                       \
    asm volatile("mma.sync.aligned.m16n8k8.row.col.f32.tf32.tf32.f32 "            \
                 "{%0,%1,%2,%3},{%4,%5,%6,%7},{%8,%9},{%0,%1,%2,%3};"             \
                 : "+f"(d[0]), "+f"(d[1]), "+f"(d[2]), "+f"(d[3])                  \
                 : "r"(a0), "r"(a1), "r"(a2), "r"(a3), "r"(b0), "r"(b1))
#define U(f) __float_as_uint(f)

// ---------------------------------------------------------------------------
// Kernel A: fused projections (vectorized). q,k 1x1 conv (fp32); v = w3@x + b3
// (b3 folded; valid since softmax rows sum to 1), written TRANSPOSED
// [b][c][w][j], tf32-rounded, j permuted within 16-blocks.
// Tile 32j x 32w; thread = (1 j-row, 4 w). grid (8 w-tiles, 8 j-tiles, 64 b)
// ---------------------------------------------------------------------------
__global__ __launch_bounds__(256)
void proj_kernel(const float* __restrict__ x,
                 const float* __restrict__ w1, const float* __restrict__ b1,
                 const float* __restrict__ w2, const float* __restrict__ b2,
                 const float* __restrict__ w3, const float* __restrict__ b3) {
    __shared__ float xt_s[8][32][33];
    __shared__ float w1s[8], w2s[8], w3s[64], b3s[8], bqk[2];
    const int tid = threadIdx.x;
    if (tid < 8)  { w1s[tid] = w1[tid]; w2s[tid] = w2[tid]; b3s[tid] = b3[tid]; }
    if (tid < 64) w3s[tid] = w3[tid];
    if (tid == 0) { bqk[0] = b1[0]; bqk[1] = b2[0]; }
    __syncthreads();
    const int b = blockIdx.z, j0 = blockIdx.y * 32, w0 = blockIdx.x * 32;
    const int jl = tid >> 3, wq = (tid & 7) << 2;
    const float* xb = x + (size_t)b * NC * HW + (size_t)(j0 + jl) * NW + w0 + wq;

    float4 xv[8];
#pragma unroll
    for (int c = 0; c < 8; c++) xv[c] = *(const float4*)(xb + (size_t)c * HW);

    float4 q = make_float4(bqk[0], bqk[0], bqk[0], bqk[0]);
    float4 k = make_float4(bqk[1], bqk[1], bqk[1], bqk[1]);
#pragma unroll
    for (int c = 0; c < 8; c++) {
        q.x = fmaf(w1s[c], xv[c].x, q.x); q.y = fmaf(w1s[c], xv[c].y, q.y);
        q.z = fmaf(w1s[c], xv[c].z, q.z); q.w = fmaf(w1s[c], xv[c].w, q.w);
        k.x = fmaf(w2s[c], xv[c].x, k.x); k.y = fmaf(w2s[c], xv[c].y, k.y);
        k.z = fmaf(w2s[c], xv[c].z, k.z); k.w = fmaf(w2s[c], xv[c].w, k.w);
    }
    *(float4*)(g_q + (size_t)b * HW + (size_t)(j0 + jl) * NW + w0 + wq) = q;
    *(float4*)(g_k + (size_t)b * HW + (size_t)(j0 + jl) * NW + w0 + wq) = k;

#pragma unroll
    for (int c = 0; c < 8; c++) {
        float4 v = make_float4(b3s[c], b3s[c], b3s[c], b3s[c]);
#pragma unroll
        for (int cp = 0; cp < 8; cp++) {
            float w = w3s[c * 8 + cp];
            v.x = fmaf(w, xv[cp].x, v.x); v.y = fmaf(w, xv[cp].y, v.y);
            v.z = fmaf(w, xv[cp].z, v.z); v.w = fmaf(w, xv[cp].w, v.w);
        }
        xt_s[c][jl][wq + 0] = v.x; xt_s[c][jl][wq + 1] = v.y;
        xt_s[c][jl][wq + 2] = v.z; xt_s[c][jl][wq + 3] = v.w;
    }
    __syncthreads();
    // transposed + permuted + tf32 write (coalesced over j)
    const int jj = tid & 31, wl = tid >> 5;
    const int jp = (jj & 16) | (((jj & 3) << 2) | ((jj & 15) >> 2));
#pragma unroll
    for (int c = 0; c < 8; c++)
#pragma unroll
        for (int ws = 0; ws < 32; ws += 8) {
            int wg = ws + wl;
            g_vt[(((size_t)(b * 8 + c)) * NW + w0 + wg) * NH + j0 + jp] =
                f2tf(xt_s[c][jj][wg]);
        }
}

// ---------------------------------------------------------------------------
// Kernel B: scores (fp32, validated)
// ---------------------------------------------------------------------------
__global__ __launch_bounds__(256, 2)
void scores_kernel() {
    __shared__ float qs[8][128];
    __shared__ float ks[8][128];
    const int b  = blockIdx.z;
    const int i0 = blockIdx.y * 128;
    const int j0 = blockIdx.x * 128;
    const float* q = g_q + (size_t)b * HW;
    const float* k = g_k + (size_t)b * HW;
    const int tid = threadIdx.x;
    const int tx = tid & 15, ty = tid >> 4;
    const int lr = tid >> 1;
    const int lc = (tid & 1) * 4;

    float acc[8][8];
#pragma unroll
    for (int i = 0; i < 8; i++)
#pragma unroll
        for (int j = 0; j < 8; j++) acc[i][j] = 0.f;

    for (int kk = 0; kk < NW; kk += 8) {
        float4 qv = *(const float4*)(q + (size_t)(i0 + lr) * NW + kk + lc);
        float4 kv = *(const float4*)(k + (size_t)(j0 + lr) * NW + kk + lc);
        __syncthreads();
        qs[lc + 0][lr] = qv.x; qs[lc + 1][lr] = qv.y;
        qs[lc + 2][lr] = qv.z; qs[lc + 3][lr] = qv.w;
        ks[lc + 0][lr] = kv.x; ks[lc + 1][lr] = kv.y;
        ks[lc + 2][lr] = kv.z; ks[lc + 3][lr] = kv.w;
        __syncthreads();
#pragma unroll
        for (int u = 0; u < 8; u++) {
            float a[8], bb[8];
            *(float4*)&a[0]  = *(const float4*)&qs[u][ty * 8];
            *(float4*)&a[4]  = *(const float4*)&qs[u][ty * 8 + 4];
            *(float4*)&bb[0] = *(const float4*)&ks[u][tx * 8];
            *(float4*)&bb[4] = *(const float4*)&ks[u][tx * 8 + 4];
#pragma unroll
            for (int i = 0; i < 8; i++)
#pragma unroll
                for (int j = 0; j < 8; j++)
                    acc[i][j] = fmaf(a[i], bb[j], acc[i][j]);
        }
    }
    float* dst = g_attn + (size_t)b * NH * NH;
#pragma unroll
    for (int i = 0; i < 8; i++) {
        int row = i0 + ty * 8 + i;
        *(float4*)(dst + (size_t)row * NH + j0 + tx * 8) =
            make_float4(acc[i][0], acc[i][1], acc[i][2], acc[i][3]);
        *(float4*)(dst + (size_t)row * NH + j0 + tx * 8 + 4) =
            make_float4(acc[i][4], acc[i][5], acc[i][6], acc[i][7]);
    }
}

// ---------------------------------------------------------------------------
// Kernel C: row softmax (fp32 math), stores tf32-rounded + k-permuted.
// ---------------------------------------------------------------------------
__global__ __launch_bounds__(256)
void softmax_kernel() {
    int row  = blockIdx.x * 8 + (threadIdx.x >> 5);
    int lane = threadIdx.x & 31;
    float* p = g_attn + (size_t)row * NH;
    float4 v0 = *(const float4*)(p + lane * 8);
    float4 v1 = *(const float4*)(p + lane * 8 + 4);
    float m = fmaxf(fmaxf(fmaxf(v0.x, v0.y), fmaxf(v0.z, v0.w)),
                    fmaxf(fmaxf(v1.x, v1.y), fmaxf(v1.z, v1.w)));
#pragma unroll
    for (int o = 16; o > 0; o >>= 1) m = fmaxf(m, __shfl_xor_sync(0xffffffffu, m, o));
    v0.x = expf(v0.x - m); v0.y = expf(v0.y - m);
    v0.z = expf(v0.z - m); v0.w = expf(v0.w - m);
    v1.x = expf(v1.x - m); v1.y = expf(v1.y - m);
    v1.z = expf(v1.z - m); v1.w = expf(v1.w - m);
    float s = v0.x + v0.y + v0.z + v0.w + v1.x + v1.y + v1.z + v1.w;
#pragma unroll
    for (int o = 16; o > 0; o >>= 1) s += __shfl_xor_sync(0xffffffffu, s, o);
    float inv = 1.0f / s;
    float vals[8] = { v0.x * inv, v0.y * inv, v0.z * inv, v0.w * inv,
                      v1.x * inv, v1.y * inv, v1.z * inv, v1.w * inv };
    __syncwarp();
#pragma unroll
    for (int r = 0; r < 8; r++) {
        int j = lane * 8 + r;
        int blk = j & ~15, w = j & 15;
        p[blk + ((w & 3) << 2) + (w >> 2)] = f2tf(vals[r]);
    }
}

// ---------------------------------------------------------------------------
// Kernel D: out[b,c] = attn_b @ v[b,c], tf32 mma.sync, 3-stage cp.async ring,
// ONE barrier per chunk. 512 thr = 16 warps (4m x 4n), warp tile 32x64.
// Smem/stage: A [row][16k, XOR-swz quads] 8KB; B [n][16k, swz] 16KB.
// ---------------------------------------------------------------------------
#define KC 16
#define NSTG 3
#define A_ST 8192
#define B_ST 16384
#define STG_BYTES (A_ST + B_ST)          // 24576
#define SMEM_TOT (NSTG * STG_BYTES)      // 73728

__global__ __launch_bounds__(512, 1)
void mma_out_kernel(float* __restrict__ out) {
    extern __shared__ char smem[];
    const uint32_t sb = smem_u32(smem);
    const int tid = threadIdx.x;
    const int lane = tid & 31, warp = tid >> 5;
    const int warpM = warp & 3, warpN = warp >> 2;
    const int g = lane >> 2, t4 = lane & 3;

    const int i0 = blockIdx.x * 128;
    const int c  = blockIdx.y;
    const int b  = blockIdx.z;
    const float* Ab = g_attn + (size_t)b * NH * NH + (size_t)i0 * NH;
    const float* Bb = g_vt + ((size_t)(b * 8 + c)) * HW;

    // staging indices: A 1 quad/thread, B 2 quads/thread
    const int ar = tid >> 2, aq = tid & 3;
    const uint32_t a_soff = (uint32_t)(ar * 64 + ((aq ^ (ar & 3)) << 4));
    const size_t   a_goff = (size_t)ar * NH + aq * 4;

    float acc[2][8][4];
#pragma unroll
    for (int mi = 0; mi < 2; mi++)
#pragma unroll
        for (int ni = 0; ni < 8; ni++)
#pragma unroll
            for (int r = 0; r < 4; r++) acc[mi][ni][r] = 0.f;

    // prologue: stage chunks 0,1
#pragma unroll
    for (int s = 0; s < NSTG - 1; s++) {
        uint32_t as = sb + s * STG_BYTES, bs = as + A_ST;
        CP16(as + a_soff, Ab + s * KC + a_goff);
#pragma unroll
        for (int u = 0; u < 2; u++) {
            int n = ar + 128 * u;
            CP16(bs + n * 64 + ((aq ^ (n & 3)) << 4), Bb + s * KC + (size_t)n * NH + aq * 4);
        }
        CP_COMMIT();
    }

    for (int kc = 0; kc < 16; kc++) {
        CP_WAIT1();                       // chunk kc arrived
        __syncthreads();                  // also: all warps done with slot (kc+2)%3

        const int pf = kc + NSTG - 1;
        if (pf < 16) {
            uint32_t as = sb + (pf % NSTG) * STG_BYTES, bs = as + A_ST;
            CP16(as + a_soff, Ab + pf * KC + a_goff);
#pragma unroll
            for (int u = 0; u < 2; u++) {
                int n = ar + 128 * u;
                CP16(bs + n * 64 + ((aq ^ (n & 3)) << 4),
                     Bb + pf * KC + (size_t)n * NH + aq * 4);
            }
        }
        CP_COMMIT();

        const uint32_t as = sb + (kc % NSTG) * STG_BYTES;
        const uint32_t bs = as + A_ST;
        const uint32_t swq = (uint32_t)(t4 ^ (g & 3)) << 4;

        float4 afr[2][2];
#pragma unroll
        for (int mi = 0; mi < 2; mi++) {
            int rb = warpM * 32 + mi * 16 + g;
            afr[mi][0] = lds128(as + rb * 64 + swq);
            afr[mi][1] = lds128(as + (rb + 8) * 64 + swq);
        }
#pragma unroll
        for (int ni = 0; ni < 8; ni++) {
            int n = warpN * 64 + ni * 8 + g;
            float4 bf = lds128(bs + n * 64 + swq);
#pragma unroll
            for (int mi = 0; mi < 2; mi++) {
                MMA_TF32(acc[mi][ni],
                         U(afr[mi][0].x), U(afr[mi][1].x),
                         U(afr[mi][0].y), U(afr[mi][1].y),
                         U(bf.x), U(bf.y));
                MMA_TF32(acc[mi][ni],
                         U(afr[mi][0].z), U(afr[mi][1].z),
                         U(afr[mi][0].w), U(afr[mi][1].w),
                         U(bf.z), U(bf.w));
            }
        }
    }

    // epilogue
    float* ob = out + ((size_t)(b * 8 + c)) * HW;
#pragma unroll
    for (int mi = 0; mi < 2; mi++) {
        int row = i0 + warpM * 32 + mi * 16 + g;
#pragma unroll
        for (int ni = 0; ni < 8; ni++) {
            int col = warpN * 64 + ni * 8 + t4 * 2;
            *(float2*)(ob + (size_t)row * NW + col) =
                make_float2(acc[mi][ni][0], acc[mi][ni][1]);
            *(float2*)(ob + (size_t)(row + 8) * NW + col) =
                make_float2(acc[mi][ni][2], acc[mi][ni][3]);
        }
    }
}

// ---------------------------------------------------------------------------
extern "C" void kernel_launch(void* const* d_in, const int* in_sizes, int n_in,
                              void* d_out, int out_size) {
    const float* x  = (const float*)d_in[0];
    const float* w1 = (const float*)d_in[1];
    const float* b1 = (const float*)d_in[2];
    const float* w2 = (const float*)d_in[3];
    const float* b2 = (const float*)d_in[4];
    const float* w3 = (const float*)d_in[5];
    const float* b3 = (const float*)d_in[6];
    float* out = (float*)d_out;

    static bool configured = false;
    if (!configured) {
        cudaFuncSetAttribute(mma_out_kernel,
                             cudaFuncAttributeMaxDynamicSharedMemorySize, SMEM_TOT);
        configured = true;
    }

    dim3 ga(8, 8, NB);
    proj_kernel<<<ga, 256>>>(x, w1, b1, w2, b2, w3, b3);
    dim3 gb(2, 2, NB);
    scores_kernel<<<gb, 256>>>();
    softmax_kernel<<<(NB * NH) / 8, 256>>>();
    dim3 gd(2, 8, NB);   // m-tile fastest: CTA pairs share v[b,c] in L2
    mma_out_kernel<<<gd, 512, SMEM_TOT>>>(out);
}

// round 6
// speedup vs baseline: 2.5467x; 1.0804x over previous
#include <cuda_runtime.h>
#include <cstdint>
#include <cfloat>

#define NB 64
#define NC 8
#define NH 256
#define NW 256
#define HW (NH*NW)

// Scratch (__device__ globals per allocation-free rule)
__device__ float g_q[NB*HW];                 // fp32, w-permuted within 16-blocks
__device__ float g_k[NB*HW];                 // fp32, w-permuted within 16-blocks
__device__ float g_attn[NB*NH*NH];           // tf32, j-permuted (written by fused kernel)
__device__ float g_vt[(size_t)NB*NC*HW];     // [b][c][w][j] tf32, j-permuted

// ---------------------------------------------------------------------------
// helpers
// ---------------------------------------------------------------------------
__device__ __forceinline__ float f2tf(float x) {
    uint32_t u;
    asm("cvt.rna.tf32.f32 %0, %1;" : "=r"(u) : "f"(x));
    return __uint_as_float(u);
}
__device__ __forceinline__ float4 tf4(float4 v) {
    return make_float4(f2tf(v.x), f2tf(v.y), f2tf(v.z), f2tf(v.w));
}
__device__ __forceinline__ float4 tf4lo(float4 v, float4 h) {
    return make_float4(f2tf(v.x - h.x), f2tf(v.y - h.y),
                       f2tf(v.z - h.z), f2tf(v.w - h.w));
}
__device__ __forceinline__ uint32_t smem_u32(const void* p) {
    uint32_t a;
    asm("{ .reg .u64 t; cvta.to.shared.u64 t, %1; cvt.u32.u64 %0, t; }" : "=r"(a) : "l"(p));
    return a;
}
__device__ __forceinline__ float4 lds128(uint32_t a) {
    float4 v;
    asm volatile("ld.shared.v4.f32 {%0,%1,%2,%3}, [%4];"
                 : "=f"(v.x), "=f"(v.y), "=f"(v.z), "=f"(v.w) : "r"(a));
    return v;
}
// exp(x) for x <= 0, FMA-pipe only (no MUFU): 2^(x*log2e), deg-6 Taylor on [-.5,.5]
__device__ __forceinline__ float fast_exp(float x) {
    float t = fmaxf(x * 1.4426950408889634f, -126.0f);
    float n = rintf(t);
    float f = t - n;
    float p = fmaf(f, 0.00015403530393381609f, 0.0013333558146428443f);
    p = fmaf(f, p, 0.009618129107628477f);
    p = fmaf(f, p, 0.0555041086648216f);
    p = fmaf(f, p, 0.2402265069591007f);
    p = fmaf(f, p, 0.6931471805599453f);
    p = fmaf(f, p, 1.0f);
    return __int_as_float(__float_as_int(p) + (((int)n) << 23));
}
#define CP16(sa, ga) asm volatile("cp.async.cg.shared.global [%0], [%1], 16;" :: "r"(sa), "l"(ga))
#define CP_COMMIT()  asm volatile("cp.async.commit_group;")
#define CP_WAIT1()   asm volatile("cp.async.wait_group 1;")
#define MMA_TF32(d, a0, a1, a2, a3, b0, b1)                                       \
    asm volatile("mma.sync.aligned.m16n8k8.row.col.f32.tf32.tf32.f32 "            \
                 "{%0,%1,%2,%3},{%4,%5,%6,%7},{%8,%9},{%0,%1,%2,%3};"             \
                 : "+f"(d[0]), "+f"(d[1]), "+f"(d[2]), "+f"(d[3])                  \
                 : "r"(a0), "r"(a1), "r"(a2), "r"(a3), "r"(b0), "r"(b1))
#define U(f) __float_as_uint(f)

// ---------------------------------------------------------------------------
// Kernel A: fused projections. q,k 1x1 conv (fp32, stored w-permuted within
// 16-blocks for MMA frag layout); v = w3@x + b3 (b3 folded; softmax rows sum
// to 1), TRANSPOSED [b][c][w][j], tf32, j-permuted.
// ---------------------------------------------------------------------------
__global__ __launch_bounds__(256)
void proj_kernel(const float* __restrict__ x,
                 const float* __restrict__ w1, const float* __restrict__ b1,
                 const float* __restrict__ w2, const float* __restrict__ b2,
                 const float* __restrict__ w3, const float* __restrict__ b3) {
    __shared__ float xt_s[8][32][33];
    __shared__ float w1s[8], w2s[8], w3s[64], b3s[8], bqk[2];
    const int tid = threadIdx.x;
    if (tid < 8)  { w1s[tid] = w1[tid]; w2s[tid] = w2[tid]; b3s[tid] = b3[tid]; }
    if (tid < 64) w3s[tid] = w3[tid];
    if (tid == 0) { bqk[0] = b1[0]; bqk[1] = b2[0]; }
    __syncthreads();
    const int b = blockIdx.z, j0 = blockIdx.y * 32, w0 = blockIdx.x * 32;
    const int jl = tid >> 3, wq = (tid & 7) << 2;
    const float* xb = x + (size_t)b * NC * HW + (size_t)(j0 + jl) * NW + w0 + wq;

    float4 xv[8];
#pragma unroll
    for (int c = 0; c < 8; c++) xv[c] = *(const float4*)(xb + (size_t)c * HW);

    float4 q = make_float4(bqk[0], bqk[0], bqk[0], bqk[0]);
    float4 k = make_float4(bqk[1], bqk[1], bqk[1], bqk[1]);
#pragma unroll
    for (int c = 0; c < 8; c++) {
        q.x = fmaf(w1s[c], xv[c].x, q.x); q.y = fmaf(w1s[c], xv[c].y, q.y);
        q.z = fmaf(w1s[c], xv[c].z, q.z); q.w = fmaf(w1s[c], xv[c].w, q.w);
        k.x = fmaf(w2s[c], xv[c].x, k.x); k.y = fmaf(w2s[c], xv[c].y, k.y);
        k.z = fmaf(w2s[c], xv[c].z, k.z); k.w = fmaf(w2s[c], xv[c].w, k.w);
    }
    // permuted scalar stores: w = w0+wq+i  ->  b16 + 4i + r4
    {
        const int b16 = (w0 + wq) & ~15, r4 = (wq & 15) >> 2;
        float* qp = g_q + (size_t)b * HW + (size_t)(j0 + jl) * NW + b16 + r4;
        float* kp = g_k + (size_t)b * HW + (size_t)(j0 + jl) * NW + b16 + r4;
        qp[0] = q.x; qp[4] = q.y; qp[8] = q.z; qp[12] = q.w;
        kp[0] = k.x; kp[4] = k.y; kp[8] = k.z; kp[12] = k.w;
    }

#pragma unroll
    for (int c = 0; c < 8; c++) {
        float4 v = make_float4(b3s[c], b3s[c], b3s[c], b3s[c]);
#pragma unroll
        for (int cp = 0; cp < 8; cp++) {
            float w = w3s[c * 8 + cp];
            v.x = fmaf(w, xv[cp].x, v.x); v.y = fmaf(w, xv[cp].y, v.y);
            v.z = fmaf(w, xv[cp].z, v.z); v.w = fmaf(w, xv[cp].w, v.w);
        }
        xt_s[c][jl][wq + 0] = v.x; xt_s[c][jl][wq + 1] = v.y;
        xt_s[c][jl][wq + 2] = v.z; xt_s[c][jl][wq + 3] = v.w;
    }
    __syncthreads();
    const int jj = tid & 31, wl = tid >> 5;
    const int jp = (jj & 16) | (((jj & 3) << 2) | ((jj & 15) >> 2));
#pragma unroll
    for (int c = 0; c < 8; c++)
#pragma unroll
        for (int ws = 0; ws < 32; ws += 8) {
            int wg = ws + wl;
            g_vt[(((size_t)(b * 8 + c)) * NW + w0 + wg) * NH + j0 + jp] =
                f2tf(xt_s[c][jj][wg]);
        }
}

// ---------------------------------------------------------------------------
// Kernel B: FUSED scores+softmax. s = q@k^T via 3-term tf32 split (fp32-grade
// accuracy), softmax in registers (poly exp on FMA pipe), writes g_attn
// tf32 + j-permuted. CTA: 128 rows x 256 cols, K=256. 512 thr, warp 32x64.
// ---------------------------------------------------------------------------
#define KC 16
#define NSTG 3
#define A_ST 8192
#define B_ST 16384
#define STG_BYTES (A_ST + B_ST)
#define SMEM_MMA (NSTG * STG_BYTES)            // 73728
#define SMEM_FUSED (SMEM_MMA + 4 * 128 * 4)    // + reduction buffer

__global__ __launch_bounds__(512, 1)
void scores_softmax_kernel() {
    extern __shared__ char smem[];
    const uint32_t sb = smem_u32(smem);
    float* red = (float*)(smem + SMEM_MMA);    // [4][128]
    const int tid = threadIdx.x;
    const int lane = tid & 31, warp = tid >> 5;
    const int warpM = warp & 3, warpN = warp >> 2;
    const int g = lane >> 2, t4 = lane & 3;

    const int i0 = blockIdx.x * 128;
    const int b  = blockIdx.y;
    const float* Ab = g_q + (size_t)b * HW + (size_t)i0 * NW;
    const float* Bb = g_k + (size_t)b * HW;

    const int ar = tid >> 2, aq = tid & 3;
    const uint32_t a_soff = (uint32_t)(ar * 64 + ((aq ^ (ar & 3)) << 4));
    const size_t   a_goff = (size_t)ar * NW + aq * 4;

    float acc[2][8][4];
#pragma unroll
    for (int mi = 0; mi < 2; mi++)
#pragma unroll
        for (int ni = 0; ni < 8; ni++)
#pragma unroll
            for (int r = 0; r < 4; r++) acc[mi][ni][r] = 0.f;

#pragma unroll
    for (int s = 0; s < NSTG - 1; s++) {
        uint32_t as = sb + s * STG_BYTES, bs = as + A_ST;
        CP16(as + a_soff, Ab + s * KC + a_goff);
#pragma unroll
        for (int u = 0; u < 2; u++) {
            int n = ar + 128 * u;
            CP16(bs + n * 64 + ((aq ^ (n & 3)) << 4), Bb + s * KC + (size_t)n * NW + aq * 4);
        }
        CP_COMMIT();
    }

    for (int kc = 0; kc < 16; kc++) {
        CP_WAIT1();
        __syncthreads();

        const int pf = kc + NSTG - 1;
        if (pf < 16) {
            uint32_t as = sb + (pf % NSTG) * STG_BYTES, bs = as + A_ST;
            CP16(as + a_soff, Ab + pf * KC + a_goff);
#pragma unroll
            for (int u = 0; u < 2; u++) {
                int n = ar + 128 * u;
                CP16(bs + n * 64 + ((aq ^ (n & 3)) << 4),
                     Bb + pf * KC + (size_t)n * NW + aq * 4);
            }
        }
        CP_COMMIT();

        const uint32_t as = sb + (kc % NSTG) * STG_BYTES;
        const uint32_t bs = as + A_ST;
        const uint32_t swq = (uint32_t)(t4 ^ (g & 3)) << 4;

        float4 ahi[2][2], alo[2][2];
#pragma unroll
        for (int mi = 0; mi < 2; mi++) {
            int rb = warpM * 32 + mi * 16 + g;
            float4 r0 = lds128(as + rb * 64 + swq);
            float4 r1 = lds128(as + (rb + 8) * 64 + swq);
            ahi[mi][0] = tf4(r0); alo[mi][0] = tf4lo(r0, ahi[mi][0]);
            ahi[mi][1] = tf4(r1); alo[mi][1] = tf4lo(r1, ahi[mi][1]);
        }
#pragma unroll
        for (int ni = 0; ni < 8; ni++) {
            int n = warpN * 64 + ni * 8 + g;
            float4 bf = lds128(bs + n * 64 + swq);
            float4 bh = tf4(bf), bl = tf4lo(bf, bh);
#pragma unroll
            for (int mi = 0; mi < 2; mi++) {
                // k-half 0 (components x,y)
                MMA_TF32(acc[mi][ni],
                         U(ahi[mi][0].x), U(ahi[mi][1].x),
                         U(ahi[mi][0].y), U(ahi[mi][1].y), U(bh.x), U(bh.y));
                MMA_TF32(acc[mi][ni],
                         U(ahi[mi][0].x), U(ahi[mi][1].x),
                         U(ahi[mi][0].y), U(ahi[mi][1].y), U(bl.x), U(bl.y));
                MMA_TF32(acc[mi][ni],
                         U(alo[mi][0].x), U(alo[mi][1].x),
                         U(alo[mi][0].y), U(alo[mi][1].y), U(bh.x), U(bh.y));
                // k-half 1 (components z,w)
                MMA_TF32(acc[mi][ni],
                         U(ahi[mi][0].z), U(ahi[mi][1].z),
                         U(ahi[mi][0].w), U(ahi[mi][1].w), U(bh.z), U(bh.w));
                MMA_TF32(acc[mi][ni],
                         U(ahi[mi][0].z), U(ahi[mi][1].z),
                         U(ahi[mi][0].w), U(ahi[mi][1].w), U(bl.z), U(bl.w));
                MMA_TF32(acc[mi][ni],
                         U(alo[mi][0].z), U(alo[mi][1].z),
                         U(alo[mi][0].w), U(alo[mi][1].w), U(bh.z), U(bh.w));
            }
        }
    }

    // ---- fused softmax over rows (each lane owns 4 rows x 16 cols) ----
    // rows: rl(mi,h) = warpM*32 + mi*16 + h*8 + g
    float rowv[4];
    // 1) max
#pragma unroll
    for (int mi = 0; mi < 2; mi++)
#pragma unroll
        for (int h = 0; h < 2; h++) {
            float m = -FLT_MAX;
#pragma unroll
            for (int ni = 0; ni < 8; ni++)
                m = fmaxf(m, fmaxf(acc[mi][ni][h * 2], acc[mi][ni][h * 2 + 1]));
            m = fmaxf(m, __shfl_xor_sync(0xffffffffu, m, 1));
            m = fmaxf(m, __shfl_xor_sync(0xffffffffu, m, 2));
            rowv[mi * 2 + h] = m;
        }
    if (t4 == 0) {
#pragma unroll
        for (int mi = 0; mi < 2; mi++)
#pragma unroll
            for (int h = 0; h < 2; h++)
                red[warpN * 128 + warpM * 32 + mi * 16 + h * 8 + g] = rowv[mi * 2 + h];
    }
    __syncthreads();
    float rowmax[4];
#pragma unroll
    for (int mi = 0; mi < 2; mi++)
#pragma unroll
        for (int h = 0; h < 2; h++) {
            int rl = warpM * 32 + mi * 16 + h * 8 + g;
            rowmax[mi * 2 + h] = fmaxf(fmaxf(red[rl], red[128 + rl]),
                                       fmaxf(red[256 + rl], red[384 + rl]));
        }
    __syncthreads();
    // 2) exp + sum
#pragma unroll
    for (int mi = 0; mi < 2; mi++)
#pragma unroll
        for (int h = 0; h < 2; h++) {
            float m = rowmax[mi * 2 + h], s = 0.f;
#pragma unroll
            for (int ni = 0; ni < 8; ni++) {
                float e0 = fast_exp(acc[mi][ni][h * 2] - m);
                float e1 = fast_exp(acc[mi][ni][h * 2 + 1] - m);
                acc[mi][ni][h * 2] = e0; acc[mi][ni][h * 2 + 1] = e1;
                s += e0 + e1;
            }
            s += __shfl_xor_sync(0xffffffffu, s, 1);
            s += __shfl_xor_sync(0xffffffffu, s, 2);
            rowv[mi * 2 + h] = s;
        }
    if (t4 == 0) {
#pragma unroll
        for (int mi = 0; mi < 2; mi++)
#pragma unroll
            for (int h = 0; h < 2; h++)
                red[warpN * 128 + warpM * 32 + mi * 16 + h * 8 + g] = rowv[mi * 2 + h];
    }
    __syncthreads();
    // 3) scale + permuted tf32 store
    float* attn = g_attn + (size_t)b * NH * NH;
#pragma unroll
    for (int mi = 0; mi < 2; mi++)
#pragma unroll
        for (int h = 0; h < 2; h++) {
            int rl = warpM * 32 + mi * 16 + h * 8 + g;
            float inv = 1.0f / (red[rl] + red[128 + rl] + red[256 + rl] + red[384 + rl]);
            size_t rb = (size_t)(i0 + rl) * NH;
#pragma unroll
            for (int ni = 0; ni < 8; ni++) {
                int j = warpN * 64 + ni * 8 + t4 * 2;
                int p = (j & ~15) + ((j & 3) << 2) + ((j & 15) >> 2);
                attn[rb + p]     = f2tf(acc[mi][ni][h * 2] * inv);
                attn[rb + p + 4] = f2tf(acc[mi][ni][h * 2 + 1] * inv);
            }
        }
}

// ---------------------------------------------------------------------------
// Kernel D: out[b,c] = attn_b @ v[b,c], tf32 mma.sync, 3-stage cp.async ring,
// one barrier/chunk, B-fragment prefetch pipelining.
// ---------------------------------------------------------------------------
__global__ __launch_bounds__(512, 1)
void mma_out_kernel(float* __restrict__ out) {
    extern __shared__ char smem[];
    const uint32_t sb = smem_u32(smem);
    const int tid = threadIdx.x;
    const int lane = tid & 31, warp = tid >> 5;
    const int warpM = warp & 3, warpN = warp >> 2;
    const int g = lane >> 2, t4 = lane & 3;

    const int i0 = blockIdx.x * 128;
    const int c  = blockIdx.y;
    const int b  = blockIdx.z;
    const float* Ab = g_attn + (size_t)b * NH * NH + (size_t)i0 * NH;
    const float* Bb = g_vt + ((size_t)(b * 8 + c)) * HW;

    const int ar = tid >> 2, aq = tid & 3;
    const uint32_t a_soff = (uint32_t)(ar * 64 + ((aq ^ (ar & 3)) << 4));
    const size_t   a_goff = (size_t)ar * NH + aq * 4;

    float acc[2][8][4];
#pragma unroll
    for (int mi = 0; mi < 2; mi++)
#pragma unroll
        for (int ni = 0; ni < 8; ni++)
#pragma unroll
            for (int r = 0; r < 4; r++) acc[mi][ni][r] = 0.f;

#pragma unroll
    for (int s = 0; s < NSTG - 1; s++) {
        uint32_t as = sb + s * STG_BYTES, bs = as + A_ST;
        CP16(as + a_soff, Ab + s * KC + a_goff);
#pragma unroll
        for (int u = 0; u < 2; u++) {
            int n = ar + 128 * u;
            CP16(bs + n * 64 + ((aq ^ (n & 3)) << 4), Bb + s * KC + (size_t)n * NH + aq * 4);
        }
        CP_COMMIT();
    }

    for (int kc = 0; kc < 16; kc++) {
        CP_WAIT1();
        __syncthreads();

        const int pf = kc + NSTG - 1;
        if (pf < 16) {
            uint32_t as = sb + (pf % NSTG) * STG_BYTES, bs = as + A_ST;
            CP16(as + a_soff, Ab + pf * KC + a_goff);
#pragma unroll
            for (int u = 0; u < 2; u++) {
                int n = ar + 128 * u;
                CP16(bs + n * 64 + ((aq ^ (n & 3)) << 4),
                     Bb + pf * KC + (size_t)n * NH + aq * 4);
            }
        }
        CP_COMMIT();

        const uint32_t as = sb + (kc % NSTG) * STG_BYTES;
        const uint32_t bs = as + A_ST;
        const uint32_t swq = (uint32_t)(t4 ^ (g & 3)) << 4;

        float4 afr[2][2];
#pragma unroll
        for (int mi = 0; mi < 2; mi++) {
            int rb = warpM * 32 + mi * 16 + g;
            afr[mi][0] = lds128(as + rb * 64 + swq);
            afr[mi][1] = lds128(as + (rb + 8) * 64 + swq);
        }
        float4 bf = lds128(bs + (warpN * 64 + g) * 64 + swq);
#pragma unroll
        for (int ni = 0; ni < 8; ni++) {
            float4 bfn;
            if (ni < 7)
                bfn = lds128(bs + (warpN * 64 + (ni + 1) * 8 + g) * 64 + swq);
#pragma unroll
            for (int mi = 0; mi < 2; mi++) {
                MMA_TF32(acc[mi][ni],
                         U(afr[mi][0].x), U(afr[mi][1].x),
                         U(afr[mi][0].y), U(afr[mi][1].y),
                         U(bf.x), U(bf.y));
                MMA_TF32(acc[mi][ni],
                         U(afr[mi][0].z), U(afr[mi][1].z),
                         U(afr[mi][0].w), U(afr[mi][1].w),
                         U(bf.z), U(bf.w));
            }
            bf = bfn;
        }
    }

    float* ob = out + ((size_t)(b * 8 + c)) * HW;
#pragma unroll
    for (int mi = 0; mi < 2; mi++) {
        int row = i0 + warpM * 32 + mi * 16 + g;
#pragma unroll
        for (int ni = 0; ni < 8; ni++) {
            int col = warpN * 64 + ni * 8 + t4 * 2;
            *(float2*)(ob + (size_t)row * NW + col) =
                make_float2(acc[mi][ni][0], acc[mi][ni][1]);
            *(float2*)(ob + (size_t)(row + 8) * NW + col) =
                make_float2(acc[mi][ni][2], acc[mi][ni][3]);
        }
    }
}

// ---------------------------------------------------------------------------
extern "C" void kernel_launch(void* const* d_in, const int* in_sizes, int n_in,
                              void* d_out, int out_size) {
    const float* x  = (const float*)d_in[0];
    const float* w1 = (const float*)d_in[1];
    const float* b1 = (const float*)d_in[2];
    const float* w2 = (const float*)d_in[3];
    const float* b2 = (const float*)d_in[4];
    const float* w3 = (const float*)d_in[5];
    const float* b3 = (const float*)d_in[6];
    float* out = (float*)d_out;

    static bool configured = false;
    if (!configured) {
        cudaFuncSetAttribute(scores_softmax_kernel,
                             cudaFuncAttributeMaxDynamicSharedMemorySize, SMEM_FUSED);
        cudaFuncSetAttribute(mma_out_kernel,
                             cudaFuncAttributeMaxDynamicSharedMemorySize, SMEM_MMA);
        configured = true;
    }

    dim3 ga(8, 8, NB);
    proj_kernel<<<ga, 256>>>(x, w1, b1, w2, b2, w3, b3);
    dim3 gs(2, NB);
    scores_softmax_kernel<<<gs, 512, SMEM_FUSED>>>();
    dim3 gd(2, 8, NB);
    mma_out_kernel<<<gd, 512, SMEM_MMA>>>(out);
}

// round 7
// speedup vs baseline: 2.6709x; 1.0488x over previous
#include <cuda_runtime.h>
#include <cstdint>
#include <cfloat>

#define NB 64
#define NC 8
#define NH 256
#define NW 256
#define HW (NH*NW)

// Scratch (__device__ globals per allocation-free rule)
__device__ float g_q[NB*HW];                 // fp32, w-permuted within 16-blocks
__device__ float g_k[NB*HW];                 // fp32, w-permuted within 16-blocks
__device__ float g_attn[NB*NH*NH];           // tf32, j-permuted
__device__ float g_vt[(size_t)NB*NC*HW];     // [b][c][w][j] tf32, j-permuted

// ---------------------------------------------------------------------------
// helpers
// ---------------------------------------------------------------------------
__device__ __forceinline__ float f2tf(float x) {
    uint32_t u;
    asm("cvt.rna.tf32.f32 %0, %1;" : "=r"(u) : "f"(x));
    return __uint_as_float(u);
}
__device__ __forceinline__ float4 tf4(float4 v) {
    return make_float4(f2tf(v.x), f2tf(v.y), f2tf(v.z), f2tf(v.w));
}
__device__ __forceinline__ float4 tf4lo(float4 v, float4 h) {
    return make_float4(f2tf(v.x - h.x), f2tf(v.y - h.y),
                       f2tf(v.z - h.z), f2tf(v.w - h.w));
}
__device__ __forceinline__ uint32_t smem_u32(const void* p) {
    uint32_t a;
    asm("{ .reg .u64 t; cvta.to.shared.u64 t, %1; cvt.u32.u64 %0, t; }" : "=r"(a) : "l"(p));
    return a;
}
__device__ __forceinline__ float4 lds128(uint32_t a) {
    float4 v;
    asm volatile("ld.shared.v4.f32 {%0,%1,%2,%3}, [%4];"
                 : "=f"(v.x), "=f"(v.y), "=f"(v.z), "=f"(v.w) : "r"(a));
    return v;
}
// exp(x) for x <= 0, FMA-pipe only: 2^(x*log2e), deg-6 poly
__device__ __forceinline__ float fast_exp(float x) {
    float t = fmaxf(x * 1.4426950408889634f, -126.0f);
    float n = rintf(t);
    float f = t - n;
    float p = fmaf(f, 0.00015403530393381609f, 0.0013333558146428443f);
    p = fmaf(f, p, 0.009618129107628477f);
    p = fmaf(f, p, 0.0555041086648216f);
    p = fmaf(f, p, 0.2402265069591007f);
    p = fmaf(f, p, 0.6931471805599453f);
    p = fmaf(f, p, 1.0f);
    return __int_as_float(__float_as_int(p) + (((int)n) << 23));
}
#define CP16(sa, ga) asm volatile("cp.async.cg.shared.global [%0], [%1], 16;" :: "r"(sa), "l"(ga))
#define CP_COMMIT()  asm volatile("cp.async.commit_group;")
#define CP_WAIT1()   asm volatile("cp.async.wait_group 1;")
#define MMA_TF32(d, a0, a1, a2, a3, b0, b1)                                       \
    asm volatile("mma.sync.aligned.m16n8k8.row.col.f32.tf32.tf32.f32 "            \
                 "{%0,%1,%2,%3},{%4,%5,%6,%7},{%8,%9},{%0,%1,%2,%3};"             \
                 : "+f"(d[0]), "+f"(d[1]), "+f"(d[2]), "+f"(d[3])                  \
                 : "r"(a0), "r"(a1), "r"(a2), "r"(a3), "r"(b0), "r"(b1))
#define U(f) __float_as_uint(f)

// ---------------------------------------------------------------------------
// Kernel A: fused projections (validated R6). q,k fp32 w-permuted;
// v = w3@x + b3 transposed [b][c][w][j], tf32, j-permuted.
// ---------------------------------------------------------------------------
__global__ __launch_bounds__(256)
void proj_kernel(const float* __restrict__ x,
                 const float* __restrict__ w1, const float* __restrict__ b1,
                 const float* __restrict__ w2, const float* __restrict__ b2,
                 const float* __restrict__ w3, const float* __restrict__ b3) {
    __shared__ float xt_s[8][32][33];
    __shared__ float w1s[8], w2s[8], w3s[64], b3s[8], bqk[2];
    const int tid = threadIdx.x;
    if (tid < 8)  { w1s[tid] = w1[tid]; w2s[tid] = w2[tid]; b3s[tid] = b3[tid]; }
    if (tid < 64) w3s[tid] = w3[tid];
    if (tid == 0) { bqk[0] = b1[0]; bqk[1] = b2[0]; }
    __syncthreads();
    const int b = blockIdx.z, j0 = blockIdx.y * 32, w0 = blockIdx.x * 32;
    const int jl = tid >> 3, wq = (tid & 7) << 2;
    const float* xb = x + (size_t)b * NC * HW + (size_t)(j0 + jl) * NW + w0 + wq;

    float4 xv[8];
#pragma unroll
    for (int c = 0; c < 8; c++) xv[c] = *(const float4*)(xb + (size_t)c * HW);

    float4 q = make_float4(bqk[0], bqk[0], bqk[0], bqk[0]);
    float4 k = make_float4(bqk[1], bqk[1], bqk[1], bqk[1]);
#pragma unroll
    for (int c = 0; c < 8; c++) {
        q.x = fmaf(w1s[c], xv[c].x, q.x); q.y = fmaf(w1s[c], xv[c].y, q.y);
        q.z = fmaf(w1s[c], xv[c].z, q.z); q.w = fmaf(w1s[c], xv[c].w, q.w);
        k.x = fmaf(w2s[c], xv[c].x, k.x); k.y = fmaf(w2s[c], xv[c].y, k.y);
        k.z = fmaf(w2s[c], xv[c].z, k.z); k.w = fmaf(w2s[c], xv[c].w, k.w);
    }
    {
        const int b16 = (w0 + wq) & ~15, r4 = (wq & 15) >> 2;
        float* qp = g_q + (size_t)b * HW + (size_t)(j0 + jl) * NW + b16 + r4;
        float* kp = g_k + (size_t)b * HW + (size_t)(j0 + jl) * NW + b16 + r4;
        qp[0] = q.x; qp[4] = q.y; qp[8] = q.z; qp[12] = q.w;
        kp[0] = k.x; kp[4] = k.y; kp[8] = k.z; kp[12] = k.w;
    }

#pragma unroll
    for (int c = 0; c < 8; c++) {
        float4 v = make_float4(b3s[c], b3s[c], b3s[c], b3s[c]);
#pragma unroll
        for (int cp = 0; cp < 8; cp++) {
            float w = w3s[c * 8 + cp];
            v.x = fmaf(w, xv[cp].x, v.x); v.y = fmaf(w, xv[cp].y, v.y);
            v.z = fmaf(w, xv[cp].z, v.z); v.w = fmaf(w, xv[cp].w, v.w);
        }
        xt_s[c][jl][wq + 0] = v.x; xt_s[c][jl][wq + 1] = v.y;
        xt_s[c][jl][wq + 2] = v.z; xt_s[c][jl][wq + 3] = v.w;
    }
    __syncthreads();
    const int jj = tid & 31, wl = tid >> 5;
    const int jp = (jj & 16) | (((jj & 3) << 2) | ((jj & 15) >> 2));
#pragma unroll
    for (int c = 0; c < 8; c++)
#pragma unroll
        for (int ws = 0; ws < 32; ws += 8) {
            int wg = ws + wl;
            g_vt[(((size_t)(b * 8 + c)) * NW + w0 + wg) * NH + j0 + jp] =
                f2tf(xt_s[c][jj][wg]);
        }
}

// ---------------------------------------------------------------------------
// Kernel B: FUSED scores+softmax. CTA: M=64 x N=256, K=256. 256 thr = 8 warps
// (2m x 4n), warp tile 32x64. 3-term tf32 split; softmax in regs.
// grid (4 m-tiles, 64 b) = 256 CTAs -> 2 CTAs/SM, single wave.
// ---------------------------------------------------------------------------
#define KC 16
#define NSTG 3
// fused kernel stage: A 64x16 = 4KB, B 256x16 = 16KB
#define F_A_ST 4096
#define F_B_ST 16384
#define F_STG (F_A_ST + F_B_ST)            // 20480
#define SMEM_FUSED (NSTG * F_STG + 4 * 64 * 4)

__global__ __launch_bounds__(256, 2)
void scores_softmax_kernel() {
    extern __shared__ char smem[];
    const uint32_t sb = smem_u32(smem);
    float* red = (float*)(smem + NSTG * F_STG);    // [4][64]
    const int tid = threadIdx.x;
    const int lane = tid & 31, warp = tid >> 5;
    const int warpM = warp & 1, warpN = warp >> 1;
    const int g = lane >> 2, t4 = lane & 3;

    const int i0 = blockIdx.x * 64;
    const int b  = blockIdx.y;
    const float* Ab = g_q + (size_t)b * HW + (size_t)i0 * NW;
    const float* Bb = g_k + (size_t)b * HW;

    const int ar = tid >> 2, aq = tid & 3;       // ar 0..63
    const uint32_t a_soff = (uint32_t)(ar * 64 + ((aq ^ (ar & 3)) << 4));
    const size_t   a_goff = (size_t)ar * NW + aq * 4;

    float acc[2][8][4];
#pragma unroll
    for (int mi = 0; mi < 2; mi++)
#pragma unroll
        for (int ni = 0; ni < 8; ni++)
#pragma unroll
            for (int r = 0; r < 4; r++) acc[mi][ni][r] = 0.f;

#pragma unroll
    for (int s = 0; s < NSTG - 1; s++) {
        uint32_t as = sb + s * F_STG, bs = as + F_A_ST;
        CP16(as + a_soff, Ab + s * KC + a_goff);
#pragma unroll
        for (int u = 0; u < 4; u++) {
            int n = ar + 64 * u;
            CP16(bs + n * 64 + ((aq ^ (n & 3)) << 4), Bb + s * KC + (size_t)n * NW + aq * 4);
        }
        CP_COMMIT();
    }

    for (int kc = 0; kc < 16; kc++) {
        CP_WAIT1();
        __syncthreads();

        const int pf = kc + NSTG - 1;
        if (pf < 16) {
            uint32_t as = sb + (pf % NSTG) * F_STG, bs = as + F_A_ST;
            CP16(as + a_soff, Ab + pf * KC + a_goff);
#pragma unroll
            for (int u = 0; u < 4; u++) {
                int n = ar + 64 * u;
                CP16(bs + n * 64 + ((aq ^ (n & 3)) << 4),
                     Bb + pf * KC + (size_t)n * NW + aq * 4);
            }
        }
        CP_COMMIT();

        const uint32_t as = sb + (kc % NSTG) * F_STG;
        const uint32_t bs = as + F_A_ST;
        const uint32_t swq = (uint32_t)(t4 ^ (g & 3)) << 4;

        float4 ahi[2][2], alo[2][2];
#pragma unroll
        for (int mi = 0; mi < 2; mi++) {
            int rb = warpM * 32 + mi * 16 + g;
            float4 r0 = lds128(as + rb * 64 + swq);
            float4 r1 = lds128(as + (rb + 8) * 64 + swq);
            ahi[mi][0] = tf4(r0); alo[mi][0] = tf4lo(r0, ahi[mi][0]);
            ahi[mi][1] = tf4(r1); alo[mi][1] = tf4lo(r1, ahi[mi][1]);
        }
#pragma unroll
        for (int ni = 0; ni < 8; ni++) {
            int n = warpN * 64 + ni * 8 + g;
            float4 bf = lds128(bs + n * 64 + swq);
            float4 bh = tf4(bf), bl = tf4lo(bf, bh);
#pragma unroll
            for (int mi = 0; mi < 2; mi++) {
                MMA_TF32(acc[mi][ni],
                         U(ahi[mi][0].x), U(ahi[mi][1].x),
                         U(ahi[mi][0].y), U(ahi[mi][1].y), U(bh.x), U(bh.y));
                MMA_TF32(acc[mi][ni],
                         U(ahi[mi][0].x), U(ahi[mi][1].x),
                         U(ahi[mi][0].y), U(ahi[mi][1].y), U(bl.x), U(bl.y));
                MMA_TF32(acc[mi][ni],
                         U(alo[mi][0].x), U(alo[mi][1].x),
                         U(alo[mi][0].y), U(alo[mi][1].y), U(bh.x), U(bh.y));
                MMA_TF32(acc[mi][ni],
                         U(ahi[mi][0].z), U(ahi[mi][1].z),
                         U(ahi[mi][0].w), U(ahi[mi][1].w), U(bh.z), U(bh.w));
                MMA_TF32(acc[mi][ni],
                         U(ahi[mi][0].z), U(ahi[mi][1].z),
                         U(ahi[mi][0].w), U(ahi[mi][1].w), U(bl.z), U(bl.w));
                MMA_TF32(acc[mi][ni],
                         U(alo[mi][0].z), U(alo[mi][1].z),
                         U(alo[mi][0].w), U(alo[mi][1].w), U(bh.z), U(bh.w));
            }
        }
    }

    // ---- fused softmax (lane owns 4 rows x 16 cols; 4 n-warps reduce in smem)
    float rowv[4];
#pragma unroll
    for (int mi = 0; mi < 2; mi++)
#pragma unroll
        for (int h = 0; h < 2; h++) {
            float m = -FLT_MAX;
#pragma unroll
            for (int ni = 0; ni < 8; ni++)
                m = fmaxf(m, fmaxf(acc[mi][ni][h * 2], acc[mi][ni][h * 2 + 1]));
            m = fmaxf(m, __shfl_xor_sync(0xffffffffu, m, 1));
            m = fmaxf(m, __shfl_xor_sync(0xffffffffu, m, 2));
            rowv[mi * 2 + h] = m;
        }
    if (t4 == 0) {
#pragma unroll
        for (int mi = 0; mi < 2; mi++)
#pragma unroll
            for (int h = 0; h < 2; h++)
                red[warpN * 64 + warpM * 32 + mi * 16 + h * 8 + g] = rowv[mi * 2 + h];
    }
    __syncthreads();
    float rowmax[4];
#pragma unroll
    for (int mi = 0; mi < 2; mi++)
#pragma unroll
        for (int h = 0; h < 2; h++) {
            int rl = warpM * 32 + mi * 16 + h * 8 + g;
            rowmax[mi * 2 + h] = fmaxf(fmaxf(red[rl], red[64 + rl]),
                                       fmaxf(red[128 + rl], red[192 + rl]));
        }
    __syncthreads();
#pragma unroll
    for (int mi = 0; mi < 2; mi++)
#pragma unroll
        for (int h = 0; h < 2; h++) {
            float m = rowmax[mi * 2 + h], s = 0.f;
#pragma unroll
            for (int ni = 0; ni < 8; ni++) {
                float e0 = fast_exp(acc[mi][ni][h * 2] - m);
                float e1 = fast_exp(acc[mi][ni][h * 2 + 1] - m);
                acc[mi][ni][h * 2] = e0; acc[mi][ni][h * 2 + 1] = e1;
                s += e0 + e1;
            }
            s += __shfl_xor_sync(0xffffffffu, s, 1);
            s += __shfl_xor_sync(0xffffffffu, s, 2);
            rowv[mi * 2 + h] = s;
        }
    if (t4 == 0) {
#pragma unroll
        for (int mi = 0; mi < 2; mi++)
#pragma unroll
            for (int h = 0; h < 2; h++)
                red[warpN * 64 + warpM * 32 + mi * 16 + h * 8 + g] = rowv[mi * 2 + h];
    }
    __syncthreads();
    float* attn = g_attn + (size_t)b * NH * NH;
#pragma unroll
    for (int mi = 0; mi < 2; mi++)
#pragma unroll
        for (int h = 0; h < 2; h++) {
            int rl = warpM * 32 + mi * 16 + h * 8 + g;
            float inv = 1.0f / (red[rl] + red[64 + rl] + red[128 + rl] + red[192 + rl]);
            size_t rb = (size_t)(i0 + rl) * NH;
#pragma unroll
            for (int ni = 0; ni < 8; ni++) {
                int j = warpN * 64 + ni * 8 + t4 * 2;
                int p = (j & ~15) + ((j & 3) << 2) + ((j & 15) >> 2);
                attn[rb + p]     = f2tf(acc[mi][ni][h * 2] * inv);
                attn[rb + p + 4] = f2tf(acc[mi][ni][h * 2 + 1] * inv);
            }
        }
}

// ---------------------------------------------------------------------------
// Kernel D: out[b,c] = attn_b @ v[b,c]. CTA: 128(M) x 128(N), 256 thr = 8
// warps (4m x 2n), warp tile 32x64. 3-stage cp.async, 2 CTAs/SM.
// grid (4 = mt*nt, 8 c, 64 b)
// ---------------------------------------------------------------------------
#define D_A_ST 8192
#define D_B_ST 8192
#define D_STG (D_A_ST + D_B_ST)            // 16384
#define SMEM_MMA (NSTG * D_STG)            // 49152

__global__ __launch_bounds__(256, 2)
void mma_out_kernel(float* __restrict__ out) {
    extern __shared__ char smem[];
    const uint32_t sb = smem_u32(smem);
    const int tid = threadIdx.x;
    const int lane = tid & 31, warp = tid >> 5;
    const int warpM = warp & 3, warpN = warp >> 2;
    const int g = lane >> 2, t4 = lane & 3;

    const int mt = blockIdx.x & 1, nt = blockIdx.x >> 1;
    const int i0 = mt * 128, n0 = nt * 128;
    const int c  = blockIdx.y;
    const int b  = blockIdx.z;
    const float* Ab = g_attn + (size_t)b * NH * NH + (size_t)i0 * NH;
    const float* Bb = g_vt + ((size_t)(b * 8 + c)) * HW + (size_t)n0 * NH;

    const int ar = tid >> 2, aq = tid & 3;       // ar 0..63

    float acc[2][8][4];
#pragma unroll
    for (int mi = 0; mi < 2; mi++)
#pragma unroll
        for (int ni = 0; ni < 8; ni++)
#pragma unroll
            for (int r = 0; r < 4; r++) acc[mi][ni][r] = 0.f;

#pragma unroll
    for (int s = 0; s < NSTG - 1; s++) {
        uint32_t as = sb + s * D_STG, bs = as + D_A_ST;
#pragma unroll
        for (int u = 0; u < 2; u++) {
            int row = ar + 64 * u;
            uint32_t so = (uint32_t)(row * 64 + ((aq ^ (row & 3)) << 4));
            CP16(as + so, Ab + s * KC + (size_t)row * NH + aq * 4);
            CP16(bs + so, Bb + s * KC + (size_t)row * NH + aq * 4);
        }
        CP_COMMIT();
    }

    for (int kc = 0; kc < 16; kc++) {
        CP_WAIT1();
        __syncthreads();

        const int pf = kc + NSTG - 1;
        if (pf < 16) {
            uint32_t as = sb + (pf % NSTG) * D_STG, bs = as + D_A_ST;
#pragma unroll
            for (int u = 0; u < 2; u++) {
                int row = ar + 64 * u;
                uint32_t so = (uint32_t)(row * 64 + ((aq ^ (row & 3)) << 4));
                CP16(as + so, Ab + pf * KC + (size_t)row * NH + aq * 4);
                CP16(bs + so, Bb + pf * KC + (size_t)row * NH + aq * 4);
            }
        }
        CP_COMMIT();

        const uint32_t as = sb + (kc % NSTG) * D_STG;
        const uint32_t bs = as + D_A_ST;
        const uint32_t swq = (uint32_t)(t4 ^ (g & 3)) << 4;

        float4 afr[2][2];
#pragma unroll
        for (int mi = 0; mi < 2; mi++) {
            int rb = warpM * 32 + mi * 16 + g;
            afr[mi][0] = lds128(as + rb * 64 + swq);
            afr[mi][1] = lds128(as + (rb + 8) * 64 + swq);
        }
        float4 bf = lds128(bs + (warpN * 64 + g) * 64 + swq);
#pragma unroll
        for (int ni = 0; ni < 8; ni++) {
            float4 bfn;
            if (ni < 7)
                bfn = lds128(bs + (warpN * 64 + (ni + 1) * 8 + g) * 64 + swq);
#pragma unroll
            for (int mi = 0; mi < 2; mi++) {
                MMA_TF32(acc[mi][ni],
                         U(afr[mi][0].x), U(afr[mi][1].x),
                         U(afr[mi][0].y), U(afr[mi][1].y),
                         U(bf.x), U(bf.y));
                MMA_TF32(acc[mi][ni],
                         U(afr[mi][0].z), U(afr[mi][1].z),
                         U(afr[mi][0].w), U(afr[mi][1].w),
                         U(bf.z), U(bf.w));
            }
            bf = bfn;
        }
    }

    float* ob = out + ((size_t)(b * 8 + c)) * HW;
#pragma unroll
    for (int mi = 0; mi < 2; mi++) {
        int row = i0 + warpM * 32 + mi * 16 + g;
#pragma unroll
        for (int ni = 0; ni < 8; ni++) {
            int col = n0 + warpN * 64 + ni * 8 + t4 * 2;
            *(float2*)(ob + (size_t)row * NW + col) =
                make_float2(acc[mi][ni][0], acc[mi][ni][1]);
            *(float2*)(ob + (size_t)(row + 8) * NW + col) =
                make_float2(acc[mi][ni][2], acc[mi][ni][3]);
        }
    }
}

// ---------------------------------------------------------------------------
extern "C" void kernel_launch(void* const* d_in, const int* in_sizes, int n_in,
                              void* d_out, int out_size) {
    const float* x  = (const float*)d_in[0];
    const float* w1 = (const float*)d_in[1];
    const float* b1 = (const float*)d_in[2];
    const float* w2 = (const float*)d_in[3];
    const float* b2 = (const float*)d_in[4];
    const float* w3 = (const float*)d_in[5];
    const float* b3 = (const float*)d_in[6];
    float* out = (float*)d_out;

    static bool configured = false;
    if (!configured) {
        cudaFuncSetAttribute(scores_softmax_kernel,
                             cudaFuncAttributeMaxDynamicSharedMemorySize, SMEM_FUSED);
        cudaFuncSetAttribute(mma_out_kernel,
                             cudaFuncAttributeMaxDynamicSharedMemorySize, SMEM_MMA);
        configured = true;
    }

    dim3 ga(8, 8, NB);
    proj_kernel<<<ga, 256>>>(x, w1, b1, w2, b2, w3, b3);
    dim3 gs(4, NB);
    scores_softmax_kernel<<<gs, 256, SMEM_FUSED>>>();
    dim3 gd(4, 8, NB);
    mma_out_kernel<<<gd, 256, SMEM_MMA>>>(out);
}

// round 8
// speedup vs baseline: 3.5314x; 1.3222x over previous
#include <cuda_runtime.h>
#include <cuda_fp16.h>
#include <cstdint>
#include <cfloat>

#define NB 64
#define NC 8
#define NH 256
#define NW 256
#define HW (NH*NW)

// Scratch (__device__ globals per allocation-free rule)
__device__ float  g_q[NB*HW];                  // fp32, w-permuted within 16-blocks
__device__ float  g_k[NB*HW];                  // fp32, w-permuted within 16-blocks
__device__ __half g_attnh[(size_t)NB*NH*NH];   // fp16 attn, j pair-permuted (8.4 MB)
__device__ __half g_vth[(size_t)NB*NC*HW];     // fp16 v^T [b][c][w][j], j pair-perm (67 MB)

// ---------------------------------------------------------------------------
// helpers
// ---------------------------------------------------------------------------
__device__ __forceinline__ float f2tf(float x) {
    uint32_t u;
    asm("cvt.rna.tf32.f32 %0, %1;" : "=r"(u) : "f"(x));
    return __uint_as_float(u);
}
__device__ __forceinline__ float4 tf4(float4 v) {
    return make_float4(f2tf(v.x), f2tf(v.y), f2tf(v.z), f2tf(v.w));
}
__device__ __forceinline__ float4 tf4lo(float4 v, float4 h) {
    return make_float4(f2tf(v.x - h.x), f2tf(v.y - h.y),
                       f2tf(v.z - h.z), f2tf(v.w - h.w));
}
__device__ __forceinline__ uint32_t smem_u32(const void* p) {
    uint32_t a;
    asm("{ .reg .u64 t; cvta.to.shared.u64 t, %1; cvt.u32.u64 %0, t; }" : "=r"(a) : "l"(p));
    return a;
}
__device__ __forceinline__ float4 lds128(uint32_t a) {
    float4 v;
    asm volatile("ld.shared.v4.f32 {%0,%1,%2,%3}, [%4];"
                 : "=f"(v.x), "=f"(v.y), "=f"(v.z), "=f"(v.w) : "r"(a));
    return v;
}
__device__ __forceinline__ uint2 lds64(uint32_t a) {
    uint2 v;
    asm volatile("ld.shared.v2.u32 {%0,%1}, [%2];" : "=r"(v.x), "=r"(v.y) : "r"(a));
    return v;
}
// exp(x) for x <= 0, FMA-pipe only: 2^(x*log2e), deg-6 poly
__device__ __forceinline__ float fast_exp(float x) {
    float t = fmaxf(x * 1.4426950408889634f, -126.0f);
    float n = rintf(t);
    float f = t - n;
    float p = fmaf(f, 0.00015403530393381609f, 0.0013333558146428443f);
    p = fmaf(f, p, 0.009618129107628477f);
    p = fmaf(f, p, 0.0555041086648216f);
    p = fmaf(f, p, 0.2402265069591007f);
    p = fmaf(f, p, 0.6931471805599453f);
    p = fmaf(f, p, 1.0f);
    return __int_as_float(__float_as_int(p) + (((int)n) << 23));
}
#define CP16(sa, ga) asm volatile("cp.async.cg.shared.global [%0], [%1], 16;" :: "r"(sa), "l"(ga))
#define CP_COMMIT()  asm volatile("cp.async.commit_group;")
#define CP_WAIT1()   asm volatile("cp.async.wait_group 1;")
#define MMA_TF32(d, a0, a1, a2, a3, b0, b1)                                       \
    asm volatile("mma.sync.aligned.m16n8k8.row.col.f32.tf32.tf32.f32 "            \
                 "{%0,%1,%2,%3},{%4,%5,%6,%7},{%8,%9},{%0,%1,%2,%3};"             \
                 : "+f"(d[0]), "+f"(d[1]), "+f"(d[2]), "+f"(d[3])                  \
                 : "r"(a0), "r"(a1), "r"(a2), "r"(a3), "r"(b0), "r"(b1))
#define MMA_F16(d, a0, a1, a2, a3, b0, b1)                                        \
    asm volatile("mma.sync.aligned.m16n8k16.row.col.f32.f16.f16.f32 "             \
                 "{%0,%1,%2,%3},{%4,%5,%6,%7},{%8,%9},{%0,%1,%2,%3};"             \
                 : "+f"(d[0]), "+f"(d[1]), "+f"(d[2]), "+f"(d[3])                  \
                 : "r"(a0), "r"(a1), "r"(a2), "r"(a3), "r"(b0), "r"(b1))
#define U(f) __float_as_uint(f)

// fp16 k-pair permutation within a 16-element block:
// pair pk (0..7) -> position (pk&3)*2 + (pk>>2); halfidx = pos*2 + (k&1).
// Gives each mma thread its (t4, t4+4) pairs as one contiguous 8B LDS.64.
__device__ __forceinline__ int kperm16(int kb) {   // kb = k & 15
    int pk = kb >> 1;
    return ((((pk & 3) << 1) | (pk >> 2)) << 1) | (kb & 1);
}

// ---------------------------------------------------------------------------
// Kernel A: fused projections. q,k fp32 w-permuted (for tf32 GEMM);
// v = w3@x + b3 (b3 folded; softmax rows sum to 1), transposed [b][c][w][j],
// fp16 with j pair-permutation.
// ---------------------------------------------------------------------------
__global__ __launch_bounds__(256)
void proj_kernel(const float* __restrict__ x,
                 const float* __restrict__ w1, const float* __restrict__ b1,
                 const float* __restrict__ w2, const float* __restrict__ b2,
                 const float* __restrict__ w3, const float* __restrict__ b3) {
    __shared__ float xt_s[8][32][33];
    __shared__ float w1s[8], w2s[8], w3s[64], b3s[8], bqk[2];
    const int tid = threadIdx.x;
    if (tid < 8)  { w1s[tid] = w1[tid]; w2s[tid] = w2[tid]; b3s[tid] = b3[tid]; }
    if (tid < 64) w3s[tid] = w3[tid];
    if (tid == 0) { bqk[0] = b1[0]; bqk[1] = b2[0]; }
    __syncthreads();
    const int b = blockIdx.z, j0 = blockIdx.y * 32, w0 = blockIdx.x * 32;
    const int jl = tid >> 3, wq = (tid & 7) << 2;
    const float* xb = x + (size_t)b * NC * HW + (size_t)(j0 + jl) * NW + w0 + wq;

    float4 xv[8];
#pragma unroll
    for (int c = 0; c < 8; c++) xv[c] = *(const float4*)(xb + (size_t)c * HW);

    float4 q = make_float4(bqk[0], bqk[0], bqk[0], bqk[0]);
    float4 k = make_float4(bqk[1], bqk[1], bqk[1], bqk[1]);
#pragma unroll
    for (int c = 0; c < 8; c++) {
        q.x = fmaf(w1s[c], xv[c].x, q.x); q.y = fmaf(w1s[c], xv[c].y, q.y);
        q.z = fmaf(w1s[c], xv[c].z, q.z); q.w = fmaf(w1s[c], xv[c].w, q.w);
        k.x = fmaf(w2s[c], xv[c].x, k.x); k.y = fmaf(w2s[c], xv[c].y, k.y);
        k.z = fmaf(w2s[c], xv[c].z, k.z); k.w = fmaf(w2s[c], xv[c].w, k.w);
    }
    {
        const int b16 = (w0 + wq) & ~15, r4 = (wq & 15) >> 2;
        float* qp = g_q + (size_t)b * HW + (size_t)(j0 + jl) * NW + b16 + r4;
        float* kp = g_k + (size_t)b * HW + (size_t)(j0 + jl) * NW + b16 + r4;
        qp[0] = q.x; qp[4] = q.y; qp[8] = q.z; qp[12] = q.w;
        kp[0] = k.x; kp[4] = k.y; kp[8] = k.z; kp[12] = k.w;
    }

#pragma unroll
    for (int c = 0; c < 8; c++) {
        float4 v = make_float4(b3s[c], b3s[c], b3s[c], b3s[c]);
#pragma unroll
        for (int cp = 0; cp < 8; cp++) {
            float w = w3s[c * 8 + cp];
            v.x = fmaf(w, xv[cp].x, v.x); v.y = fmaf(w, xv[cp].y, v.y);
            v.z = fmaf(w, xv[cp].z, v.z); v.w = fmaf(w, xv[cp].w, v.w);
        }
        xt_s[c][jl][wq + 0] = v.x; xt_s[c][jl][wq + 1] = v.y;
        xt_s[c][jl][wq + 2] = v.z; xt_s[c][jl][wq + 3] = v.w;
    }
    __syncthreads();
    // transposed + pair-permuted fp16 write (coalesced within 64B per (c,w))
    const int jj = tid & 31, wl = tid >> 5;
    const int hoff = (jj & 16) + kperm16(jj & 15);
#pragma unroll
    for (int c = 0; c < 8; c++)
#pragma unroll
        for (int ws = 0; ws < 32; ws += 8) {
            int wg = ws + wl;
            g_vth[(((size_t)(b * 8 + c)) * NW + w0 + wg) * NH + j0 + hoff] =
                __float2half_rn(xt_s[c][jj][wg]);
        }
}

// ---------------------------------------------------------------------------
// Kernel B: FUSED scores+softmax. CTA: M=64 x N=256, K=256. 256 thr = 8 warps
// (2m x 4n). 3-term tf32 split; softmax in regs; stores fp16 attn pair-perm.
// ---------------------------------------------------------------------------
#define KC 16
#define NSTG 3
#define F_A_ST 4096
#define F_B_ST 16384
#define F_STG (F_A_ST + F_B_ST)
#define SMEM_FUSED (NSTG * F_STG + 4 * 64 * 4)

__global__ __launch_bounds__(256, 2)
void scores_softmax_kernel() {
    extern __shared__ char smem[];
    const uint32_t sb = smem_u32(smem);
    float* red = (float*)(smem + NSTG * F_STG);    // [4][64]
    const int tid = threadIdx.x;
    const int lane = tid & 31, warp = tid >> 5;
    const int warpM = warp & 1, warpN = warp >> 1;
    const int g = lane >> 2, t4 = lane & 3;

    const int i0 = blockIdx.x * 64;
    const int b  = blockIdx.y;
    const float* Ab = g_q + (size_t)b * HW + (size_t)i0 * NW;
    const float* Bb = g_k + (size_t)b * HW;

    const int ar = tid >> 2, aq = tid & 3;
    const uint32_t a_soff = (uint32_t)(ar * 64 + ((aq ^ (ar & 3)) << 4));
    const size_t   a_goff = (size_t)ar * NW + aq * 4;

    float acc[2][8][4];
#pragma unroll
    for (int mi = 0; mi < 2; mi++)
#pragma unroll
        for (int ni = 0; ni < 8; ni++)
#pragma unroll
            for (int r = 0; r < 4; r++) acc[mi][ni][r] = 0.f;

#pragma unroll
    for (int s = 0; s < NSTG - 1; s++) {
        uint32_t as = sb + s * F_STG, bs = as + F_A_ST;
        CP16(as + a_soff, Ab + s * KC + a_goff);
#pragma unroll
        for (int u = 0; u < 4; u++) {
            int n = ar + 64 * u;
            CP16(bs + n * 64 + ((aq ^ (n & 3)) << 4), Bb + s * KC + (size_t)n * NW + aq * 4);
        }
        CP_COMMIT();
    }

    for (int kc = 0; kc < 16; kc++) {
        CP_WAIT1();
        __syncthreads();

        const int pf = kc + NSTG - 1;
        if (pf < 16) {
            uint32_t as = sb + (pf % NSTG) * F_STG, bs = as + F_A_ST;
            CP16(as + a_soff, Ab + pf * KC + a_goff);
#pragma unroll
            for (int u = 0; u < 4; u++) {
                int n = ar + 64 * u;
                CP16(bs + n * 64 + ((aq ^ (n & 3)) << 4),
                     Bb + pf * KC + (size_t)n * NW + aq * 4);
            }
        }
        CP_COMMIT();

        const uint32_t as = sb + (kc % NSTG) * F_STG;
        const uint32_t bs = as + F_A_ST;
        const uint32_t swq = (uint32_t)(t4 ^ (g & 3)) << 4;

        float4 ahi[2][2], alo[2][2];
#pragma unroll
        for (int mi = 0; mi < 2; mi++) {
            int rb = warpM * 32 + mi * 16 + g;
            float4 r0 = lds128(as + rb * 64 + swq);
            float4 r1 = lds128(as + (rb + 8) * 64 + swq);
            ahi[mi][0] = tf4(r0); alo[mi][0] = tf4lo(r0, ahi[mi][0]);
            ahi[mi][1] = tf4(r1); alo[mi][1] = tf4lo(r1, ahi[mi][1]);
        }
#pragma unroll
        for (int ni = 0; ni < 8; ni++) {
            int n = warpN * 64 + ni * 8 + g;
            float4 bf = lds128(bs + n * 64 + swq);
            float4 bh = tf4(bf), bl = tf4lo(bf, bh);
#pragma unroll
            for (int mi = 0; mi < 2; mi++) {
                MMA_TF32(acc[mi][ni],
                         U(ahi[mi][0].x), U(ahi[mi][1].x),
                         U(ahi[mi][0].y), U(ahi[mi][1].y), U(bh.x), U(bh.y));
                MMA_TF32(acc[mi][ni],
                         U(ahi[mi][0].x), U(ahi[mi][1].x),
                         U(ahi[mi][0].y), U(ahi[mi][1].y), U(bl.x), U(bl.y));
                MMA_TF32(acc[mi][ni],
                         U(alo[mi][0].x), U(alo[mi][1].x),
                         U(alo[mi][0].y), U(alo[mi][1].y), U(bh.x), U(bh.y));
                MMA_TF32(acc[mi][ni],
                         U(ahi[mi][0].z), U(ahi[mi][1].z),
                         U(ahi[mi][0].w), U(ahi[mi][1].w), U(bh.z), U(bh.w));
                MMA_TF32(acc[mi][ni],
                         U(ahi[mi][0].z), U(ahi[mi][1].z),
                         U(ahi[mi][0].w), U(ahi[mi][1].w), U(bl.z), U(bl.w));
                MMA_TF32(acc[mi][ni],
                         U(alo[mi][0].z), U(alo[mi][1].z),
                         U(alo[mi][0].w), U(alo[mi][1].w), U(bh.z), U(bh.w));
            }
        }
    }

    // ---- fused softmax ----
    float rowv[4];
#pragma unroll
    for (int mi = 0; mi < 2; mi++)
#pragma unroll
        for (int h = 0; h < 2; h++) {
            float m = -FLT_MAX;
#pragma unroll
            for (int ni = 0; ni < 8; ni++)
                m = fmaxf(m, fmaxf(acc[mi][ni][h * 2], acc[mi][ni][h * 2 + 1]));
            m = fmaxf(m, __shfl_xor_sync(0xffffffffu, m, 1));
            m = fmaxf(m, __shfl_xor_sync(0xffffffffu, m, 2));
            rowv[mi * 2 + h] = m;
        }
    if (t4 == 0) {
#pragma unroll
        for (int mi = 0; mi < 2; mi++)
#pragma unroll
            for (int h = 0; h < 2; h++)
                red[warpN * 64 + warpM * 32 + mi * 16 + h * 8 + g] = rowv[mi * 2 + h];
    }
    __syncthreads();
    float rowmax[4];
#pragma unroll
    for (int mi = 0; mi < 2; mi++)
#pragma unroll
        for (int h = 0; h < 2; h++) {
            int rl = warpM * 32 + mi * 16 + h * 8 + g;
            rowmax[mi * 2 + h] = fmaxf(fmaxf(red[rl], red[64 + rl]),
                                       fmaxf(red[128 + rl], red[192 + rl]));
        }
    __syncthreads();
#pragma unroll
    for (int mi = 0; mi < 2; mi++)
#pragma unroll
        for (int h = 0; h < 2; h++) {
            float m = rowmax[mi * 2 + h], s = 0.f;
#pragma unroll
            for (int ni = 0; ni < 8; ni++) {
                float e0 = fast_exp(acc[mi][ni][h * 2] - m);
                float e1 = fast_exp(acc[mi][ni][h * 2 + 1] - m);
                acc[mi][ni][h * 2] = e0; acc[mi][ni][h * 2 + 1] = e1;
                s += e0 + e1;
            }
            s += __shfl_xor_sync(0xffffffffu, s, 1);
            s += __shfl_xor_sync(0xffffffffu, s, 2);
            rowv[mi * 2 + h] = s;
        }
    if (t4 == 0) {
#pragma unroll
        for (int mi = 0; mi < 2; mi++)
#pragma unroll
            for (int h = 0; h < 2; h++)
                red[warpN * 64 + warpM * 32 + mi * 16 + h * 8 + g] = rowv[mi * 2 + h];
    }
    __syncthreads();
    // scale + fp16 pair-permuted store
    __half* attn = g_attnh + (size_t)b * NH * NH;
#pragma unroll
    for (int mi = 0; mi < 2; mi++)
#pragma unroll
        for (int h = 0; h < 2; h++) {
            int rl = warpM * 32 + mi * 16 + h * 8 + g;
            float inv = 1.0f / (red[rl] + red[64 + rl] + red[128 + rl] + red[192 + rl]);
            size_t rb = (size_t)(i0 + rl) * NH;
#pragma unroll
            for (int ni = 0; ni < 8; ni++) {
                int j = warpN * 64 + ni * 8 + t4 * 2;
                int idx = (j & ~15) + kperm16(j & 15);   // j even -> pair start
                *(__half2*)(attn + rb + idx) =
                    __floats2half2_rn(acc[mi][ni][h * 2] * inv,
                                      acc[mi][ni][h * 2 + 1] * inv);
            }
        }
}

// ---------------------------------------------------------------------------
// Kernel D: out[b,c] = attn_b @ v[b,c], FP16 HMMA m16n8k16, fp32 accum.
// CTA 128(M) x 128(N), K=256 in 8 chunks of 32 halfs. 256 thr = 8 warps
// (4m x 2n), warp tile 32x64. Smem row = 64B (32 halfs), 8B-slot XOR swizzle.
// ---------------------------------------------------------------------------
#define H_A_ST 8192
#define H_B_ST 8192
#define H_STG (H_A_ST + H_B_ST)            // 16384
#define SMEM_MMA (NSTG * H_STG)            // 49152

__global__ __launch_bounds__(256, 2)
void mma_out_kernel(float* __restrict__ out) {
    extern __shared__ char smem[];
    const uint32_t sb = smem_u32(smem);
    const int tid = threadIdx.x;
    const int lane = tid & 31, warp = tid >> 5;
    const int warpM = warp & 3, warpN = warp >> 2;
    const int g = lane >> 2, t4 = lane & 3;

    const int mt = blockIdx.x & 1, nt = blockIdx.x >> 1;
    const int i0 = mt * 128, n0 = nt * 128;
    const int c  = blockIdx.y;
    const int b  = blockIdx.z;
    const __half* Ab = g_attnh + (size_t)b * NH * NH + (size_t)i0 * NH;
    const __half* Bb = g_vth + ((size_t)(b * 8 + c)) * HW + (size_t)n0 * NH;

    const int ar = tid >> 2, aq = tid & 3;       // ar 0..63, quad 0..3

    float acc[2][8][4];
#pragma unroll
    for (int mi = 0; mi < 2; mi++)
#pragma unroll
        for (int ni = 0; ni < 8; ni++)
#pragma unroll
            for (int r = 0; r < 4; r++) acc[mi][ni][r] = 0.f;

    // staging: per chunk, row needs 64B = 4 quads; rows ar, ar+64 for A and B
#pragma unroll
    for (int s = 0; s < NSTG - 1; s++) {
        uint32_t as = sb + s * H_STG, bs = as + H_A_ST;
#pragma unroll
        for (int u = 0; u < 2; u++) {
            int row = ar + 64 * u;
            uint32_t so = (uint32_t)(row * 64 + ((aq ^ (((row >> 1) & 1) << 1)) << 4));
            CP16(as + so, Ab + (size_t)row * NH + s * 32 + aq * 8);
            CP16(bs + so, Bb + (size_t)row * NH + s * 32 + aq * 8);
        }
        CP_COMMIT();
    }

    for (int kc = 0; kc < 8; kc++) {
        CP_WAIT1();
        __syncthreads();

        const int pf = kc + NSTG - 1;
        if (pf < 8) {
            uint32_t as = sb + (pf % NSTG) * H_STG, bs = as + H_A_ST;
#pragma unroll
            for (int u = 0; u < 2; u++) {
                int row = ar + 64 * u;
                uint32_t so = (uint32_t)(row * 64 + ((aq ^ (((row >> 1) & 1) << 1)) << 4));
                CP16(as + so, Ab + (size_t)row * NH + pf * 32 + aq * 8);
                CP16(bs + so, Bb + (size_t)row * NH + pf * 32 + aq * 8);
            }
        }
        CP_COMMIT();

        const uint32_t as = sb + (kc % NSTG) * H_STG;
        const uint32_t bs = as + H_A_ST;

#pragma unroll
        for (int ks = 0; ks < 2; ks++) {
            uint32_t aop[2][4];
#pragma unroll
            for (int mi = 0; mi < 2; mi++) {
                int r0 = warpM * 32 + mi * 16 + g;
                int r1 = r0 + 8;
                uint32_t s0 = (uint32_t)((ks * 4 + t4) ^ (((r0 >> 1) & 1) << 2));
                uint32_t s1 = (uint32_t)((ks * 4 + t4) ^ (((r1 >> 1) & 1) << 2));
                uint2 q0 = lds64(as + r0 * 64 + s0 * 8);
                uint2 q1 = lds64(as + r1 * 64 + s1 * 8);
                aop[mi][0] = q0.x; aop[mi][1] = q1.x;
                aop[mi][2] = q0.y; aop[mi][3] = q1.y;
            }
#pragma unroll
            for (int ni = 0; ni < 8; ni++) {
                int n = warpN * 64 + ni * 8 + g;
                uint32_t sn = (uint32_t)((ks * 4 + t4) ^ (((n >> 1) & 1) << 2));
                uint2 bq = lds64(bs + n * 64 + sn * 8);
#pragma unroll
                for (int mi = 0; mi < 2; mi++)
                    MMA_F16(acc[mi][ni], aop[mi][0], aop[mi][1],
                            aop[mi][2], aop[mi][3], bq.x, bq.y);
            }
        }
    }

    float* ob = out + ((size_t)(b * 8 + c)) * HW;
#pragma unroll
    for (int mi = 0; mi < 2; mi++) {
        int row = i0 + warpM * 32 + mi * 16 + g;
#pragma unroll
        for (int ni = 0; ni < 8; ni++) {
            int col = n0 + warpN * 64 + ni * 8 + t4 * 2;
            *(float2*)(ob + (size_t)row * NW + col) =
                make_float2(acc[mi][ni][0], acc[mi][ni][1]);
            *(float2*)(ob + (size_t)(row + 8) * NW + col) =
                make_float2(acc[mi][ni][2], acc[mi][ni][3]);
        }
    }
}

// ---------------------------------------------------------------------------
extern "C" void kernel_launch(void* const* d_in, const int* in_sizes, int n_in,
                              void* d_out, int out_size) {
    const float* x  = (const float*)d_in[0];
    const float* w1 = (const float*)d_in[1];
    const float* b1 = (const float*)d_in[2];
    const float* w2 = (const float*)d_in[3];
    const float* b2 = (const float*)d_in[4];
    const float* w3 = (const float*)d_in[5];
    const float* b3 = (const float*)d_in[6];
    float* out = (float*)d_out;

    static bool configured = false;
    if (!configured) {
        cudaFuncSetAttribute(scores_softmax_kernel,
                             cudaFuncAttributeMaxDynamicSharedMemorySize, SMEM_FUSED);
        cudaFuncSetAttribute(mma_out_kernel,
                             cudaFuncAttributeMaxDynamicSharedMemorySize, SMEM_MMA);
        configured = true;
    }

    dim3 ga(8, 8, NB);
    proj_kernel<<<ga, 256>>>(x, w1, b1, w2, b2, w3, b3);
    dim3 gs(4, NB);
    scores_softmax_kernel<<<gs, 256, SMEM_FUSED>>>();
    dim3 gd(4, 8, NB);
    mma_out_kernel<<<gd, 256, SMEM_MMA>>>(out);
}

// round 9
// speedup vs baseline: 3.6114x; 1.0227x over previous
#include <cuda_runtime.h>
#include <cuda_fp16.h>
#include <cstdint>
#include <cfloat>

#define NB 64
#define NC 8
#define NH 256
#define NW 256
#define HW (NH*NW)

// Scratch (__device__ globals per allocation-free rule)
__device__ __half g_qh[NB*HW], g_ql[NB*HW];    // q hi/lo fp16, w pair-permuted
__device__ __half g_kh[NB*HW], g_kl[NB*HW];    // k hi/lo fp16, w pair-permuted
__device__ __half g_attnh[(size_t)NB*NH*NH];   // fp16 attn, j pair-permuted
__device__ __half g_vth[(size_t)NB*NC*HW];     // fp16 v^T [b][c][w][j], j pair-perm

// ---------------------------------------------------------------------------
// helpers
// ---------------------------------------------------------------------------
__device__ __forceinline__ uint32_t smem_u32(const void* p) {
    uint32_t a;
    asm("{ .reg .u64 t; cvta.to.shared.u64 t, %1; cvt.u32.u64 %0, t; }" : "=r"(a) : "l"(p));
    return a;
}
__device__ __forceinline__ uint2 lds64(uint32_t a) {
    uint2 v;
    asm volatile("ld.shared.v2.u32 {%0,%1}, [%2];" : "=r"(v.x), "=r"(v.y) : "r"(a));
    return v;
}
// exp(x) for x <= 0, FMA-pipe only: 2^(x*log2e), deg-6 poly
__device__ __forceinline__ float fast_exp(float x) {
    float t = fmaxf(x * 1.4426950408889634f, -126.0f);
    float n = rintf(t);
    float f = t - n;
    float p = fmaf(f, 0.00015403530393381609f, 0.0013333558146428443f);
    p = fmaf(f, p, 0.009618129107628477f);
    p = fmaf(f, p, 0.0555041086648216f);
    p = fmaf(f, p, 0.2402265069591007f);
    p = fmaf(f, p, 0.6931471805599453f);
    p = fmaf(f, p, 1.0f);
    return __int_as_float(__float_as_int(p) + (((int)n) << 23));
}
#define CP16(sa, ga) asm volatile("cp.async.cg.shared.global [%0], [%1], 16;" :: "r"(sa), "l"(ga))
#define CP_COMMIT()  asm volatile("cp.async.commit_group;")
#define CP_WAIT1()   asm volatile("cp.async.wait_group 1;")
#define MMA_F16(d, a0, a1, a2, a3, b0, b1)                                        \
    asm volatile("mma.sync.aligned.m16n8k16.row.col.f32.f16.f16.f32 "             \
                 "{%0,%1,%2,%3},{%4,%5,%6,%7},{%8,%9},{%0,%1,%2,%3};"             \
                 : "+f"(d[0]), "+f"(d[1]), "+f"(d[2]), "+f"(d[3])                  \
                 : "r"(a0), "r"(a1), "r"(a2), "r"(a3), "r"(b0), "r"(b1))

// fp16 k-pair permutation within a 16-element block: pair pk -> pos so that
// each mma thread's pairs (t4, t4+4) land in one contiguous 8B LDS.64 slot.
__device__ __forceinline__ int kperm16(int kb) {   // kb = k & 15
    int pk = kb >> 1;
    return ((((pk & 3) << 1) | (pk >> 2)) << 1) | (kb & 1);
}

// ---------------------------------------------------------------------------
// Kernel A: fused projections. q,k -> fp16 hi/lo (split for 3-term fp16 MMA),
// w pair-permuted; v = w3@x + b3 (b3 folded; softmax rows sum to 1),
// transposed [b][c][w][j], fp16 j pair-permuted, half2 stores.
// ---------------------------------------------------------------------------
__global__ __launch_bounds__(256)
void proj_kernel(const float* __restrict__ x,
                 const float* __restrict__ w1, const float* __restrict__ b1,
                 const float* __restrict__ w2, const float* __restrict__ b2,
                 const float* __restrict__ w3, const float* __restrict__ b3) {
    __shared__ float xt_s[8][32][33];
    __shared__ float w1s[8], w2s[8], w3s[64], b3s[8], bqk[2];
    const int tid = threadIdx.x;
    if (tid < 8)  { w1s[tid] = w1[tid]; w2s[tid] = w2[tid]; b3s[tid] = b3[tid]; }
    if (tid < 64) w3s[tid] = w3[tid];
    if (tid == 0) { bqk[0] = b1[0]; bqk[1] = b2[0]; }
    __syncthreads();
    const int b = blockIdx.z, j0 = blockIdx.y * 32, w0 = blockIdx.x * 32;
    const int jl = tid >> 3, wq = (tid & 7) << 2;
    const float* xb = x + (size_t)b * NC * HW + (size_t)(j0 + jl) * NW + w0 + wq;

    float4 xv[8];
#pragma unroll
    for (int c = 0; c < 8; c++) xv[c] = *(const float4*)(xb + (size_t)c * HW);

    float4 q = make_float4(bqk[0], bqk[0], bqk[0], bqk[0]);
    float4 k = make_float4(bqk[1], bqk[1], bqk[1], bqk[1]);
#pragma unroll
    for (int c = 0; c < 8; c++) {
        q.x = fmaf(w1s[c], xv[c].x, q.x); q.y = fmaf(w1s[c], xv[c].y, q.y);
        q.z = fmaf(w1s[c], xv[c].z, q.z); q.w = fmaf(w1s[c], xv[c].w, q.w);
        k.x = fmaf(w2s[c], xv[c].x, k.x); k.y = fmaf(w2s[c], xv[c].y, k.y);
        k.z = fmaf(w2s[c], xv[c].z, k.z); k.w = fmaf(w2s[c], xv[c].w, k.w);
    }
    // hi/lo split + pair-permuted half2 stores
    {
        const size_t rowoff = (size_t)b * HW + (size_t)(j0 + jl) * NW + ((w0 + wq) & ~15);
        const int kb = wq & 15;
        const int h0 = kperm16(kb), h1 = kperm16(kb + 2);
        __half qhx = __float2half_rn(q.x), qhy = __float2half_rn(q.y);
        __half qhz = __float2half_rn(q.z), qhw = __float2half_rn(q.w);
        __half khx = __float2half_rn(k.x), khy = __float2half_rn(k.y);
        __half khz = __float2half_rn(k.z), khw = __float2half_rn(k.w);
        *(__half2*)(g_qh + rowoff + h0) = __halves2half2(qhx, qhy);
        *(__half2*)(g_qh + rowoff + h1) = __halves2half2(qhz, qhw);
        *(__half2*)(g_kh + rowoff + h0) = __halves2half2(khx, khy);
        *(__half2*)(g_kh + rowoff + h1) = __halves2half2(khz, khw);
        *(__half2*)(g_ql + rowoff + h0) = __floats2half2_rn(q.x - __half2float(qhx),
                                                            q.y - __half2float(qhy));
        *(__half2*)(g_ql + rowoff + h1) = __floats2half2_rn(q.z - __half2float(qhz),
                                                            q.w - __half2float(qhw));
        *(__half2*)(g_kl + rowoff + h0) = __floats2half2_rn(k.x - __half2float(khx),
                                                            k.y - __half2float(khy));
        *(__half2*)(g_kl + rowoff + h1) = __floats2half2_rn(k.z - __half2float(khz),
                                                            k.w - __half2float(khw));
    }

#pragma unroll
    for (int c = 0; c < 8; c++) {
        float4 v = make_float4(b3s[c], b3s[c], b3s[c], b3s[c]);
#pragma unroll
        for (int cp = 0; cp < 8; cp++) {
            float w = w3s[c * 8 + cp];
            v.x = fmaf(w, xv[cp].x, v.x); v.y = fmaf(w, xv[cp].y, v.y);
            v.z = fmaf(w, xv[cp].z, v.z); v.w = fmaf(w, xv[cp].w, v.w);
        }
        xt_s[c][jl][wq + 0] = v.x; xt_s[c][jl][wq + 1] = v.y;
        xt_s[c][jl][wq + 2] = v.z; xt_s[c][jl][wq + 3] = v.w;
    }
    __syncthreads();
    // transposed + pair-permuted fp16 write (half2 over original j pairs)
    const int jp = (tid & 15) << 1, wl = tid >> 4;
    const int hoff = (jp & 16) + kperm16(jp & 15);
#pragma unroll
    for (int c = 0; c < 8; c++)
#pragma unroll
        for (int ws = 0; ws < 32; ws += 16) {
            int wg = ws + wl;
            *(__half2*)(g_vth + (((size_t)(b * 8 + c)) * NW + w0 + wg) * NH + j0 + hoff) =
                __floats2half2_rn(xt_s[c][jp][wg], xt_s[c][jp + 1][wg]);
        }
}

// ---------------------------------------------------------------------------
// Kernel B: FUSED scores+softmax, fp16 3-term split (qh·kh + qh·kl + ql·kh).
// CTA: M=64 x N=256, K=256 in 16 chunks of k16. 256 thr = 8 warps (2m x 4n).
// Stage: qh 2KB | ql 2KB | kh 8KB | kl 8KB = 20KB, linear 32B rows (no swz).
// ---------------------------------------------------------------------------
#define NSTG 3
#define F_QH 0
#define F_QL 2048
#define F_KH 4096
#define F_KL 12288
#define F_STG 20480
#define SMEM_FUSED (NSTG * F_STG + 4 * 64 * 4)

__global__ __launch_bounds__(256, 2)
void scores_softmax_kernel() {
    extern __shared__ char smem[];
    const uint32_t sb = smem_u32(smem);
    float* red = (float*)(smem + NSTG * F_STG);    // [4][64]
    const int tid = threadIdx.x;
    const int lane = tid & 31, warp = tid >> 5;
    const int warpM = warp & 1, warpN = warp >> 1;
    const int g = lane >> 2, t4 = lane & 3;

    const int i0 = blockIdx.x * 64;
    const int b  = blockIdx.y;
    const size_t qoff = (size_t)b * HW + (size_t)i0 * NW;
    const size_t koff = (size_t)b * HW;

    // staging indices: A (qh/ql): 1 quad/thread; B (kh/kl): 4 quads/thread
    const int a_row = tid & 63, a_part = (tid >> 6) & 1, a_arr = tid >> 7;
    const __half* a_src = (a_arr ? g_ql : g_qh) + qoff + (size_t)a_row * NW + a_part * 8;
    const uint32_t a_dst = (uint32_t)(a_arr * 2048 + a_row * 32 + a_part * 16);

    float acc[2][8][4];
#pragma unroll
    for (int mi = 0; mi < 2; mi++)
#pragma unroll
        for (int ni = 0; ni < 8; ni++)
#pragma unroll
            for (int r = 0; r < 4; r++) acc[mi][ni][r] = 0.f;

#pragma unroll
    for (int s = 0; s < NSTG - 1; s++) {
        uint32_t st = sb + s * F_STG;
        CP16(st + a_dst, a_src + s * 16);
#pragma unroll
        for (int u = 0; u < 4; u++) {
            int item = tid + 256 * u;
            int n = item & 255, part = (item >> 8) & 1, arr = item >> 9;
            const __half* src = (arr ? g_kl : g_kh) + koff + (size_t)n * NW + s * 16 + part * 8;
            CP16(st + F_KH + arr * 8192 + n * 32 + part * 16, src);
        }
        CP_COMMIT();
    }

    for (int kc = 0; kc < 16; kc++) {
        CP_WAIT1();
        __syncthreads();

        const int pf = kc + NSTG - 1;
        if (pf < 16) {
            uint32_t st = sb + (pf % NSTG) * F_STG;
            CP16(st + a_dst, a_src + pf * 16);
#pragma unroll
            for (int u = 0; u < 4; u++) {
                int item = tid + 256 * u;
                int n = item & 255, part = (item >> 8) & 1, arr = item >> 9;
                const __half* src = (arr ? g_kl : g_kh) + koff + (size_t)n * NW + pf * 16 + part * 8;
                CP16(st + F_KH + arr * 8192 + n * 32 + part * 16, src);
            }
        }
        CP_COMMIT();

        const uint32_t st = sb + (kc % NSTG) * F_STG;
        const uint32_t tq = (uint32_t)(t4 * 8);

        uint32_t ah[2][4], al[2][4];
#pragma unroll
        for (int mi = 0; mi < 2; mi++) {
            int r0 = warpM * 32 + mi * 16 + g, r1 = r0 + 8;
            uint2 h0 = lds64(st + F_QH + r0 * 32 + tq);
            uint2 h1 = lds64(st + F_QH + r1 * 32 + tq);
            uint2 l0 = lds64(st + F_QL + r0 * 32 + tq);
            uint2 l1 = lds64(st + F_QL + r1 * 32 + tq);
            ah[mi][0] = h0.x; ah[mi][1] = h1.x; ah[mi][2] = h0.y; ah[mi][3] = h1.y;
            al[mi][0] = l0.x; al[mi][1] = l1.x; al[mi][2] = l0.y; al[mi][3] = l1.y;
        }
#pragma unroll
        for (int ni = 0; ni < 8; ni++) {
            int n = warpN * 64 + ni * 8 + g;
            uint2 bh = lds64(st + F_KH + n * 32 + tq);
            uint2 bl = lds64(st + F_KL + n * 32 + tq);
#pragma unroll
            for (int mi = 0; mi < 2; mi++) {
                MMA_F16(acc[mi][ni], ah[mi][0], ah[mi][1], ah[mi][2], ah[mi][3],
                        bh.x, bh.y);
                MMA_F16(acc[mi][ni], ah[mi][0], ah[mi][1], ah[mi][2], ah[mi][3],
                        bl.x, bl.y);
                MMA_F16(acc[mi][ni], al[mi][0], al[mi][1], al[mi][2], al[mi][3],
                        bh.x, bh.y);
            }
        }
    }

    // ---- fused softmax (lane owns 4 rows x 16 cols; 4 n-warps via smem) ----
    float rowv[4];
#pragma unroll
    for (int mi = 0; mi < 2; mi++)
#pragma unroll
        for (int h = 0; h < 2; h++) {
            float m = -FLT_MAX;
#pragma unroll
            for (int ni = 0; ni < 8; ni++)
                m = fmaxf(m, fmaxf(acc[mi][ni][h * 2], acc[mi][ni][h * 2 + 1]));
            m = fmaxf(m, __shfl_xor_sync(0xffffffffu, m, 1));
            m = fmaxf(m, __shfl_xor_sync(0xffffffffu, m, 2));
            rowv[mi * 2 + h] = m;
        }
    if (t4 == 0) {
#pragma unroll
        for (int mi = 0; mi < 2; mi++)
#pragma unroll
            for (int h = 0; h < 2; h++)
                red[warpN * 64 + warpM * 32 + mi * 16 + h * 8 + g] = rowv[mi * 2 + h];
    }
    __syncthreads();
    float rowmax[4];
#pragma unroll
    for (int mi = 0; mi < 2; mi++)
#pragma unroll
        for (int h = 0; h < 2; h++) {
            int rl = warpM * 32 + mi * 16 + h * 8 + g;
            rowmax[mi * 2 + h] = fmaxf(fmaxf(red[rl], red[64 + rl]),
                                       fmaxf(red[128 + rl], red[192 + rl]));
        }
    __syncthreads();
#pragma unroll
    for (int mi = 0; mi < 2; mi++)
#pragma unroll
        for (int h = 0; h < 2; h++) {
            float m = rowmax[mi * 2 + h], s = 0.f;
#pragma unroll
            for (int ni = 0; ni < 8; ni++) {
                float e0 = fast_exp(acc[mi][ni][h * 2] - m);
                float e1 = fast_exp(acc[mi][ni][h * 2 + 1] - m);
                acc[mi][ni][h * 2] = e0; acc[mi][ni][h * 2 + 1] = e1;
                s += e0 + e1;
            }
            s += __shfl_xor_sync(0xffffffffu, s, 1);
            s += __shfl_xor_sync(0xffffffffu, s, 2);
            rowv[mi * 2 + h] = s;
        }
    if (t4 == 0) {
#pragma unroll
        for (int mi = 0; mi < 2; mi++)
#pragma unroll
            for (int h = 0; h < 2; h++)
                red[warpN * 64 + warpM * 32 + mi * 16 + h * 8 + g] = rowv[mi * 2 + h];
    }
    __syncthreads();
    __half* attn = g_attnh + (size_t)b * NH * NH;
#pragma unroll
    for (int mi = 0; mi < 2; mi++)
#pragma unroll
        for (int h = 0; h < 2; h++) {
            int rl = warpM * 32 + mi * 16 + h * 8 + g;
            float inv = 1.0f / (red[rl] + red[64 + rl] + red[128 + rl] + red[192 + rl]);
            size_t rb = (size_t)(i0 + rl) * NH;
#pragma unroll
            for (int ni = 0; ni < 8; ni++) {
                int j = warpN * 64 + ni * 8 + t4 * 2;
                int idx = (j & ~15) + kperm16(j & 15);
                *(__half2*)(attn + rb + idx) =
                    __floats2half2_rn(acc[mi][ni][h * 2] * inv,
                                      acc[mi][ni][h * 2 + 1] * inv);
            }
        }
}

// ---------------------------------------------------------------------------
// Kernel D: out[b,c] = attn_b @ v[b,c], FP16 HMMA m16n8k16 (validated R8).
// CTA 128x128, K=256 in 8 chunks of 32 halfs. 256 thr = 8 warps (4m x 2n).
// ---------------------------------------------------------------------------
#define H_A_ST 8192
#define H_B_ST 8192
#define H_STG (H_A_ST + H_B_ST)
#define SMEM_MMA (NSTG * H_STG)

__global__ __launch_bounds__(256, 2)
void mma_out_kernel(float* __restrict__ out) {
    extern __shared__ char smem[];
    const uint32_t sb = smem_u32(smem);
    const int tid = threadIdx.x;
    const int lane = tid & 31, warp = tid >> 5;
    const int warpM = warp & 3, warpN = warp >> 2;
    const int g = lane >> 2, t4 = lane & 3;

    const int mt = blockIdx.x & 1, nt = blockIdx.x >> 1;
    const int i0 = mt * 128, n0 = nt * 128;
    const int c  = blockIdx.y;
    const int b  = blockIdx.z;
    const __half* Ab = g_attnh + (size_t)b * NH * NH + (size_t)i0 * NH;
    const __half* Bb = g_vth + ((size_t)(b * 8 + c)) * HW + (size_t)n0 * NH;

    const int ar = tid >> 2, aq = tid & 3;

    float acc[2][8][4];
#pragma unroll
    for (int mi = 0; mi < 2; mi++)
#pragma unroll
        for (int ni = 0; ni < 8; ni++)
#pragma unroll
            for (int r = 0; r < 4; r++) acc[mi][ni][r] = 0.f;

#pragma unroll
    for (int s = 0; s < NSTG - 1; s++) {
        uint32_t as = sb + s * H_STG, bs = as + H_A_ST;
#pragma unroll
        for (int u = 0; u < 2; u++) {
            int row = ar + 64 * u;
            uint32_t so = (uint32_t)(row * 64 + ((aq ^ (((row >> 1) & 1) << 1)) << 4));
            CP16(as + so, Ab + (size_t)row * NH + s * 32 + aq * 8);
            CP16(bs + so, Bb + (size_t)row * NH + s * 32 + aq * 8);
        }
        CP_COMMIT();
    }

    for (int kc = 0; kc < 8; kc++) {
        CP_WAIT1();
        __syncthreads();

        const int pf = kc + NSTG - 1;
        if (pf < 8) {
            uint32_t as = sb + (pf % NSTG) * H_STG, bs = as + H_A_ST;
#pragma unroll
            for (int u = 0; u < 2; u++) {
                int row = ar + 64 * u;
                uint32_t so = (uint32_t)(row * 64 + ((aq ^ (((row >> 1) & 1) << 1)) << 4));
                CP16(as + so, Ab + (size_t)row * NH + pf * 32 + aq * 8);
                CP16(bs + so, Bb + (size_t)row * NH + pf * 32 + aq * 8);
            }
        }
        CP_COMMIT();

        const uint32_t as = sb + (kc % NSTG) * H_STG;
        const uint32_t bs = as + H_A_ST;

#pragma unroll
        for (int ks = 0; ks < 2; ks++) {
            uint32_t aop[2][4];
#pragma unroll
            for (int mi = 0; mi < 2; mi++) {
                int r0 = warpM * 32 + mi * 16 + g;
                int r1 = r0 + 8;
                uint32_t s0 = (uint32_t)((ks * 4 + t4) ^ (((r0 >> 1) & 1) << 2));
                uint32_t s1 = (uint32_t)((ks * 4 + t4) ^ (((r1 >> 1) & 1) << 2));
                uint2 q0 = lds64(as + r0 * 64 + s0 * 8);
                uint2 q1 = lds64(as + r1 * 64 + s1 * 8);
                aop[mi][0] = q0.x; aop[mi][1] = q1.x;
                aop[mi][2] = q0.y; aop[mi][3] = q1.y;
            }
#pragma unroll
            for (int ni = 0; ni < 8; ni++) {
                int n = warpN * 64 + ni * 8 + g;
                uint32_t sn = (uint32_t)((ks * 4 + t4) ^ (((n >> 1) & 1) << 2));
                uint2 bq = lds64(bs + n * 64 + sn * 8);
#pragma unroll
                for (int mi = 0; mi < 2; mi++)
                    MMA_F16(acc[mi][ni], aop[mi][0], aop[mi][1],
                            aop[mi][2], aop[mi][3], bq.x, bq.y);
            }
        }
    }

    float* ob = out + ((size_t)(b * 8 + c)) * HW;
#pragma unroll
    for (int mi = 0; mi < 2; mi++) {
        int row = i0 + warpM * 32 + mi * 16 + g;
#pragma unroll
        for (int ni = 0; ni < 8; ni++) {
            int col = n0 + warpN * 64 + ni * 8 + t4 * 2;
            *(float2*)(ob + (size_t)row * NW + col) =
                make_float2(acc[mi][ni][0], acc[mi][ni][1]);
            *(float2*)(ob + (size_t)(row + 8) * NW + col) =
                make_float2(acc[mi][ni][2], acc[mi][ni][3]);
        }
    }
}

// ---------------------------------------------------------------------------
extern "C" void kernel_launch(void* const* d_in, const int* in_sizes, int n_in,
                              void* d_out, int out_size) {
    const float* x  = (const float*)d_in[0];
    const float* w1 = (const float*)d_in[1];
    const float* b1 = (const float*)d_in[2];
    const float* w2 = (const float*)d_in[3];
    const float* b2 = (const float*)d_in[4];
    const float* w3 = (const float*)d_in[5];
    const float* b3 = (const float*)d_in[6];
    float* out = (float*)d_out;

    static bool configured = false;
    if (!configured) {
        cudaFuncSetAttribute(scores_softmax_kernel,
                             cudaFuncAttributeMaxDynamicSharedMemorySize, SMEM_FUSED);
        cudaFuncSetAttribute(mma_out_kernel,
                             cudaFuncAttributeMaxDynamicSharedMemorySize, SMEM_MMA);
        configured = true;
    }

    dim3 ga(8, 8, NB);
    proj_kernel<<<ga, 256>>>(x, w1, b1, w2, b2, w3, b3);
    dim3 gs(4, NB);
    scores_softmax_kernel<<<gs, 256, SMEM_FUSED>>>();
    dim3 gd(4, 8, NB);
    mma_out_kernel<<<gd, 256, SMEM_MMA>>>(out);
}

// round 10
// speedup vs baseline: 3.6701x; 1.0162x over previous
#include <cuda_runtime.h>
#include <cuda_fp16.h>
#include <cstdint>
#include <cfloat>

#define NB 64
#define NC 8
#define NH 256
#define NW 256
#define HW (NH*NW)

// Scratch (__device__ globals per allocation-free rule)
__device__ __half g_qh[NB*HW], g_ql[NB*HW];    // q hi/lo fp16, w pair-permuted
__device__ __half g_kh[NB*HW], g_kl[NB*HW];    // k hi/lo fp16, w pair-permuted
__device__ __half g_attnh[(size_t)NB*NH*NH];   // fp16 attn, swizzled rows (see layout)
__device__ __half g_vth[(size_t)NB*NC*HW];     // fp16 v^T [b][c][w][j], swizzled rows

// Global row layout for bulk-copied operands (attn, vth): within each 256-half
// (512B) row at row-index r, element j is stored at
//   ((blk ^ (r&3)) << 4) + kperm16(j & 15),   blk = j >> 4.
// The XOR makes the *linear* bulk copy land bank-conflict-free for the MMA
// fragment LDS.64 pattern; kperm16 packs each thread's (t4, t4+4) k-pairs
// into one contiguous 8B slot.

// ---------------------------------------------------------------------------
// helpers
// ---------------------------------------------------------------------------
__device__ __forceinline__ uint32_t smem_u32(const void* p) {
    uint32_t a;
    asm("{ .reg .u64 t; cvta.to.shared.u64 t, %1; cvt.u32.u64 %0, t; }" : "=r"(a) : "l"(p));
    return a;
}
__device__ __forceinline__ uint2 lds64(uint32_t a) {
    uint2 v;
    asm volatile("ld.shared.v2.u32 {%0,%1}, [%2];" : "=r"(v.x), "=r"(v.y) : "r"(a));
    return v;
}
// exp(x) for x <= 0, FMA-pipe only: 2^(x*log2e), deg-6 poly
__device__ __forceinline__ float fast_exp(float x) {
    float t = fmaxf(x * 1.4426950408889634f, -126.0f);
    float n = rintf(t);
    float f = t - n;
    float p = fmaf(f, 0.00015403530393381609f, 0.0013333558146428443f);
    p = fmaf(f, p, 0.009618129107628477f);
    p = fmaf(f, p, 0.0555041086648216f);
    p = fmaf(f, p, 0.2402265069591007f);
    p = fmaf(f, p, 0.6931471805599453f);
    p = fmaf(f, p, 1.0f);
    return __int_as_float(__float_as_int(p) + (((int)n) << 23));
}
#define CP16(sa, ga) asm volatile("cp.async.cg.shared.global [%0], [%1], 16;" :: "r"(sa), "l"(ga))
#define CP_COMMIT()  asm volatile("cp.async.commit_group;")
#define CP_WAIT1()   asm volatile("cp.async.wait_group 1;")
#define MBAR_INIT(a, n) asm volatile("mbarrier.init.shared.b64 [%0], %1;" :: "r"(a), "r"(n) : "memory")
#define MBAR_EXPECT(a, tx) asm volatile("mbarrier.arrive.expect_tx.shared.b64 _, [%0], %1;" :: "r"(a), "r"(tx) : "memory")
#define MBAR_WAIT(a, ph) do {                                                        \
    uint32_t _m = (a), _p = (ph), _d;                                                \
    asm volatile("{ .reg .pred p; mbarrier.try_wait.parity.acquire.cta.shared::cta.b64 p, [%1], %2; selp.b32 %0,1,0,p; }" \
                 : "=r"(_d) : "r"(_m), "r"(_p) : "memory");                          \
    if (!_d) {                                                                       \
      asm volatile("{ .reg .pred P1; WL%=: mbarrier.try_wait.parity.acquire.cta.shared::cta.b64 P1, [%0], %1, 0x989680; @P1 bra.uni WD%=; bra.uni WL%=; WD%=: }" \
                   :: "r"(_m), "r"(_p) : "memory");                                  \
    } } while (0)
#define BULK_G2S(sdst, gsrc, bytes, mbar)                                            \
    asm volatile("cp.async.bulk.shared::cta.global.mbarrier::complete_tx::bytes "    \
                 "[%0], [%1], %2, [%3];"                                             \
                 :: "r"(sdst), "l"(gsrc), "r"(bytes), "r"(mbar) : "memory")
#define MMA_F16(d, a0, a1, a2, a3, b0, b1)                                        \
    asm volatile("mma.sync.aligned.m16n8k16.row.col.f32.f16.f16.f32 "             \
                 "{%0,%1,%2,%3},{%4,%5,%6,%7},{%8,%9},{%0,%1,%2,%3};"             \
                 : "+f"(d[0]), "+f"(d[1]), "+f"(d[2]), "+f"(d[3])                  \
                 : "r"(a0), "r"(a1), "r"(a2), "r"(a3), "r"(b0), "r"(b1))

// fp16 k-pair permutation within a 16-element block.
__device__ __forceinline__ int kperm16(int kb) {   // kb = k & 15
    int pk = kb >> 1;
    return ((((pk & 3) << 1) | (pk >> 2)) << 1) | (kb & 1);
}

// ---------------------------------------------------------------------------
// Kernel A: fused projections. q,k -> fp16 hi/lo, w pair-permuted;
// v = w3@x + b3 transposed [b][c][w][j], fp16, swizzled-row layout.
// ---------------------------------------------------------------------------
__global__ __launch_bounds__(256)
void proj_kernel(const float* __restrict__ x,
                 const float* __restrict__ w1, const float* __restrict__ b1,
                 const float* __restrict__ w2, const float* __restrict__ b2,
                 const float* __restrict__ w3, const float* __restrict__ b3) {
    __shared__ float xt_s[8][32][33];
    __shared__ float w1s[8], w2s[8], w3s[64], b3s[8], bqk[2];
    const int tid = threadIdx.x;
    if (tid < 8)  { w1s[tid] = w1[tid]; w2s[tid] = w2[tid]; b3s[tid] = b3[tid]; }
    if (tid < 64) w3s[tid] = w3[tid];
    if (tid == 0) { bqk[0] = b1[0]; bqk[1] = b2[0]; }
    __syncthreads();
    const int b = blockIdx.z, j0 = blockIdx.y * 32, w0 = blockIdx.x * 32;
    const int jl = tid >> 3, wq = (tid & 7) << 2;
    const float* xb = x + (size_t)b * NC * HW + (size_t)(j0 + jl) * NW + w0 + wq;

    float4 xv[8];
#pragma unroll
    for (int c = 0; c < 8; c++) xv[c] = *(const float4*)(xb + (size_t)c * HW);

    float4 q = make_float4(bqk[0], bqk[0], bqk[0], bqk[0]);
    float4 k = make_float4(bqk[1], bqk[1], bqk[1], bqk[1]);
#pragma unroll
    for (int c = 0; c < 8; c++) {
        q.x = fmaf(w1s[c], xv[c].x, q.x); q.y = fmaf(w1s[c], xv[c].y, q.y);
        q.z = fmaf(w1s[c], xv[c].z, q.z); q.w = fmaf(w1s[c], xv[c].w, q.w);
        k.x = fmaf(w2s[c], xv[c].x, k.x); k.y = fmaf(w2s[c], xv[c].y, k.y);
        k.z = fmaf(w2s[c], xv[c].z, k.z); k.w = fmaf(w2s[c], xv[c].w, k.w);
    }
    // hi/lo split + pair-permuted half2 stores (q/k layout unchanged from R9)
    {
        const size_t rowoff = (size_t)b * HW + (size_t)(j0 + jl) * NW + ((w0 + wq) & ~15);
        const int kb = wq & 15;
        const int h0 = kperm16(kb), h1 = kperm16(kb + 2);
        __half qhx = __float2half_rn(q.x), qhy = __float2half_rn(q.y);
        __half qhz = __float2half_rn(q.z), qhw = __float2half_rn(q.w);
        __half khx = __float2half_rn(k.x), khy = __float2half_rn(k.y);
        __half khz = __float2half_rn(k.z), khw = __float2half_rn(k.w);
        *(__half2*)(g_qh + rowoff + h0) = __halves2half2(qhx, qhy);
        *(__half2*)(g_qh + rowoff + h1) = __halves2half2(qhz, qhw);
        *(__half2*)(g_kh + rowoff + h0) = __halves2half2(khx, khy);
        *(__half2*)(g_kh + rowoff + h1) = __halves2half2(khz, khw);
        *(__half2*)(g_ql + rowoff + h0) = __floats2half2_rn(q.x - __half2float(qhx),
                                                            q.y - __half2float(qhy));
        *(__half2*)(g_ql + rowoff + h1) = __floats2half2_rn(q.z - __half2float(qhz),
                                                            q.w - __half2float(qhw));
        *(__half2*)(g_kl + rowoff + h0) = __floats2half2_rn(k.x - __half2float(khx),
                                                            k.y - __half2float(khy));
        *(__half2*)(g_kl + rowoff + h1) = __floats2half2_rn(k.z - __half2float(khz),
                                                            k.w - __half2float(khw));
    }

#pragma unroll
    for (int c = 0; c < 8; c++) {
        float4 v = make_float4(b3s[c], b3s[c], b3s[c], b3s[c]);
#pragma unroll
        for (int cp = 0; cp < 8; cp++) {
            float w = w3s[c * 8 + cp];
            v.x = fmaf(w, xv[cp].x, v.x); v.y = fmaf(w, xv[cp].y, v.y);
            v.z = fmaf(w, xv[cp].z, v.z); v.w = fmaf(w, xv[cp].w, v.w);
        }
        xt_s[c][jl][wq + 0] = v.x; xt_s[c][jl][wq + 1] = v.y;
        xt_s[c][jl][wq + 2] = v.z; xt_s[c][jl][wq + 3] = v.w;
    }
    __syncthreads();
    // transposed fp16 write in swizzled-row layout
    const int jp = (tid & 15) << 1, wl = tid >> 4;
    const int pos = kperm16(jp & 15);
    const int blk = (j0 + jp) >> 4;
#pragma unroll
    for (int c = 0; c < 8; c++)
#pragma unroll
        for (int ws = 0; ws < 32; ws += 16) {
            int wg = ws + wl;
            int idx = ((blk ^ (wg & 3)) << 4) + pos;
            *(__half2*)(g_vth + (((size_t)(b * 8 + c)) * NW + w0 + wg) * NH + idx) =
                __floats2half2_rn(xt_s[c][jp][wg], xt_s[c][jp + 1][wg]);
        }
}

// ---------------------------------------------------------------------------
// Kernel B: FUSED scores+softmax, fp16 3-term split (validated R9).
// Stores attn fp16 in the swizzled-row layout for bulk-copy consumption.
// ---------------------------------------------------------------------------
#define NSTG 3
#define F_QH 0
#define F_QL 2048
#define F_KH 4096
#define F_KL 12288
#define F_STG 20480
#define SMEM_FUSED (NSTG * F_STG + 4 * 64 * 4)

__global__ __launch_bounds__(256, 2)
void scores_softmax_kernel() {
    extern __shared__ char smem[];
    const uint32_t sb = smem_u32(smem);
    float* red = (float*)(smem + NSTG * F_STG);    // [4][64]
    const int tid = threadIdx.x;
    const int lane = tid & 31, warp = tid >> 5;
    const int warpM = warp & 1, warpN = warp >> 1;
    const int g = lane >> 2, t4 = lane & 3;

    const int i0 = blockIdx.x * 64;
    const int b  = blockIdx.y;
    const size_t qoff = (size_t)b * HW + (size_t)i0 * NW;
    const size_t koff = (size_t)b * HW;

    const int a_row = tid & 63, a_part = (tid >> 6) & 1, a_arr = tid >> 7;
    const __half* a_src = (a_arr ? g_ql : g_qh) + qoff + (size_t)a_row * NW + a_part * 8;
    const uint32_t a_dst = (uint32_t)(a_arr * 2048 + a_row * 32 + a_part * 16);

    float acc[2][8][4];
#pragma unroll
    for (int mi = 0; mi < 2; mi++)
#pragma unroll
        for (int ni = 0; ni < 8; ni++)
#pragma unroll
            for (int r = 0; r < 4; r++) acc[mi][ni][r] = 0.f;

#pragma unroll
    for (int s = 0; s < NSTG - 1; s++) {
        uint32_t st = sb + s * F_STG;
        CP16(st + a_dst, a_src + s * 16);
#pragma unroll
        for (int u = 0; u < 4; u++) {
            int item = tid + 256 * u;
            int n = item & 255, part = (item >> 8) & 1, arr = item >> 9;
            const __half* src = (arr ? g_kl : g_kh) + koff + (size_t)n * NW + s * 16 + part * 8;
            CP16(st + F_KH + arr * 8192 + n * 32 + part * 16, src);
        }
        CP_COMMIT();
    }

    for (int kc = 0; kc < 16; kc++) {
        CP_WAIT1();
        __syncthreads();

        const int pf = kc + NSTG - 1;
        if (pf < 16) {
            uint32_t st = sb + (pf % NSTG) * F_STG;
            CP16(st + a_dst, a_src + pf * 16);
#pragma unroll
            for (int u = 0; u < 4; u++) {
                int item = tid + 256 * u;
                int n = item & 255, part = (item >> 8) & 1, arr = item >> 9;
                const __half* src = (arr ? g_kl : g_kh) + koff + (size_t)n * NW + pf * 16 + part * 8;
                CP16(st + F_KH + arr * 8192 + n * 32 + part * 16, src);
            }
        }
        CP_COMMIT();

        const uint32_t st = sb + (kc % NSTG) * F_STG;
        const uint32_t tq = (uint32_t)(t4 * 8);

        uint32_t ah[2][4], al[2][4];
#pragma unroll
        for (int mi = 0; mi < 2; mi++) {
            int r0 = warpM * 32 + mi * 16 + g, r1 = r0 + 8;
            uint2 h0 = lds64(st + F_QH + r0 * 32 + tq);
            uint2 h1 = lds64(st + F_QH + r1 * 32 + tq);
            uint2 l0 = lds64(st + F_QL + r0 * 32 + tq);
            uint2 l1 = lds64(st + F_QL + r1 * 32 + tq);
            ah[mi][0] = h0.x; ah[mi][1] = h1.x; ah[mi][2] = h0.y; ah[mi][3] = h1.y;
            al[mi][0] = l0.x; al[mi][1] = l1.x; al[mi][2] = l0.y; al[mi][3] = l1.y;
        }
#pragma unroll
        for (int ni = 0; ni < 8; ni++) {
            int n = warpN * 64 + ni * 8 + g;
            uint2 bh = lds64(st + F_KH + n * 32 + tq);
            uint2 bl = lds64(st + F_KL + n * 32 + tq);
#pragma unroll
            for (int mi = 0; mi < 2; mi++) {
                MMA_F16(acc[mi][ni], ah[mi][0], ah[mi][1], ah[mi][2], ah[mi][3],
                        bh.x, bh.y);
                MMA_F16(acc[mi][ni], ah[mi][0], ah[mi][1], ah[mi][2], ah[mi][3],
                        bl.x, bl.y);
                MMA_F16(acc[mi][ni], al[mi][0], al[mi][1], al[mi][2], al[mi][3],
                        bh.x, bh.y);
            }
        }
    }

    // ---- fused softmax ----
    float rowv[4];
#pragma unroll
    for (int mi = 0; mi < 2; mi++)
#pragma unroll
        for (int h = 0; h < 2; h++) {
            float m = -FLT_MAX;
#pragma unroll
            for (int ni = 0; ni < 8; ni++)
                m = fmaxf(m, fmaxf(acc[mi][ni][h * 2], acc[mi][ni][h * 2 + 1]));
            m = fmaxf(m, __shfl_xor_sync(0xffffffffu, m, 1));
            m = fmaxf(m, __shfl_xor_sync(0xffffffffu, m, 2));
            rowv[mi * 2 + h] = m;
        }
    if (t4 == 0) {
#pragma unroll
        for (int mi = 0; mi < 2; mi++)
#pragma unroll
            for (int h = 0; h < 2; h++)
                red[warpN * 64 + warpM * 32 + mi * 16 + h * 8 + g] = rowv[mi * 2 + h];
    }
    __syncthreads();
    float rowmax[4];
#pragma unroll
    for (int mi = 0; mi < 2; mi++)
#pragma unroll
        for (int h = 0; h < 2; h++) {
            int rl = warpM * 32 + mi * 16 + h * 8 + g;
            rowmax[mi * 2 + h] = fmaxf(fmaxf(red[rl], red[64 + rl]),
                                       fmaxf(red[128 + rl], red[192 + rl]));
        }
    __syncthreads();
#pragma unroll
    for (int mi = 0; mi < 2; mi++)
#pragma unroll
        for (int h = 0; h < 2; h++) {
            float m = rowmax[mi * 2 + h], s = 0.f;
#pragma unroll
            for (int ni = 0; ni < 8; ni++) {
                float e0 = fast_exp(acc[mi][ni][h * 2] - m);
                float e1 = fast_exp(acc[mi][ni][h * 2 + 1] - m);
                acc[mi][ni][h * 2] = e0; acc[mi][ni][h * 2 + 1] = e1;
                s += e0 + e1;
            }
            s += __shfl_xor_sync(0xffffffffu, s, 1);
            s += __shfl_xor_sync(0xffffffffu, s, 2);
            rowv[mi * 2 + h] = s;
        }
    if (t4 == 0) {
#pragma unroll
        for (int mi = 0; mi < 2; mi++)
#pragma unroll
            for (int h = 0; h < 2; h++)
                red[warpN * 64 + warpM * 32 + mi * 16 + h * 8 + g] = rowv[mi * 2 + h];
    }
    __syncthreads();
    __half* attn = g_attnh + (size_t)b * NH * NH;
#pragma unroll
    for (int mi = 0; mi < 2; mi++)
#pragma unroll
        for (int h = 0; h < 2; h++) {
            int rl = warpM * 32 + mi * 16 + h * 8 + g;
            float inv = 1.0f / (red[rl] + red[64 + rl] + red[128 + rl] + red[192 + rl]);
            size_t rb = (size_t)(i0 + rl) * NH;
#pragma unroll
            for (int ni = 0; ni < 8; ni++) {
                int j = warpN * 64 + ni * 8 + t4 * 2;
                int idx = (((j >> 4) ^ (rl & 3)) << 4) + kperm16(j & 15);
                *(__half2*)(attn + rb + idx) =
                    __floats2half2_rn(acc[mi][ni][h * 2] * inv,
                                      acc[mi][ni][h * 2 + 1] * inv);
            }
        }
}

// ---------------------------------------------------------------------------
// Kernel D: out[b,c] = attn_b @ v[b,c] via FP16 HMMA with BULK-COPY operands.
// CTA = (b, c, mt): A tile (128 x 256 halfs = 64KB, contiguous) bulk-copied
// once; loop 4 n-tiles of 64 rows (32KB bulk each, single buffer).
// 256 thr = 8 warps (4m x 2n), warp tile 32x32. No per-chunk staging at all.
// ---------------------------------------------------------------------------
#define O_MB_A 0
#define O_MB_B 8
#define O_SA 1024
#define O_SB (1024 + 65536)
#define SMEM_OUT (1024 + 65536 + 32768)

__global__ __launch_bounds__(256, 2)
void mma_out_kernel(float* __restrict__ out) {
    extern __shared__ char smem[];
    const uint32_t sb = smem_u32(smem);
    const int tid = threadIdx.x;
    const int lane = tid & 31, warp = tid >> 5;
    const int warpM = warp & 3, warpN = warp >> 2;
    const int g = lane >> 2, t4 = lane & 3;

    const int mt = blockIdx.x & 1, c = blockIdx.x >> 1;
    const int b  = blockIdx.y;
    const int i0 = mt * 128;
    const __half* Ag = g_attnh + (size_t)b * NH * NH + (size_t)i0 * NH;
    const __half* Bg = g_vth + ((size_t)(b * 8 + c)) * HW;

    if (tid == 0) {
        MBAR_INIT(sb + O_MB_A, 1);
        MBAR_INIT(sb + O_MB_B, 1);
    }
    __syncthreads();
    if (tid == 0) {
        MBAR_EXPECT(sb + O_MB_A, 65536u);
        BULK_G2S(sb + O_SA, Ag, 65536u, sb + O_MB_A);
        MBAR_EXPECT(sb + O_MB_B, 32768u);
        BULK_G2S(sb + O_SB, Bg, 32768u, sb + O_MB_B);
    }
    MBAR_WAIT(sb + O_MB_A, 0);

    float* ob = out + ((size_t)(b * 8 + c)) * HW;
    const uint32_t gx = (uint32_t)(g & 3);       // row&3 for all fragment rows

    for (int it = 0; it < 4; it++) {
        MBAR_WAIT(sb + O_MB_B, it & 1);

        float acc[2][4][4];
#pragma unroll
        for (int mi = 0; mi < 2; mi++)
#pragma unroll
            for (int ni = 0; ni < 4; ni++)
#pragma unroll
                for (int r = 0; r < 4; r++) acc[mi][ni][r] = 0.f;

#pragma unroll
        for (int kc = 0; kc < 8; kc++) {
#pragma unroll
            for (int ks = 0; ks < 2; ks++) {
                const uint32_t blk = (uint32_t)(kc * 2 + ks);
                const uint32_t off = ((blk ^ gx) << 5) + (uint32_t)(t4 * 8);
                uint32_t aop[2][4];
#pragma unroll
                for (int mi = 0; mi < 2; mi++) {
                    int r0 = warpM * 32 + mi * 16 + g;
                    uint2 q0 = lds64(sb + O_SA + r0 * 512 + off);
                    uint2 q1 = lds64(sb + O_SA + (r0 + 8) * 512 + off);
                    aop[mi][0] = q0.x; aop[mi][1] = q1.x;
                    aop[mi][2] = q0.y; aop[mi][3] = q1.y;
                }
#pragma unroll
                for (int ni = 0; ni < 4; ni++) {
                    int n = warpN * 32 + ni * 8 + g;
                    uint2 bq = lds64(sb + O_SB + n * 512 + off);
#pragma unroll
                    for (int mi = 0; mi < 2; mi++)
                        MMA_F16(acc[mi][ni], aop[mi][0], aop[mi][1],
                                aop[mi][2], aop[mi][3], bq.x, bq.y);
                }
            }
        }

        __syncthreads();                         // everyone done reading B
        if (tid == 0 && it < 3) {
            MBAR_EXPECT(sb + O_MB_B, 32768u);
            BULK_G2S(sb + O_SB, Bg + (size_t)(it + 1) * 64 * NH, 32768u, sb + O_MB_B);
        }

        // epilogue for this n-tile (overlaps with next B fill)
#pragma unroll
        for (int mi = 0; mi < 2; mi++) {
            int row = i0 + warpM * 32 + mi * 16 + g;
#pragma unroll
            for (int ni = 0; ni < 4; ni++) {
                int col = it * 64 + warpN * 32 + ni * 8 + t4 * 2;
                *(float2*)(ob + (size_t)row * NW + col) =
                    make_float2(acc[mi][ni][0], acc[mi][ni][1]);
                *(float2*)(ob + (size_t)(row + 8) * NW + col) =
                    make_float2(acc[mi][ni][2], acc[mi][ni][3]);
            }
        }
    }
}

// ---------------------------------------------------------------------------
extern "C" void kernel_launch(void* const* d_in, const int* in_sizes, int n_in,
                              void* d_out, int out_size) {
    const float* x  = (const float*)d_in[0];
    const float* w1 = (const float*)d_in[1];
    const float* b1 = (const float*)d_in[2];
    const float* w2 = (const float*)d_in[3];
    const float* b2 = (const float*)d_in[4];
    const float* w3 = (const float*)d_in[5];
    const float* b3 = (const float*)d_in[6];
    float* out = (float*)d_out;

    static bool configured = false;
    if (!configured) {
        cudaFuncSetAttribute(scores_softmax_kernel,
                             cudaFuncAttributeMaxDynamicSharedMemorySize, SMEM_FUSED);
        cudaFuncSetAttribute(mma_out_kernel,
                             cudaFuncAttributeMaxDynamicSharedMemorySize, SMEM_OUT);
        configured = true;
    }

    dim3 ga(8, 8, NB);
    proj_kernel<<<ga, 256>>>(x, w1, b1, w2, b2, w3, b3);
    dim3 gs(4, NB);
    scores_softmax_kernel<<<gs, 256, SMEM_FUSED>>>();
    dim3 gd(16, NB);   // x = mt + 2*c, y = b  (same-b CTAs co-scheduled for L2)
    mma_out_kernel<<<gd, 256, SMEM_OUT>>>(out);
}

// round 11
// speedup vs baseline: 3.7090x; 1.0106x over previous
#include <cuda_runtime.h>
#include <cuda_fp16.h>
#include <cstdint>
#include <cfloat>

#define NB 64
#define NC 8
#define NH 256
#define NW 256
#define HW (NH*NW)

// Scratch (__device__ globals per allocation-free rule)
// Global row layout for ALL fp16 GEMM operands (q,k,attn,vth): within each
// 256-half (512B) row at row-index r, element j is stored at
//   ((blk ^ (r&3)) << 4) + kperm16(j & 15),   blk = j >> 4.
// Linear bulk copies then land bank-conflict-free for MMA fragment LDS.64.
__device__ __half g_qh[NB*HW], g_ql[NB*HW];    // q hi/lo fp16 (3-term split)
__device__ __half g_kh[NB*HW], g_kl[NB*HW];    // k hi/lo fp16
__device__ __half g_attnh[(size_t)NB*NH*NH];   // fp16 attn
__device__ __half g_vth[(size_t)NB*NC*HW];     // fp16 v^T [b][c][w][j]

// ---------------------------------------------------------------------------
// helpers
// ---------------------------------------------------------------------------
__device__ __forceinline__ uint32_t smem_u32(const void* p) {
    uint32_t a;
    asm("{ .reg .u64 t; cvta.to.shared.u64 t, %1; cvt.u32.u64 %0, t; }" : "=r"(a) : "l"(p));
    return a;
}
__device__ __forceinline__ uint2 lds64(uint32_t a) {
    uint2 v;
    asm volatile("ld.shared.v2.u32 {%0,%1}, [%2];" : "=r"(v.x), "=r"(v.y) : "r"(a));
    return v;
}
// exp(x) for x <= 0, FMA-pipe only: 2^(x*log2e), deg-6 poly
__device__ __forceinline__ float fast_exp(float x) {
    float t = fmaxf(x * 1.4426950408889634f, -126.0f);
    float n = rintf(t);
    float f = t - n;
    float p = fmaf(f, 0.00015403530393381609f, 0.0013333558146428443f);
    p = fmaf(f, p, 0.009618129107628477f);
    p = fmaf(f, p, 0.0555041086648216f);
    p = fmaf(f, p, 0.2402265069591007f);
    p = fmaf(f, p, 0.6931471805599453f);
    p = fmaf(f, p, 1.0f);
    return __int_as_float(__float_as_int(p) + (((int)n) << 23));
}
#define MBAR_INIT(a, n) asm volatile("mbarrier.init.shared.b64 [%0], %1;" :: "r"(a), "r"(n) : "memory")
#define MBAR_EXPECT(a, tx) asm volatile("mbarrier.arrive.expect_tx.shared.b64 _, [%0], %1;" :: "r"(a), "r"(tx) : "memory")
#define MBAR_WAIT(a, ph) do {                                                        \
    uint32_t _m = (a), _p = (ph), _d;                                                \
    asm volatile("{ .reg .pred p; mbarrier.try_wait.parity.acquire.cta.shared::cta.b64 p, [%1], %2; selp.b32 %0,1,0,p; }" \
                 : "=r"(_d) : "r"(_m), "r"(_p) : "memory");                          \
    if (!_d) {                                                                       \
      asm volatile("{ .reg .pred P1; WL%=: mbarrier.try_wait.parity.acquire.cta.shared::cta.b64 P1, [%0], %1, 0x989680; @P1 bra.uni WD%=; bra.uni WL%=; WD%=: }" \
                   :: "r"(_m), "r"(_p) : "memory");                                  \
    } } while (0)
#define BULK_G2S(sdst, gsrc, bytes, mbar)                                            \
    asm volatile("cp.async.bulk.shared::cta.global.mbarrier::complete_tx::bytes "    \
                 "[%0], [%1], %2, [%3];"                                             \
                 :: "r"(sdst), "l"(gsrc), "r"(bytes), "r"(mbar) : "memory")
#define MMA_F16(d, a0, a1, a2, a3, b0, b1)                                        \
    asm volatile("mma.sync.aligned.m16n8k16.row.col.f32.f16.f16.f32 "             \
                 "{%0,%1,%2,%3},{%4,%5,%6,%7},{%8,%9},{%0,%1,%2,%3};"             \
                 : "+f"(d[0]), "+f"(d[1]), "+f"(d[2]), "+f"(d[3])                  \
                 : "r"(a0), "r"(a1), "r"(a2), "r"(a3), "r"(b0), "r"(b1))

// fp16 k-pair permutation within a 16-element block.
__device__ __forceinline__ int kperm16(int kb) {   // kb = k & 15
    int pk = kb >> 1;
    return ((((pk & 3) << 1) | (pk >> 2)) << 1) | (kb & 1);
}

// ---------------------------------------------------------------------------
// Kernel A: fused projections. q,k -> fp16 hi/lo in swizzled-row layout;
// v = w3@x + b3 (b3 folded) transposed [b][c][w][j], fp16 swizzled rows.
// ---------------------------------------------------------------------------
__global__ __launch_bounds__(256)
void proj_kernel(const float* __restrict__ x,
                 const float* __restrict__ w1, const float* __restrict__ b1,
                 const float* __restrict__ w2, const float* __restrict__ b2,
                 const float* __restrict__ w3, const float* __restrict__ b3) {
    __shared__ float xt_s[8][32][33];
    __shared__ float w1s[8], w2s[8], w3s[64], b3s[8], bqk[2];
    const int tid = threadIdx.x;
    if (tid < 8)  { w1s[tid] = w1[tid]; w2s[tid] = w2[tid]; b3s[tid] = b3[tid]; }
    if (tid < 64) w3s[tid] = w3[tid];
    if (tid == 0) { bqk[0] = b1[0]; bqk[1] = b2[0]; }
    __syncthreads();
    const int b = blockIdx.z, j0 = blockIdx.y * 32, w0 = blockIdx.x * 32;
    const int jl = tid >> 3, wq = (tid & 7) << 2;
    const float* xb = x + (size_t)b * NC * HW + (size_t)(j0 + jl) * NW + w0 + wq;

    float4 xv[8];
#pragma unroll
    for (int c = 0; c < 8; c++) xv[c] = *(const float4*)(xb + (size_t)c * HW);

    float4 q = make_float4(bqk[0], bqk[0], bqk[0], bqk[0]);
    float4 k = make_float4(bqk[1], bqk[1], bqk[1], bqk[1]);
#pragma unroll
    for (int c = 0; c < 8; c++) {
        q.x = fmaf(w1s[c], xv[c].x, q.x); q.y = fmaf(w1s[c], xv[c].y, q.y);
        q.z = fmaf(w1s[c], xv[c].z, q.z); q.w = fmaf(w1s[c], xv[c].w, q.w);
        k.x = fmaf(w2s[c], xv[c].x, k.x); k.y = fmaf(w2s[c], xv[c].y, k.y);
        k.z = fmaf(w2s[c], xv[c].z, k.z); k.w = fmaf(w2s[c], xv[c].w, k.w);
    }
    // hi/lo split + swizzled-row stores (row-XOR + pair permutation)
    {
        const int row = j0 + jl;
        const size_t rowoff = (size_t)b * HW + (size_t)row * NW;
        const int base = (((w0 + wq) >> 4) ^ (row & 3)) << 4;
        const int kb = wq & 15;
        const int h0 = base + kperm16(kb), h1 = base + kperm16(kb + 2);
        __half qhx = __float2half_rn(q.x), qhy = __float2half_rn(q.y);
        __half qhz = __float2half_rn(q.z), qhw = __float2half_rn(q.w);
        __half khx = __float2half_rn(k.x), khy = __float2half_rn(k.y);
        __half khz = __float2half_rn(k.z), khw = __float2half_rn(k.w);
        *(__half2*)(g_qh + rowoff + h0) = __halves2half2(qhx, qhy);
        *(__half2*)(g_qh + rowoff + h1) = __halves2half2(qhz, qhw);
        *(__half2*)(g_kh + rowoff + h0) = __halves2half2(khx, khy);
        *(__half2*)(g_kh + rowoff + h1) = __halves2half2(khz, khw);
        *(__half2*)(g_ql + rowoff + h0) = __floats2half2_rn(q.x - __half2float(qhx),
                                                            q.y - __half2float(qhy));
        *(__half2*)(g_ql + rowoff + h1) = __floats2half2_rn(q.z - __half2float(qhz),
                                                            q.w - __half2float(qhw));
        *(__half2*)(g_kl + rowoff + h0) = __floats2half2_rn(k.x - __half2float(khx),
                                                            k.y - __half2float(khy));
        *(__half2*)(g_kl + rowoff + h1) = __floats2half2_rn(k.z - __half2float(khz),
                                                            k.w - __half2float(khw));
    }

#pragma unroll
    for (int c = 0; c < 8; c++) {
        float4 v = make_float4(b3s[c], b3s[c], b3s[c], b3s[c]);
#pragma unroll
        for (int cp = 0; cp < 8; cp++) {
            float w = w3s[c * 8 + cp];
            v.x = fmaf(w, xv[cp].x, v.x); v.y = fmaf(w, xv[cp].y, v.y);
            v.z = fmaf(w, xv[cp].z, v.z); v.w = fmaf(w, xv[cp].w, v.w);
        }
        xt_s[c][jl][wq + 0] = v.x; xt_s[c][jl][wq + 1] = v.y;
        xt_s[c][jl][wq + 2] = v.z; xt_s[c][jl][wq + 3] = v.w;
    }
    __syncthreads();
    // transposed fp16 write in swizzled-row layout (row = w, in-row index = j)
    const int jp = (tid & 15) << 1, wl = tid >> 4;
    const int pos = kperm16(jp & 15);
    const int blk = (j0 + jp) >> 4;
#pragma unroll
    for (int c = 0; c < 8; c++)
#pragma unroll
        for (int ws = 0; ws < 32; ws += 16) {
            int wg = ws + wl;
            int idx = ((blk ^ (wg & 3)) << 4) + pos;
            *(__half2*)(g_vth + (((size_t)(b * 8 + c)) * NW + w0 + wg) * NH + idx) =
                __floats2half2_rn(xt_s[c][jp][wg], xt_s[c][jp + 1][wg]);
        }
}

// ---------------------------------------------------------------------------
// Kernel B: FUSED scores+softmax, fp16 3-term split, K-RESIDENT + bulk ring.
// CTA = (i-tile 128, b), 512 thr = 16 warps (4m x 4n). q hi/lo (128KB)
// resident; k hi/lo streamed as 8 j-tiles of 32 rows via 2-slot mbarrier ring.
// ---------------------------------------------------------------------------
#define SF_MB_F0 0
#define SF_MB_F1 8
#define SF_MB_A  16
#define SF_QH 1024
#define SF_QL (SF_QH + 65536)
#define SF_B  (SF_QL + 65536)          // slot s: KH at +s*32768, KL at +16384
#define SF_RED (SF_B + 65536)          // 4*128 floats
#define SMEM_FUSED (SF_RED + 2048)     // 199680

__global__ __launch_bounds__(512, 1)
void scores_softmax_kernel() {
    extern __shared__ char smem[];
    const uint32_t sb = smem_u32(smem);
    float* red = (float*)(smem + SF_RED);
    const int tid = threadIdx.x;
    const int lane = tid & 31, warp = tid >> 5;
    const int warpM = warp & 3, warpN = warp >> 2;
    const int g = lane >> 2, t4 = lane & 3;
    const uint32_t gx = (uint32_t)(g & 3);

    const int i0 = blockIdx.x * 128;
    const int b  = blockIdx.y;
    const __half* Aqh = g_qh + (size_t)b * HW + (size_t)i0 * NW;
    const __half* Aql = g_ql + (size_t)b * HW + (size_t)i0 * NW;
    const __half* Bkh = g_kh + (size_t)b * HW;
    const __half* Bkl = g_kl + (size_t)b * HW;

    if (tid == 0) {
        MBAR_INIT(sb + SF_MB_F0, 1);
        MBAR_INIT(sb + SF_MB_F1, 1);
        MBAR_INIT(sb + SF_MB_A, 1);
    }
    __syncthreads();
    if (tid == 0) {
        MBAR_EXPECT(sb + SF_MB_A, 131072u);
        BULK_G2S(sb + SF_QH, Aqh, 65536u, sb + SF_MB_A);
        BULK_G2S(sb + SF_QL, Aql, 65536u, sb + SF_MB_A);
        MBAR_EXPECT(sb + SF_MB_F0, 32768u);
        BULK_G2S(sb + SF_B,          Bkh, 16384u, sb + SF_MB_F0);
        BULK_G2S(sb + SF_B + 16384,  Bkl, 16384u, sb + SF_MB_F0);
        MBAR_EXPECT(sb + SF_MB_F1, 32768u);
        BULK_G2S(sb + SF_B + 32768,  Bkh + 32 * NH, 16384u, sb + SF_MB_F1);
        BULK_G2S(sb + SF_B + 49152,  Bkl + 32 * NH, 16384u, sb + SF_MB_F1);
    }

    float acc[8][2][4];
#pragma unroll
    for (int t = 0; t < 8; t++)
#pragma unroll
        for (int mi = 0; mi < 2; mi++)
#pragma unroll
            for (int r = 0; r < 4; r++) acc[t][mi][r] = 0.f;

    MBAR_WAIT(sb + SF_MB_A, 0);

    const int nrow = warpN * 8 + g;            // B row within 32-row tile
#pragma unroll
    for (int t = 0; t < 8; t++) {              // unrolled: acc[t] must stay in regs
        MBAR_WAIT(sb + ((t & 1) ? SF_MB_F1 : SF_MB_F0), (t >> 1) & 1);
        const uint32_t kh = sb + SF_B + (t & 1) * 32768;
        const uint32_t kl = kh + 16384;
        for (int kb = 0; kb < 16; kb++) {      // rolled: keeps I$ small
            const uint32_t off = ((uint32_t)(kb ^ (int)gx) << 5) + (uint32_t)(t4 * 8);
            uint32_t ah[2][4], al[2][4];
#pragma unroll
            for (int mi = 0; mi < 2; mi++) {
                int r0 = warpM * 32 + mi * 16 + g;
                uint2 h0 = lds64(sb + SF_QH + r0 * 512 + off);
                uint2 h1 = lds64(sb + SF_QH + (r0 + 8) * 512 + off);
                uint2 l0 = lds64(sb + SF_QL + r0 * 512 + off);
                uint2 l1 = lds64(sb + SF_QL + (r0 + 8) * 512 + off);
                ah[mi][0] = h0.x; ah[mi][1] = h1.x; ah[mi][2] = h0.y; ah[mi][3] = h1.y;
                al[mi][0] = l0.x; al[mi][1] = l1.x; al[mi][2] = l0.y; al[mi][3] = l1.y;
            }
            uint2 bh = lds64(kh + nrow * 512 + off);
            uint2 bl = lds64(kl + nrow * 512 + off);
#pragma unroll
            for (int mi = 0; mi < 2; mi++) {
                MMA_F16(acc[t][mi], ah[mi][0], ah[mi][1], ah[mi][2], ah[mi][3],
                        bh.x, bh.y);
                MMA_F16(acc[t][mi], ah[mi][0], ah[mi][1], ah[mi][2], ah[mi][3],
                        bl.x, bl.y);
                MMA_F16(acc[t][mi], al[mi][0], al[mi][1], al[mi][2], al[mi][3],
                        bh.x, bh.y);
            }
        }
        __syncthreads();                        // slot (t&1) free for refill
        if (tid == 0 && t < 6) {
            uint32_t mb = sb + ((t & 1) ? SF_MB_F1 : SF_MB_F0);
            MBAR_EXPECT(mb, 32768u);
            uint32_t dst = sb + SF_B + (t & 1) * 32768;
            BULK_G2S(dst,         Bkh + (size_t)(t + 2) * 32 * NH, 16384u, mb);
            BULK_G2S(dst + 16384, Bkl + (size_t)(t + 2) * 32 * NH, 16384u, mb);
        }
    }

    // ---- fused softmax (rows 128; lane owns 4 rows; reduce 4 warpN groups) --
    float rowv[4];
#pragma unroll
    for (int mi = 0; mi < 2; mi++)
#pragma unroll
        for (int h = 0; h < 2; h++) {
            float m = -FLT_MAX;
#pragma unroll
            for (int t = 0; t < 8; t++)
                m = fmaxf(m, fmaxf(acc[t][mi][h * 2], acc[t][mi][h * 2 + 1]));
            m = fmaxf(m, __shfl_xor_sync(0xffffffffu, m, 1));
            m = fmaxf(m, __shfl_xor_sync(0xffffffffu, m, 2));
            rowv[mi * 2 + h] = m;
        }
    if (t4 == 0) {
#pragma unroll
        for (int mi = 0; mi < 2; mi++)
#pragma unroll
            for (int h = 0; h < 2; h++)
                red[warpN * 128 + warpM * 32 + mi * 16 + h * 8 + g] = rowv[mi * 2 + h];
    }
    __syncthreads();
    float rowmax[4];
#pragma unroll
    for (int mi = 0; mi < 2; mi++)
#pragma unroll
        for (int h = 0; h < 2; h++) {
            int rl = warpM * 32 + mi * 16 + h * 8 + g;
            rowmax[mi * 2 + h] = fmaxf(fmaxf(red[rl], red[128 + rl]),
                                       fmaxf(red[256 + rl], red[384 + rl]));
        }
    __syncthreads();
#pragma unroll
    for (int mi = 0; mi < 2; mi++)
#pragma unroll
        for (int h = 0; h < 2; h++) {
            float m = rowmax[mi * 2 + h], s = 0.f;
#pragma unroll
            for (int t = 0; t < 8; t++) {
                float e0 = fast_exp(acc[t][mi][h * 2] - m);
                float e1 = fast_exp(acc[t][mi][h * 2 + 1] - m);
                acc[t][mi][h * 2] = e0; acc[t][mi][h * 2 + 1] = e1;
                s += e0 + e1;
            }
            s += __shfl_xor_sync(0xffffffffu, s, 1);
            s += __shfl_xor_sync(0xffffffffu, s, 2);
            rowv[mi * 2 + h] = s;
        }
    if (t4 == 0) {
#pragma unroll
        for (int mi = 0; mi < 2; mi++)
#pragma unroll
            for (int h = 0; h < 2; h++)
                red[warpN * 128 + warpM * 32 + mi * 16 + h * 8 + g] = rowv[mi * 2 + h];
    }
    __syncthreads();
    __half* attn = g_attnh + (size_t)b * NH * NH;
#pragma unroll
    for (int mi = 0; mi < 2; mi++)
#pragma unroll
        for (int h = 0; h < 2; h++) {
            int rl = warpM * 32 + mi * 16 + h * 8 + g;
            float inv = 1.0f / (red[rl] + red[128 + rl] + red[256 + rl] + red[384 + rl]);
            size_t rb = (size_t)(i0 + rl) * NH;
#pragma unroll
            for (int t = 0; t < 8; t++) {
                int j = t * 32 + warpN * 8 + t4 * 2;
                int idx = (((j >> 4) ^ (rl & 3)) << 4) + kperm16(j & 15);
                *(__half2*)(attn + rb + idx) =
                    __floats2half2_rn(acc[t][mi][h * 2] * inv,
                                      acc[t][mi][h * 2 + 1] * inv);
            }
        }
}

// ---------------------------------------------------------------------------
// Kernel D: out[b,c] = attn_b @ v[b,c], FP16 HMMA, K-RESIDENT A + bulk ring B.
// CTA = (b, c, mt): A 64KB resident; vth streamed as 8 n-tiles of 32 rows via
// 2-slot mbarrier ring (16KB fills). 256 thr = 8 warps (4m x 2n). 2 CTAs/SM.
// ---------------------------------------------------------------------------
#define O_MB_F0 0
#define O_MB_F1 8
#define O_MB_A  16
#define O_SA 1024
#define O_SB (1024 + 65536)            // slot s at +s*16384
#define SMEM_OUT (O_SB + 32768)        // 99328

__global__ __launch_bounds__(256, 2)
void mma_out_kernel(float* __restrict__ out) {
    extern __shared__ char smem[];
    const uint32_t sb = smem_u32(smem);
    const int tid = threadIdx.x;
    const int lane = tid & 31, warp = tid >> 5;
    const int warpM = warp & 3, warpN = warp >> 2;   // 4m x 2n
    const int g = lane >> 2, t4 = lane & 3;
    const uint32_t gx = (uint32_t)(g & 3);

    const int mt = blockIdx.x & 1, c = blockIdx.x >> 1;
    const int b  = blockIdx.y;
    const int i0 = mt * 128;
    const __half* Ag = g_attnh + (size_t)b * NH * NH + (size_t)i0 * NH;
    const __half* Bg = g_vth + ((size_t)(b * 8 + c)) * HW;

    if (tid == 0) {
        MBAR_INIT(sb + O_MB_F0, 1);
        MBAR_INIT(sb + O_MB_F1, 1);
        MBAR_INIT(sb + O_MB_A, 1);
    }
    __syncthreads();
    if (tid == 0) {
        MBAR_EXPECT(sb + O_MB_A, 65536u);
        BULK_G2S(sb + O_SA, Ag, 65536u, sb + O_MB_A);
        MBAR_EXPECT(sb + O_MB_F0, 16384u);
        BULK_G2S(sb + O_SB, Bg, 16384u, sb + O_MB_F0);
        MBAR_EXPECT(sb + O_MB_F1, 16384u);
        BULK_G2S(sb + O_SB + 16384, Bg + 32 * NH, 16384u, sb + O_MB_F1);
    }
    MBAR_WAIT(sb + O_MB_A, 0);

    float* ob = out + ((size_t)(b * 8 + c)) * HW;

    for (int t = 0; t < 8; t++) {
        MBAR_WAIT(sb + ((t & 1) ? O_MB_F1 : O_MB_F0), (t >> 1) & 1);
        const uint32_t bsl = sb + O_SB + (t & 1) * 16384;

        float acc[2][2][4];
#pragma unroll
        for (int mi = 0; mi < 2; mi++)
#pragma unroll
            for (int ni = 0; ni < 2; ni++)
#pragma unroll
                for (int r = 0; r < 4; r++) acc[mi][ni][r] = 0.f;

        for (int kb = 0; kb < 16; kb++) {
            const uint32_t off = ((uint32_t)(kb ^ (int)gx) << 5) + (uint32_t)(t4 * 8);
            uint32_t aop[2][4];
#pragma unroll
            for (int mi = 0; mi < 2; mi++) {
                int r0 = warpM * 32 + mi * 16 + g;
                uint2 q0 = lds64(sb + O_SA + r0 * 512 + off);
                uint2 q1 = lds64(sb + O_SA + (r0 + 8) * 512 + off);
                aop[mi][0] = q0.x; aop[mi][1] = q1.x;
                aop[mi][2] = q0.y; aop[mi][3] = q1.y;
            }
#pragma unroll
            for (int ni = 0; ni < 2; ni++) {
                int n = warpN * 16 + ni * 8 + g;
                uint2 bq = lds64(bsl + n * 512 + off);
#pragma unroll
                for (int mi = 0; mi < 2; mi++)
                    MMA_F16(acc[mi][ni], aop[mi][0], aop[mi][1],
                            aop[mi][2], aop[mi][3], bq.x, bq.y);
            }
        }

        __syncthreads();                        // slot (t&1) free for refill
        if (tid == 0 && t < 6) {
            uint32_t mb = sb + ((t & 1) ? O_MB_F1 : O_MB_F0);
            MBAR_EXPECT(mb, 16384u);
            BULK_G2S(sb + O_SB + (t & 1) * 16384,
                     Bg + (size_t)(t + 2) * 32 * NH, 16384u, mb);
        }

        // epilogue for this n-tile (overlaps next fill)
#pragma unroll
        for (int mi = 0; mi < 2; mi++) {
            int row = i0 + warpM * 32 + mi * 16 + g;
#pragma unroll
            for (int ni = 0; ni < 2; ni++) {
                int col = t * 32 + warpN * 16 + ni * 8 + t4 * 2;
                *(float2*)(ob + (size_t)row * NW + col) =
                    make_float2(acc[mi][ni][0], acc[mi][ni][1]);
                *(float2*)(ob + (size_t)(row + 8) * NW + col) =
                    make_float2(acc[mi][ni][2], acc[mi][ni][3]);
            }
        }
    }
}

// ---------------------------------------------------------------------------
extern "C" void kernel_launch(void* const* d_in, const int* in_sizes, int n_in,
                              void* d_out, int out_size) {
    const float* x  = (const float*)d_in[0];
    const float* w1 = (const float*)d_in[1];
    const float* b1 = (const float*)d_in[2];
    const float* w2 = (const float*)d_in[3];
    const float* b2 = (const float*)d_in[4];
    const float* w3 = (const float*)d_in[5];
    const float* b3 = (const float*)d_in[6];
    float* out = (float*)d_out;

    static bool configured = false;
    if (!configured) {
        cudaFuncSetAttribute(scores_softmax_kernel,
                             cudaFuncAttributeMaxDynamicSharedMemorySize, SMEM_FUSED);
        cudaFuncSetAttribute(mma_out_kernel,
                             cudaFuncAttributeMaxDynamicSharedMemorySize, SMEM_OUT);
        configured = true;
    }

    dim3 ga(8, 8, NB);
    proj_kernel<<<ga, 256>>>(x, w1, b1, w2, b2, w3, b3);
    dim3 gs(2, NB);
    scores_softmax_kernel<<<gs, 512, SMEM_FUSED>>>();
    dim3 gd(16, NB);
    mma_out_kernel<<<gd, 256, SMEM_OUT>>>(out);
}